// round 1
// baseline (speedup 1.0000x reference)
#include <cuda_runtime.h>
#include <math.h>

#define BB 2
#define SS 2048
#define DD 2048
#define NQ 32
#define NKV 8
#define HD 64
#define MM (BB*SS)   // 4096

// Scratch (no cudaMalloc allowed)
__device__ float g_Q[(size_t)MM * NQ * HD];     // [B*S, 2048]
__device__ float g_K[(size_t)MM * NKV * HD];    // [B*S, 512]
__device__ float g_V[(size_t)MM * NKV * HD];    // [B*S, 512]
__device__ float g_attn[(size_t)MM * DD];       // [B*S, 2048]

// ---------------------------------------------------------------------------
// SGEMM: C[m][n] = sum_k A[m*K+k] * Bm[n*K+k]   (C = A * B^T, both K-major)
// 128x128 block tile, BK=8, 256 threads, 8x8 per-thread micro-tile.
// Assumes M%128==0, N%128==0, K%8==0 (true for all shapes here).
// ---------------------------------------------------------------------------
__global__ __launch_bounds__(256) void sgemm_abt(const float* __restrict__ A,
                                                 const float* __restrict__ Bm,
                                                 float* __restrict__ C,
                                                 int M, int N, int K)
{
    const int BM = 128, BN = 128, BK = 8;
    __shared__ float As[BK][BM + 4];
    __shared__ float Bs[BK][BN + 4];

    int tid = threadIdx.x;
    int tx = tid & 15;         // 0..15
    int ty = tid >> 4;         // 0..15
    int bm = blockIdx.y * BM;
    int bn = blockIdx.x * BN;

    // loader: 256 threads, each one float4 along K: row = tid/2, k-offset = (tid&1)*4
    int lr = tid >> 1;
    int lk = (tid & 1) * 4;

    float acc[8][8];
#pragma unroll
    for (int i = 0; i < 8; i++)
#pragma unroll
        for (int j = 0; j < 8; j++) acc[i][j] = 0.f;

    const float* Arow = A + (size_t)(bm + lr) * K + lk;
    const float* Brow = Bm + (size_t)(bn + lr) * K + lk;

    for (int k0 = 0; k0 < K; k0 += BK) {
        float4 a4 = *(const float4*)(Arow + k0);
        float4 b4 = *(const float4*)(Brow + k0);
        __syncthreads();
        As[lk + 0][lr] = a4.x; As[lk + 1][lr] = a4.y;
        As[lk + 2][lr] = a4.z; As[lk + 3][lr] = a4.w;
        Bs[lk + 0][lr] = b4.x; Bs[lk + 1][lr] = b4.y;
        Bs[lk + 2][lr] = b4.z; Bs[lk + 3][lr] = b4.w;
        __syncthreads();
#pragma unroll
        for (int kk = 0; kk < BK; kk++) {
            float ra[8], rb[8];
#pragma unroll
            for (int i = 0; i < 8; i++) ra[i] = As[kk][ty * 8 + i];
#pragma unroll
            for (int j = 0; j < 8; j++) rb[j] = Bs[kk][tx * 8 + j];
#pragma unroll
            for (int i = 0; i < 8; i++)
#pragma unroll
                for (int j = 0; j < 8; j++)
                    acc[i][j] = fmaf(ra[i], rb[j], acc[i][j]);
        }
    }

#pragma unroll
    for (int i = 0; i < 8; i++) {
        float* crow = C + (size_t)(bm + ty * 8 + i) * N + bn + tx * 8;
        float4 v0 = make_float4(acc[i][0], acc[i][1], acc[i][2], acc[i][3]);
        float4 v1 = make_float4(acc[i][4], acc[i][5], acc[i][6], acc[i][7]);
        *(float4*)(crow + 0) = v0;
        *(float4*)(crow + 4) = v1;
    }
}

// ---------------------------------------------------------------------------
// RoPE (in-place). X layout: [B*S, nheads*HD]. Pair (i, i+32), i in [0,32).
// inv_freq[i] = 10000^{-i/32}
// ---------------------------------------------------------------------------
__global__ void rope_kernel(float* __restrict__ X, int nheads)
{
    int idx = blockIdx.x * blockDim.x + threadIdx.x;
    int total = MM * nheads * (HD / 2);
    if (idx >= total) return;
    int i = idx & 31;                 // pair index
    int t = idx >> 5;
    int h = t % nheads;
    int ms = t / nheads;              // b*S + s
    int s = ms & (SS - 1);

    const float LOG_THETA_OVER_HALF = 9.210340371976184f / 32.0f;
    float inv = __expf(0.0f) * expf(-(float)i * LOG_THETA_OVER_HALF);
    float ang = (float)s * inv;
    float sn, cs;
    sincosf(ang, &sn, &cs);

    float* base = X + (size_t)ms * nheads * HD + h * HD;
    float x1 = base[i];
    float x2 = base[i + 32];
    base[i]      = x1 * cs - x2 * sn;
    base[i + 32] = x2 * cs + x1 * sn;
}

// ---------------------------------------------------------------------------
// Flash attention, causal. 64x64 tiles, fp32, online softmax.
// grid: (S/64, NQ, B), block: 256. Thread t: row r = t>>2, col-quarter q = t&3.
// smem: Q,K,V,P tiles, each 64 x 65 floats (padded).
// ---------------------------------------------------------------------------
__global__ __launch_bounds__(256) void attn_kernel()
{
    const int TS = 64, PAD = 65;
    extern __shared__ float sm[];
    float* Qs = sm;
    float* Ks = sm + TS * PAD;
    float* Vs = sm + 2 * TS * PAD;
    float* Ps = sm + 3 * TS * PAD;

    int qt = blockIdx.x;
    int h  = blockIdx.y;
    int b  = blockIdx.z;
    int kvh = h >> 2;                  // NQ/NKV = 4

    int tid = threadIdx.x;
    int r = tid >> 2;                  // 0..63 (query row in tile)
    int q = tid & 3;                   // column quarter

    // Load Q tile
    const float* Qg = g_Q + ((size_t)(b * SS + qt * 64)) * (NQ * HD) + h * HD;
    for (int i = tid; i < 64 * 64; i += 256) {
        int rr = i >> 6, dd = i & 63;
        Qs[rr * PAD + dd] = Qg[(size_t)rr * (NQ * HD) + dd];
    }

    float m = -INFINITY, l = 0.f;
    float o[16];
#pragma unroll
    for (int j = 0; j < 16; j++) o[j] = 0.f;

    int qg = qt * 64 + r;              // global query row

    for (int kt = 0; kt <= qt; kt++) {
        __syncthreads();               // protect Ks/Vs/Ps reuse
        const float* Kg = g_K + ((size_t)(b * SS + kt * 64)) * (NKV * HD) + kvh * HD;
        const float* Vg = g_V + ((size_t)(b * SS + kt * 64)) * (NKV * HD) + kvh * HD;
        for (int i = tid; i < 64 * 64; i += 256) {
            int rr = i >> 6, dd = i & 63;
            Ks[rr * PAD + dd] = Kg[(size_t)rr * (NKV * HD) + dd];
            Vs[rr * PAD + dd] = Vg[(size_t)rr * (NKV * HD) + dd];
        }
        __syncthreads();

        // scores: s[j] = Q[r] . K[q*16+j]
        float sreg[16];
#pragma unroll
        for (int j = 0; j < 16; j++) sreg[j] = 0.f;
#pragma unroll 4
        for (int d = 0; d < 64; d++) {
            float qv = Qs[r * PAD + d];
#pragma unroll
            for (int j = 0; j < 16; j++)
                sreg[j] = fmaf(qv, Ks[(q * 16 + j) * PAD + d], sreg[j]);
        }
        const float scale = 0.125f;    // 1/sqrt(64)
#pragma unroll
        for (int j = 0; j < 16; j++) sreg[j] *= scale;

        if (kt == qt) {
#pragma unroll
            for (int j = 0; j < 16; j++)
                if (kt * 64 + q * 16 + j > qg) sreg[j] = -INFINITY;
        }

        // row max over 4 lanes (groups of 4 are lane-aligned)
        float mloc = sreg[0];
#pragma unroll
        for (int j = 1; j < 16; j++) mloc = fmaxf(mloc, sreg[j]);
        mloc = fmaxf(mloc, __shfl_xor_sync(0xffffffffu, mloc, 1));
        mloc = fmaxf(mloc, __shfl_xor_sync(0xffffffffu, mloc, 2));
        float mnew = fmaxf(m, mloc);
        float alpha = expf(m - mnew);  // 0 when m == -inf

        float lloc = 0.f;
#pragma unroll
        for (int j = 0; j < 16; j++) {
            float p = expf(sreg[j] - mnew);
            lloc += p;
            Ps[r * PAD + q * 16 + j] = p;
        }
        lloc += __shfl_xor_sync(0xffffffffu, lloc, 1);
        lloc += __shfl_xor_sync(0xffffffffu, lloc, 2);
        l = l * alpha + lloc;
        m = mnew;
#pragma unroll
        for (int j = 0; j < 16; j++) o[j] *= alpha;

        __syncwarp();                  // Ps row is warp-local (4 lanes/row)

        // O[r][q*16+j] += sum_c P[r][c] * V[c][q*16+j]
#pragma unroll 4
        for (int c = 0; c < 64; c++) {
            float pv = Ps[r * PAD + c];
#pragma unroll
            for (int j = 0; j < 16; j++)
                o[j] = fmaf(pv, Vs[c * PAD + q * 16 + j], o[j]);
        }
    }

    float inv_l = 1.0f / l;
    float* Og = g_attn + ((size_t)(b * SS + qt * 64 + r)) * DD + h * HD + q * 16;
#pragma unroll
    for (int j = 0; j < 16; j++) Og[j] = o[j] * inv_l;
}

// ---------------------------------------------------------------------------
extern "C" void kernel_launch(void* const* d_in, const int* in_sizes, int n_in,
                              void* d_out, int out_size)
{
    const float* x  = (const float*)d_in[0];
    // d_in[1] = attention_mask (all ones; unused by reference math)
    const float* Wq = (const float*)d_in[2];
    const float* Wk = (const float*)d_in[3];
    const float* Wv = (const float*)d_in[4];
    const float* Wo = (const float*)d_in[5];
    float* out = (float*)d_out;

    float *Qp, *Kp, *Vp, *Ap;
    cudaGetSymbolAddress((void**)&Qp, g_Q);
    cudaGetSymbolAddress((void**)&Kp, g_K);
    cudaGetSymbolAddress((void**)&Vp, g_V);
    cudaGetSymbolAddress((void**)&Ap, g_attn);

    // Projections: C = X * W^T
    sgemm_abt<<<dim3(DD / 128, MM / 128), 256>>>(x, Wq, Qp, MM, DD, DD);
    sgemm_abt<<<dim3((NKV * HD) / 128, MM / 128), 256>>>(x, Wk, Kp, MM, NKV * HD, DD);
    sgemm_abt<<<dim3((NKV * HD) / 128, MM / 128), 256>>>(x, Wv, Vp, MM, NKV * HD, DD);

    // RoPE on Q and K
    {
        int totq = MM * NQ * (HD / 2);
        rope_kernel<<<(totq + 255) / 256, 256>>>(Qp, NQ);
        int totk = MM * NKV * (HD / 2);
        rope_kernel<<<(totk + 255) / 256, 256>>>(Kp, NKV);
    }

    // Attention
    {
        int smem = 4 * 64 * 65 * (int)sizeof(float);   // 66560 B
        cudaFuncSetAttribute(attn_kernel, cudaFuncAttributeMaxDynamicSharedMemorySize, smem);
        attn_kernel<<<dim3(SS / 64, NQ, BB), 256, smem>>>();
    }

    // Output projection
    sgemm_abt<<<dim3(DD / 128, MM / 128), 256>>>(Ap, Wo, out, MM, DD, DD);
}

// round 2
// speedup vs baseline: 1.2857x; 1.2857x over previous
#include <cuda_runtime.h>
#include <math.h>
#include <stdint.h>

#define BB 2
#define SS 2048
#define DD 2048
#define NQ 32
#define NKV 8
#define HD 64
#define MM (BB*SS)   // 4096

// Scratch (no cudaMalloc allowed)
__device__ float g_Q[(size_t)MM * NQ * HD];     // [B*S, 2048]
__device__ float g_K[(size_t)MM * NKV * HD];    // [B*S, 512]
__device__ float g_V[(size_t)MM * NKV * HD];    // [B*S, 512]
__device__ float g_attn[(size_t)MM * DD];       // [B*S, 2048]

// ---------------------------------------------------------------------------
// TF32 tensor-core GEMM: C = A * B^T. A:[M,K] row-major, B:[N,K] row-major.
// Block 128x128, BK=16, 256 threads (8 warps, 2x4 grid -> 64x32 warp tile).
// mma.sync.aligned.m16n8k8.row.col.f32.tf32.tf32.f32
// smem rows padded to 20 floats -> conflict-free fragment loads.
// ---------------------------------------------------------------------------
#define AST 20

__device__ __forceinline__ uint32_t f2tf32(float f) {
    uint32_t o;
    asm("cvt.rna.tf32.f32 %0, %1;" : "=r"(o) : "f"(f));
    return o;
}

__device__ __forceinline__ void mma_tf32(float* c, const uint32_t* a, const uint32_t* b) {
    asm volatile(
        "mma.sync.aligned.m16n8k8.row.col.f32.tf32.tf32.f32 "
        "{%0,%1,%2,%3}, {%4,%5,%6,%7}, {%8,%9}, {%0,%1,%2,%3};"
        : "+f"(c[0]), "+f"(c[1]), "+f"(c[2]), "+f"(c[3])
        : "r"(a[0]), "r"(a[1]), "r"(a[2]), "r"(a[3]), "r"(b[0]), "r"(b[1]));
}

__global__ __launch_bounds__(256, 2) void gemm_tf32(const float* __restrict__ A,
                                                    const float* __restrict__ Bm,
                                                    float* __restrict__ C,
                                                    int M, int N, int K)
{
    __shared__ uint32_t As[128 * AST];
    __shared__ uint32_t Bs[128 * AST];

    int tid = threadIdx.x;
    int lane = tid & 31;
    int warp = tid >> 5;
    int wm = warp >> 2;          // 0..1
    int wn = warp & 3;           // 0..3
    int bm = blockIdx.y * 128;
    int bn = blockIdx.x * 128;

    float acc[4][4][4];
#pragma unroll
    for (int i = 0; i < 4; i++)
#pragma unroll
        for (int j = 0; j < 4; j++)
#pragma unroll
            for (int t = 0; t < 4; t++) acc[i][j][t] = 0.f;

    // loader slots: s in [0,512): row=s>>2, kcol=(s&3)*4. 2 slots/thread per tile.
    int s0 = tid, s1 = tid + 256;
    int r0 = s0 >> 2, kc0 = (s0 & 3) * 4;
    int r1 = s1 >> 2, kc1 = (s1 & 3) * 4;

    const float* Abase0 = A + (size_t)(bm + r0) * K + kc0;
    const float* Abase1 = A + (size_t)(bm + r1) * K + kc1;
    const float* Bbase0 = Bm + (size_t)(bn + r0) * K + kc0;
    const float* Bbase1 = Bm + (size_t)(bn + r1) * K + kc1;

    int lg = lane >> 2;   // 0..7
    int lk = lane & 3;    // 0..3

    for (int k0 = 0; k0 < K; k0 += 16) {
        float4 a0 = *(const float4*)(Abase0 + k0);
        float4 a1 = *(const float4*)(Abase1 + k0);
        float4 b0 = *(const float4*)(Bbase0 + k0);
        float4 b1 = *(const float4*)(Bbase1 + k0);
        __syncthreads();
        {
            uint4 v;
            v.x = f2tf32(a0.x); v.y = f2tf32(a0.y); v.z = f2tf32(a0.z); v.w = f2tf32(a0.w);
            *(uint4*)&As[r0 * AST + kc0] = v;
            v.x = f2tf32(a1.x); v.y = f2tf32(a1.y); v.z = f2tf32(a1.z); v.w = f2tf32(a1.w);
            *(uint4*)&As[r1 * AST + kc1] = v;
            v.x = f2tf32(b0.x); v.y = f2tf32(b0.y); v.z = f2tf32(b0.z); v.w = f2tf32(b0.w);
            *(uint4*)&Bs[r0 * AST + kc0] = v;
            v.x = f2tf32(b1.x); v.y = f2tf32(b1.y); v.z = f2tf32(b1.z); v.w = f2tf32(b1.w);
            *(uint4*)&Bs[r1 * AST + kc1] = v;
        }
        __syncthreads();

#pragma unroll
        for (int kk = 0; kk < 16; kk += 8) {
            uint32_t af[4][4];
#pragma unroll
            for (int mi = 0; mi < 4; mi++) {
                int r = wm * 64 + mi * 16;
                af[mi][0] = As[(r + lg) * AST + kk + lk];
                af[mi][1] = As[(r + 8 + lg) * AST + kk + lk];
                af[mi][2] = As[(r + lg) * AST + kk + 4 + lk];
                af[mi][3] = As[(r + 8 + lg) * AST + kk + 4 + lk];
            }
            uint32_t bf[4][2];
#pragma unroll
            for (int ni = 0; ni < 4; ni++) {
                int c = wn * 32 + ni * 8;
                bf[ni][0] = Bs[(c + lg) * AST + kk + lk];
                bf[ni][1] = Bs[(c + lg) * AST + kk + 4 + lk];
            }
#pragma unroll
            for (int mi = 0; mi < 4; mi++)
#pragma unroll
                for (int ni = 0; ni < 4; ni++)
                    mma_tf32(acc[mi][ni], af[mi], bf[ni]);
        }
    }

#pragma unroll
    for (int mi = 0; mi < 4; mi++) {
#pragma unroll
        for (int ni = 0; ni < 4; ni++) {
            int rr = bm + wm * 64 + mi * 16 + lg;
            int cc = bn + wn * 32 + ni * 8 + lk * 2;
            float2 v0 = make_float2(acc[mi][ni][0], acc[mi][ni][1]);
            float2 v1 = make_float2(acc[mi][ni][2], acc[mi][ni][3]);
            *(float2*)(C + (size_t)rr * N + cc) = v0;
            *(float2*)(C + (size_t)(rr + 8) * N + cc) = v1;
        }
    }
}

// ---------------------------------------------------------------------------
// RoPE (in-place). X layout: [B*S, nheads*HD]. Pair (i, i+32), i in [0,32).
// ---------------------------------------------------------------------------
__global__ void rope_kernel(float* __restrict__ X, int nheads)
{
    int idx = blockIdx.x * blockDim.x + threadIdx.x;
    int total = MM * nheads * (HD / 2);
    if (idx >= total) return;
    int i = idx & 31;                 // pair index
    int t = idx >> 5;
    int h = t % nheads;
    int ms = t / nheads;              // b*S + s
    int s = ms & (SS - 1);

    const float LOG_THETA_OVER_HALF = 9.210340371976184f / 32.0f;
    float inv = expf(-(float)i * LOG_THETA_OVER_HALF);
    float ang = (float)s * inv;
    float sn, cs;
    sincosf(ang, &sn, &cs);

    float* base = X + (size_t)ms * nheads * HD + h * HD;
    float x1 = base[i];
    float x2 = base[i + 32];
    base[i]      = x1 * cs - x2 * sn;
    base[i + 32] = x2 * cs + x1 * sn;
}

// ---------------------------------------------------------------------------
// Flash attention, causal. 64x64 tiles, fp32, online softmax.
// grid: (S/64, NQ, B), block: 256.
// ---------------------------------------------------------------------------
__global__ __launch_bounds__(256) void attn_kernel()
{
    const int TS = 64, PAD = 65;
    extern __shared__ float sm[];
    float* Qs = sm;
    float* Ks = sm + TS * PAD;
    float* Vs = sm + 2 * TS * PAD;
    float* Ps = sm + 3 * TS * PAD;

    int qt = blockIdx.x;
    int h  = blockIdx.y;
    int b  = blockIdx.z;
    int kvh = h >> 2;                  // NQ/NKV = 4

    int tid = threadIdx.x;
    int r = tid >> 2;                  // query row in tile
    int q = tid & 3;                   // column quarter

    const float* Qg = g_Q + ((size_t)(b * SS + qt * 64)) * (NQ * HD) + h * HD;
    for (int i = tid; i < 64 * 64; i += 256) {
        int rr = i >> 6, dd = i & 63;
        Qs[rr * PAD + dd] = Qg[(size_t)rr * (NQ * HD) + dd];
    }

    float m = -INFINITY, l = 0.f;
    float o[16];
#pragma unroll
    for (int j = 0; j < 16; j++) o[j] = 0.f;

    int qg = qt * 64 + r;

    for (int kt = 0; kt <= qt; kt++) {
        __syncthreads();
        const float* Kg = g_K + ((size_t)(b * SS + kt * 64)) * (NKV * HD) + kvh * HD;
        const float* Vg = g_V + ((size_t)(b * SS + kt * 64)) * (NKV * HD) + kvh * HD;
        for (int i = tid; i < 64 * 64; i += 256) {
            int rr = i >> 6, dd = i & 63;
            Ks[rr * PAD + dd] = Kg[(size_t)rr * (NKV * HD) + dd];
            Vs[rr * PAD + dd] = Vg[(size_t)rr * (NKV * HD) + dd];
        }
        __syncthreads();

        float sreg[16];
#pragma unroll
        for (int j = 0; j < 16; j++) sreg[j] = 0.f;
#pragma unroll 4
        for (int d = 0; d < 64; d++) {
            float qv = Qs[r * PAD + d];
#pragma unroll
            for (int j = 0; j < 16; j++)
                sreg[j] = fmaf(qv, Ks[(q * 16 + j) * PAD + d], sreg[j]);
        }
        const float scale = 0.125f;
#pragma unroll
        for (int j = 0; j < 16; j++) sreg[j] *= scale;

        if (kt == qt) {
#pragma unroll
            for (int j = 0; j < 16; j++)
                if (kt * 64 + q * 16 + j > qg) sreg[j] = -INFINITY;
        }

        float mloc = sreg[0];
#pragma unroll
        for (int j = 1; j < 16; j++) mloc = fmaxf(mloc, sreg[j]);
        mloc = fmaxf(mloc, __shfl_xor_sync(0xffffffffu, mloc, 1));
        mloc = fmaxf(mloc, __shfl_xor_sync(0xffffffffu, mloc, 2));
        float mnew = fmaxf(m, mloc);
        float alpha = expf(m - mnew);

        float lloc = 0.f;
#pragma unroll
        for (int j = 0; j < 16; j++) {
            float p = expf(sreg[j] - mnew);
            lloc += p;
            Ps[r * PAD + q * 16 + j] = p;
        }
        lloc += __shfl_xor_sync(0xffffffffu, lloc, 1);
        lloc += __shfl_xor_sync(0xffffffffu, lloc, 2);
        l = l * alpha + lloc;
        m = mnew;
#pragma unroll
        for (int j = 0; j < 16; j++) o[j] *= alpha;

        __syncwarp();

#pragma unroll 4
        for (int c = 0; c < 64; c++) {
            float pv = Ps[r * PAD + c];
#pragma unroll
            for (int j = 0; j < 16; j++)
                o[j] = fmaf(pv, Vs[c * PAD + q * 16 + j], o[j]);
        }
    }

    float inv_l = 1.0f / l;
    float* Og = g_attn + ((size_t)(b * SS + qt * 64 + r)) * DD + h * HD + q * 16;
#pragma unroll
    for (int j = 0; j < 16; j++) Og[j] = o[j] * inv_l;
}

// ---------------------------------------------------------------------------
extern "C" void kernel_launch(void* const* d_in, const int* in_sizes, int n_in,
                              void* d_out, int out_size)
{
    const float* x  = (const float*)d_in[0];
    const float* Wq = (const float*)d_in[2];
    const float* Wk = (const float*)d_in[3];
    const float* Wv = (const float*)d_in[4];
    const float* Wo = (const float*)d_in[5];
    float* out = (float*)d_out;

    float *Qp, *Kp, *Vp, *Ap;
    cudaGetSymbolAddress((void**)&Qp, g_Q);
    cudaGetSymbolAddress((void**)&Kp, g_K);
    cudaGetSymbolAddress((void**)&Vp, g_V);
    cudaGetSymbolAddress((void**)&Ap, g_attn);

    // Projections: C = X * W^T  (tensor cores, tf32)
    gemm_tf32<<<dim3(DD / 128, MM / 128), 256>>>(x, Wq, Qp, MM, DD, DD);
    gemm_tf32<<<dim3((NKV * HD) / 128, MM / 128), 256>>>(x, Wk, Kp, MM, NKV * HD, DD);
    gemm_tf32<<<dim3((NKV * HD) / 128, MM / 128), 256>>>(x, Wv, Vp, MM, NKV * HD, DD);

    // RoPE on Q and K
    {
        int totq = MM * NQ * (HD / 2);
        rope_kernel<<<(totq + 255) / 256, 256>>>(Qp, NQ);
        int totk = MM * NKV * (HD / 2);
        rope_kernel<<<(totk + 255) / 256, 256>>>(Kp, NKV);
    }

    // Attention
    {
        int smem = 4 * 64 * 65 * (int)sizeof(float);
        cudaFuncSetAttribute(attn_kernel, cudaFuncAttributeMaxDynamicSharedMemorySize, smem);
        attn_kernel<<<dim3(SS / 64, NQ, BB), 256, smem>>>();
    }

    // Output projection
    gemm_tf32<<<dim3(DD / 128, MM / 128), 256>>>(Ap, Wo, out, MM, DD, DD);
}

// round 3
// speedup vs baseline: 5.7553x; 4.4764x over previous
#include <cuda_runtime.h>
#include <math.h>
#include <stdint.h>

#define BB 2
#define SS 2048
#define DD 2048
#define NQ 32
#define NKV 8
#define HD 64
#define MM (BB*SS)   // 4096

// Scratch (no cudaMalloc allowed)
__device__ float g_Q[(size_t)MM * NQ * HD];
__device__ float g_K[(size_t)MM * NKV * HD];
__device__ float g_V[(size_t)MM * NKV * HD];
__device__ float g_attn[(size_t)MM * DD];

__device__ __forceinline__ uint32_t f2tf32(float f) {
    uint32_t o;
    asm("cvt.rna.tf32.f32 %0, %1;" : "=r"(o) : "f"(f));
    return o;
}

__device__ __forceinline__ void mma_tf32(float* c, const uint32_t* a, uint32_t b0, uint32_t b1) {
    asm volatile(
        "mma.sync.aligned.m16n8k8.row.col.f32.tf32.tf32.f32 "
        "{%0,%1,%2,%3}, {%4,%5,%6,%7}, {%8,%9}, {%0,%1,%2,%3};"
        : "+f"(c[0]), "+f"(c[1]), "+f"(c[2]), "+f"(c[3])
        : "r"(a[0]), "r"(a[1]), "r"(a[2]), "r"(a[3]), "r"(b0), "r"(b1));
}

__device__ __forceinline__ void cp16(float* dst, const float* src) {
    uint32_t d = (uint32_t)__cvta_generic_to_shared(dst);
    asm volatile("cp.async.cg.shared.global [%0], [%1], 16;" :: "r"(d), "l"(src));
}
__device__ __forceinline__ void cp_commit() { asm volatile("cp.async.commit_group;"); }
__device__ __forceinline__ void cp_wait1()  { asm volatile("cp.async.wait_group 1;"); }

// ---------------------------------------------------------------------------
// TF32 GEMM, 3-stage cp.async pipeline. C = A * B^T.
// Block 128x128, BK=16, 256 threads (8 warps 2x4 -> 64x32 warp tile).
// smem holds fp32 (stride 20 floats, conflict-free); cvt to tf32 at frag load.
// ---------------------------------------------------------------------------
#define AST 20
#define STAGE_F (128 * AST)   // 2560 floats per operand per stage

__global__ __launch_bounds__(256, 2) void gemm_tf32(const float* __restrict__ A,
                                                    const float* __restrict__ Bm,
                                                    float* __restrict__ C,
                                                    int M, int N, int K)
{
    extern __shared__ float smem[];
    float* As = smem;                  // [3][2560]
    float* Bs = smem + 3 * STAGE_F;    // [3][2560]

    int tid = threadIdx.x;
    int lane = tid & 31;
    int warp = tid >> 5;
    int wm = warp >> 2, wn = warp & 3;
    int bm = blockIdx.y * 128, bn = blockIdx.x * 128;
    int lg = lane >> 2, lk = lane & 3;

    float acc[4][4][4];
#pragma unroll
    for (int i = 0; i < 4; i++)
#pragma unroll
        for (int j = 0; j < 4; j++)
#pragma unroll
            for (int t = 0; t < 4; t++) acc[i][j][t] = 0.f;

    // loader: 256 threads -> rows 0..63 (r0) and 64..127 (r1), 4 float4 per row
    int r0 = tid >> 2, kc = (tid & 3) * 4;
    int r1 = r0 + 64;

    const float* Ab0 = A + (size_t)(bm + r0) * K + kc;
    const float* Ab1 = A + (size_t)(bm + r1) * K + kc;
    const float* Bb0 = Bm + (size_t)(bn + r0) * K + kc;
    const float* Bb1 = Bm + (size_t)(bn + r1) * K + kc;

    int NT = K / 16;

    // prologue: prefetch tiles 0,1
#pragma unroll
    for (int t = 0; t < 2; t++) {
        float* as = As + t * STAGE_F;
        float* bs = Bs + t * STAGE_F;
        cp16(as + r0 * AST + kc, Ab0 + t * 16);
        cp16(as + r1 * AST + kc, Ab1 + t * 16);
        cp16(bs + r0 * AST + kc, Bb0 + t * 16);
        cp16(bs + r1 * AST + kc, Bb1 + t * 16);
        cp_commit();
    }

    for (int i = 0; i < NT; i++) {
        cp_wait1();
        __syncthreads();
        if (i + 2 < NT) {
            int sl = (i + 2) % 3;
            float* as = As + sl * STAGE_F;
            float* bs = Bs + sl * STAGE_F;
            cp16(as + r0 * AST + kc, Ab0 + (i + 2) * 16);
            cp16(as + r1 * AST + kc, Ab1 + (i + 2) * 16);
            cp16(bs + r0 * AST + kc, Bb0 + (i + 2) * 16);
            cp16(bs + r1 * AST + kc, Bb1 + (i + 2) * 16);
        }
        cp_commit();

        float* as = As + (i % 3) * STAGE_F;
        float* bs = Bs + (i % 3) * STAGE_F;
#pragma unroll
        for (int kk = 0; kk < 16; kk += 8) {
            uint32_t af[4][4];
#pragma unroll
            for (int mi = 0; mi < 4; mi++) {
                int r = wm * 64 + mi * 16;
                af[mi][0] = f2tf32(as[(r + lg) * AST + kk + lk]);
                af[mi][1] = f2tf32(as[(r + 8 + lg) * AST + kk + lk]);
                af[mi][2] = f2tf32(as[(r + lg) * AST + kk + 4 + lk]);
                af[mi][3] = f2tf32(as[(r + 8 + lg) * AST + kk + 4 + lk]);
            }
            uint32_t bf[4][2];
#pragma unroll
            for (int ni = 0; ni < 4; ni++) {
                int c = wn * 32 + ni * 8;
                bf[ni][0] = f2tf32(bs[(c + lg) * AST + kk + lk]);
                bf[ni][1] = f2tf32(bs[(c + lg) * AST + kk + 4 + lk]);
            }
#pragma unroll
            for (int mi = 0; mi < 4; mi++)
#pragma unroll
                for (int ni = 0; ni < 4; ni++)
                    mma_tf32(acc[mi][ni], af[mi], bf[ni][0], bf[ni][1]);
        }
    }

#pragma unroll
    for (int mi = 0; mi < 4; mi++) {
#pragma unroll
        for (int ni = 0; ni < 4; ni++) {
            int rr = bm + wm * 64 + mi * 16 + lg;
            int cc = bn + wn * 32 + ni * 8 + lk * 2;
            *(float2*)(C + (size_t)rr * N + cc) = make_float2(acc[mi][ni][0], acc[mi][ni][1]);
            *(float2*)(C + (size_t)(rr + 8) * N + cc) = make_float2(acc[mi][ni][2], acc[mi][ni][3]);
        }
    }
}

// ---------------------------------------------------------------------------
// RoPE (in-place). X layout: [B*S, nheads*HD]. Pair (i, i+32), i in [0,32).
// ---------------------------------------------------------------------------
__global__ void rope_kernel(float* __restrict__ X, int nheads)
{
    int idx = blockIdx.x * blockDim.x + threadIdx.x;
    int total = MM * nheads * (HD / 2);
    if (idx >= total) return;
    int i = idx & 31;
    int t = idx >> 5;
    int h = t % nheads;
    int ms = t / nheads;
    int s = ms & (SS - 1);

    const float LOG_THETA_OVER_HALF = 9.210340371976184f / 32.0f;
    float inv = expf(-(float)i * LOG_THETA_OVER_HALF);
    float ang = (float)s * inv;
    float sn, cs;
    sincosf(ang, &sn, &cs);

    float* base = X + (size_t)ms * nheads * HD + h * HD;
    float x1 = base[i];
    float x2 = base[i + 32];
    base[i]      = x1 * cs - x2 * sn;
    base[i + 32] = x2 * cs + x1 * sn;
}

// ---------------------------------------------------------------------------
// Tensor-core flash attention, causal. 64x64 tiles, tf32 mma, online softmax.
// grid (S/64, NQ, B), block 128 (4 warps; warp w owns q-rows w*16..w*16+15).
// smem: Qs/Ks/Ps stride 68, Vs stride 72 (all conflict-free for frag patterns).
// ---------------------------------------------------------------------------
#define QST 68
#define VST 72

__global__ __launch_bounds__(128) void attn_kernel()
{
    extern __shared__ float sm[];
    float* Qs = sm;                     // 64 x 68
    float* Ks = sm + 64 * QST;          // 64 x 68
    float* Ps = sm + 2 * 64 * QST;      // 64 x 68
    float* Vs = sm + 3 * 64 * QST;      // 64 x 72

    int qt = blockIdx.x, h = blockIdx.y, b = blockIdx.z;
    int kvh = h >> 2;
    int tid = threadIdx.x, lane = tid & 31, w = tid >> 5;
    int lg = lane >> 2, lk = lane & 3;

    // load Q tile (fp32, float4 coalesced)
    const float* Qg = g_Q + (size_t)(b * SS + qt * 64) * (NQ * HD) + h * HD;
    for (int i = tid; i < 64 * 16; i += 128) {
        int rr = i >> 4, c4 = (i & 15) * 4;
        *(float4*)&Qs[rr * QST + c4] = *(const float4*)(Qg + (size_t)rr * (NQ * HD) + c4);
    }
    __syncthreads();

    // preload Q fragments (tf32) for this warp's 16 rows
    uint32_t qf[8][4];
    int qr0 = w * 16 + lg, qr1 = qr0 + 8;
#pragma unroll
    for (int kk = 0; kk < 8; kk++) {
        qf[kk][0] = f2tf32(Qs[qr0 * QST + kk * 8 + lk]);
        qf[kk][1] = f2tf32(Qs[qr1 * QST + kk * 8 + lk]);
        qf[kk][2] = f2tf32(Qs[qr0 * QST + kk * 8 + 4 + lk]);
        qf[kk][3] = f2tf32(Qs[qr1 * QST + kk * 8 + 4 + lk]);
    }

    float o[8][4];
#pragma unroll
    for (int j = 0; j < 8; j++)
#pragma unroll
        for (int t = 0; t < 4; t++) o[j][t] = 0.f;
    float m0 = -INFINITY, m1 = -INFINITY, l0 = 0.f, l1 = 0.f;
    int row0 = qt * 64 + w * 16 + lg, row1 = row0 + 8;

    for (int kt = 0; kt <= qt; kt++) {
        __syncthreads();
        const float* Kg = g_K + (size_t)(b * SS + kt * 64) * (NKV * HD) + kvh * HD;
        const float* Vg = g_V + (size_t)(b * SS + kt * 64) * (NKV * HD) + kvh * HD;
        for (int i = tid; i < 64 * 16; i += 128) {
            int rr = i >> 4, c4 = (i & 15) * 4;
            *(float4*)&Ks[rr * QST + c4] = *(const float4*)(Kg + (size_t)rr * (NKV * HD) + c4);
            *(float4*)&Vs[rr * VST + c4] = *(const float4*)(Vg + (size_t)rr * (NKV * HD) + c4);
        }
        __syncthreads();

        // S = Q K^T  (per n-tile j of 8 cols)
        float s[8][4];
#pragma unroll
        for (int j = 0; j < 8; j++) {
            s[j][0] = s[j][1] = s[j][2] = s[j][3] = 0.f;
#pragma unroll
            for (int kk = 0; kk < 8; kk++) {
                uint32_t b0 = f2tf32(Ks[(j * 8 + lg) * QST + kk * 8 + lk]);
                uint32_t b1 = f2tf32(Ks[(j * 8 + lg) * QST + kk * 8 + 4 + lk]);
                mma_tf32(s[j], qf[kk], b0, b1);
            }
        }
        const float scale = 0.125f;
#pragma unroll
        for (int j = 0; j < 8; j++) {
            s[j][0] *= scale; s[j][1] *= scale; s[j][2] *= scale; s[j][3] *= scale;
        }
        if (kt == qt) {
#pragma unroll
            for (int j = 0; j < 8; j++) {
                int c0 = kt * 64 + j * 8 + 2 * lk, c1 = c0 + 1;
                if (c0 > row0) s[j][0] = -INFINITY;
                if (c1 > row0) s[j][1] = -INFINITY;
                if (c0 > row1) s[j][2] = -INFINITY;
                if (c1 > row1) s[j][3] = -INFINITY;
            }
        }

        // row maxima (quad lanes share a row)
        float mn0 = s[0][0], mn1 = s[0][2];
#pragma unroll
        for (int j = 0; j < 8; j++) {
            mn0 = fmaxf(mn0, fmaxf(s[j][0], s[j][1]));
            mn1 = fmaxf(mn1, fmaxf(s[j][2], s[j][3]));
        }
        mn0 = fmaxf(mn0, __shfl_xor_sync(0xffffffffu, mn0, 1));
        mn0 = fmaxf(mn0, __shfl_xor_sync(0xffffffffu, mn0, 2));
        mn1 = fmaxf(mn1, __shfl_xor_sync(0xffffffffu, mn1, 1));
        mn1 = fmaxf(mn1, __shfl_xor_sync(0xffffffffu, mn1, 2));
        float mnew0 = fmaxf(m0, mn0), mnew1 = fmaxf(m1, mn1);
        float a0 = expf(m0 - mnew0), a1 = expf(m1 - mnew1);

        float ll0 = 0.f, ll1 = 0.f;
#pragma unroll
        for (int j = 0; j < 8; j++) {
            float p0 = expf(s[j][0] - mnew0);
            float p1 = expf(s[j][1] - mnew0);
            float p2 = expf(s[j][2] - mnew1);
            float p3 = expf(s[j][3] - mnew1);
            ll0 += p0 + p1; ll1 += p2 + p3;
            *(float2*)&Ps[qr0 * QST + j * 8 + 2 * lk] = make_float2(p0, p1);
            *(float2*)&Ps[qr1 * QST + j * 8 + 2 * lk] = make_float2(p2, p3);
        }
        ll0 += __shfl_xor_sync(0xffffffffu, ll0, 1);
        ll0 += __shfl_xor_sync(0xffffffffu, ll0, 2);
        ll1 += __shfl_xor_sync(0xffffffffu, ll1, 1);
        ll1 += __shfl_xor_sync(0xffffffffu, ll1, 2);
        l0 = l0 * a0 + ll0; l1 = l1 * a1 + ll1;
        m0 = mnew0; m1 = mnew1;
#pragma unroll
        for (int j = 0; j < 8; j++) {
            o[j][0] *= a0; o[j][1] *= a0; o[j][2] *= a1; o[j][3] *= a1;
        }
        __syncwarp();

        // P fragments (A-layout) from smem
        uint32_t pf[8][4];
#pragma unroll
        for (int kk = 0; kk < 8; kk++) {
            pf[kk][0] = f2tf32(Ps[qr0 * QST + kk * 8 + lk]);
            pf[kk][1] = f2tf32(Ps[qr1 * QST + kk * 8 + lk]);
            pf[kk][2] = f2tf32(Ps[qr0 * QST + kk * 8 + 4 + lk]);
            pf[kk][3] = f2tf32(Ps[qr1 * QST + kk * 8 + 4 + lk]);
        }
        // O += P V   (B-frag = V^T read from Vs[k][n])
#pragma unroll
        for (int j = 0; j < 8; j++) {
#pragma unroll
            for (int kk = 0; kk < 8; kk++) {
                uint32_t b0 = f2tf32(Vs[(kk * 8 + lk) * VST + j * 8 + lg]);
                uint32_t b1 = f2tf32(Vs[(kk * 8 + lk + 4) * VST + j * 8 + lg]);
                mma_tf32(o[j], pf[kk], b0, b1);
            }
        }
    }

    float il0 = 1.0f / l0, il1 = 1.0f / l1;
    int gr0 = b * SS + qt * 64 + w * 16 + lg;
#pragma unroll
    for (int j = 0; j < 8; j++) {
        int cc = h * HD + j * 8 + 2 * lk;
        *(float2*)(g_attn + (size_t)gr0 * DD + cc) = make_float2(o[j][0] * il0, o[j][1] * il0);
        *(float2*)(g_attn + (size_t)(gr0 + 8) * DD + cc) = make_float2(o[j][2] * il1, o[j][3] * il1);
    }
}

// ---------------------------------------------------------------------------
extern "C" void kernel_launch(void* const* d_in, const int* in_sizes, int n_in,
                              void* d_out, int out_size)
{
    const float* x  = (const float*)d_in[0];
    const float* Wq = (const float*)d_in[2];
    const float* Wk = (const float*)d_in[3];
    const float* Wv = (const float*)d_in[4];
    const float* Wo = (const float*)d_in[5];
    float* out = (float*)d_out;

    float *Qp, *Kp, *Vp, *Ap;
    cudaGetSymbolAddress((void**)&Qp, g_Q);
    cudaGetSymbolAddress((void**)&Kp, g_K);
    cudaGetSymbolAddress((void**)&Vp, g_V);
    cudaGetSymbolAddress((void**)&Ap, g_attn);

    int gemm_smem = 3 * 2 * STAGE_F * (int)sizeof(float);   // 61440
    cudaFuncSetAttribute(gemm_tf32, cudaFuncAttributeMaxDynamicSharedMemorySize, gemm_smem);

    gemm_tf32<<<dim3(DD / 128, MM / 128), 256, gemm_smem>>>(x, Wq, Qp, MM, DD, DD);
    gemm_tf32<<<dim3((NKV * HD) / 128, MM / 128), 256, gemm_smem>>>(x, Wk, Kp, MM, NKV * HD, DD);
    gemm_tf32<<<dim3((NKV * HD) / 128, MM / 128), 256, gemm_smem>>>(x, Wv, Vp, MM, NKV * HD, DD);

    {
        int totq = MM * NQ * (HD / 2);
        rope_kernel<<<(totq + 255) / 256, 256>>>(Qp, NQ);
        int totk = MM * NKV * (HD / 2);
        rope_kernel<<<(totk + 255) / 256, 256>>>(Kp, NKV);
    }

    {
        int smem = (3 * 64 * QST + 64 * VST) * (int)sizeof(float);   // 70656
        cudaFuncSetAttribute(attn_kernel, cudaFuncAttributeMaxDynamicSharedMemorySize, smem);
        attn_kernel<<<dim3(SS / 64, NQ, BB), 128, smem>>>();
    }

    gemm_tf32<<<dim3(DD / 128, MM / 128), 256, gemm_smem>>>(Ap, Wo, out, MM, DD, DD);
}

// round 4
// speedup vs baseline: 6.6053x; 1.1477x over previous
#include <cuda_runtime.h>
#include <math.h>
#include <stdint.h>

#define BB 2
#define SS 2048
#define DD 2048
#define NQ 32
#define NKV 8
#define HD 64
#define MM (BB*SS)   // 4096

// Scratch (no cudaMalloc allowed)
__device__ float g_Q[(size_t)MM * NQ * HD];
__device__ float g_K[(size_t)MM * NKV * HD];
__device__ float g_V[(size_t)MM * NKV * HD];
__device__ float g_attn[(size_t)MM * DD];
// tf32-rounded copies
__device__ float g_xT[(size_t)MM * DD];
__device__ float g_WqT[(size_t)DD * DD];
__device__ float g_WkT[(size_t)(NKV*HD) * DD];
__device__ float g_WvT[(size_t)(NKV*HD) * DD];
__device__ float g_WoT[(size_t)DD * DD];

__device__ __forceinline__ uint32_t f2tf32(float f) {
    uint32_t o;
    asm("cvt.rna.tf32.f32 %0, %1;" : "=r"(o) : "f"(f));
    return o;
}

__device__ __forceinline__ void mma_tf32(float* c, const uint32_t* a, uint32_t b0, uint32_t b1) {
    asm volatile(
        "mma.sync.aligned.m16n8k8.row.col.f32.tf32.tf32.f32 "
        "{%0,%1,%2,%3}, {%4,%5,%6,%7}, {%8,%9}, {%0,%1,%2,%3};"
        : "+f"(c[0]), "+f"(c[1]), "+f"(c[2]), "+f"(c[3])
        : "r"(a[0]), "r"(a[1]), "r"(a[2]), "r"(a[3]), "r"(b0), "r"(b1));
}

__device__ __forceinline__ void ldsm_x4(uint32_t* d, uint32_t saddr) {
    asm volatile("ldmatrix.sync.aligned.m8n8.x4.shared.b16 {%0,%1,%2,%3}, [%4];"
        : "=r"(d[0]), "=r"(d[1]), "=r"(d[2]), "=r"(d[3]) : "r"(saddr));
}

__device__ __forceinline__ void cp16(uint32_t dst, const float* src) {
    asm volatile("cp.async.cg.shared.global [%0], [%1], 16;" :: "r"(dst), "l"(src));
}
__device__ __forceinline__ void cp_commit() { asm volatile("cp.async.commit_group;"); }
__device__ __forceinline__ void cp_wait2()  { asm volatile("cp.async.wait_group 2;"); }

// ---------------------------------------------------------------------------
// Elementwise tf32 rounding (RNA), vectorized.
// ---------------------------------------------------------------------------
__global__ void cvt_tf32_kernel(const float* __restrict__ in, float* __restrict__ out, int n4)
{
    int i = blockIdx.x * blockDim.x + threadIdx.x;
    if (i >= n4) return;
    float4 v = ((const float4*)in)[i];
    v.x = __uint_as_float(f2tf32(v.x));
    v.y = __uint_as_float(f2tf32(v.y));
    v.z = __uint_as_float(f2tf32(v.z));
    v.w = __uint_as_float(f2tf32(v.w));
    ((float4*)out)[i] = v;
}

// ---------------------------------------------------------------------------
// TF32 GEMM, 4-stage cp.async, ldmatrix fragments. C = A * B^T.
// Inputs MUST be pre-rounded to tf32. Block 128x128, BK=16, 128 threads
// (4 warps, 2x2 -> 64x64 warp tile). smem stride 20 floats.
// ---------------------------------------------------------------------------
#define AST 20
#define STAGE_F (128 * AST)   // floats per operand per stage
#define NSTG 4

__global__ __launch_bounds__(128, 2) void gemm_tf32(const float* __restrict__ A,
                                                    const float* __restrict__ Bm,
                                                    float* __restrict__ C,
                                                    int M, int N, int K)
{
    extern __shared__ float smem[];
    float* As = smem;                     // [4][STAGE_F]
    float* Bs = smem + NSTG * STAGE_F;

    int tid = threadIdx.x;
    int lane = tid & 31;
    int warp = tid >> 5;
    int wm = warp >> 1, wn = warp & 1;    // 2x2 warp grid
    int bm = blockIdx.y * 128, bn = blockIdx.x * 128;
    int lg = lane >> 2, lk = lane & 3;

    uint32_t As_u = (uint32_t)__cvta_generic_to_shared(As);
    uint32_t Bs_u = (uint32_t)__cvta_generic_to_shared(Bs);

    // ldmatrix lane offsets
    int a_row = (lane & 7) + ((lane >> 3) & 1) * 8;   // row within 16
    int a_k   = (lane >> 4) * 4;                      // k-chunk select
    int b_row = (lane & 7) + (lane >> 4) * 8;
    int b_k   = ((lane >> 3) & 1) * 4;
    uint32_t a_off = (uint32_t)(((wm * 64 + a_row) * AST + a_k) * 4);
    uint32_t b_off = (uint32_t)(((wn * 64 + b_row) * AST + b_k) * 4);

    float acc[4][8][4];
#pragma unroll
    for (int i = 0; i < 4; i++)
#pragma unroll
        for (int j = 0; j < 8; j++)
#pragma unroll
            for (int t = 0; t < 4; t++) acc[i][j][t] = 0.f;

    // loader: 128 threads, 4 rows each (r, r+32, r+64, r+96), one float4 per row
    int lr = tid >> 2, kc = (tid & 3) * 4;
    const float* Ab = A + (size_t)(bm + lr) * K + kc;
    const float* Bb = Bm + (size_t)(bn + lr) * K + kc;
    uint32_t sA = (uint32_t)((lr * AST + kc) * 4);
    uint32_t sB = sA;
    const size_t strA = (size_t)32 * K;
    const uint32_t strS = 32 * AST * 4;

    int NT = K / 16;

#pragma unroll
    for (int t = 0; t < 3; t++) {
        uint32_t as = As_u + t * STAGE_F * 4;
        uint32_t bs = Bs_u + t * STAGE_F * 4;
#pragma unroll
        for (int rr = 0; rr < 4; rr++) {
            cp16(as + sA + rr * strS, Ab + t * 16 + rr * strA);
            cp16(bs + sB + rr * strS, Bb + t * 16 + rr * strA);
        }
        cp_commit();
    }

    for (int i = 0; i < NT; i++) {
        cp_wait2();
        __syncthreads();
        if (i + 3 < NT) {
            int sl = (i + 3) & 3;
            uint32_t as = As_u + sl * STAGE_F * 4;
            uint32_t bs = Bs_u + sl * STAGE_F * 4;
#pragma unroll
            for (int rr = 0; rr < 4; rr++) {
                cp16(as + sA + rr * strS, Ab + (i + 3) * 16 + rr * strA);
                cp16(bs + sB + rr * strS, Bb + (i + 3) * 16 + rr * strA);
            }
        }
        cp_commit();

        uint32_t as = As_u + (i & 3) * STAGE_F * 4;
        uint32_t bs = Bs_u + (i & 3) * STAGE_F * 4;
#pragma unroll
        for (int kk = 0; kk < 16; kk += 8) {
            uint32_t af[4][4];
#pragma unroll
            for (int mi = 0; mi < 4; mi++)
                ldsm_x4(af[mi], as + a_off + (uint32_t)((mi * 16 * AST + kk) * 4));
            uint32_t bf[4][4];
#pragma unroll
            for (int np = 0; np < 4; np++)
                ldsm_x4(bf[np], bs + b_off + (uint32_t)((np * 16 * AST + kk) * 4));
#pragma unroll
            for (int mi = 0; mi < 4; mi++)
#pragma unroll
                for (int ni = 0; ni < 8; ni++)
                    mma_tf32(acc[mi][ni], af[mi], bf[ni >> 1][(ni & 1) * 2], bf[ni >> 1][(ni & 1) * 2 + 1]);
        }
    }

#pragma unroll
    for (int mi = 0; mi < 4; mi++) {
#pragma unroll
        for (int ni = 0; ni < 8; ni++) {
            int rr = bm + wm * 64 + mi * 16 + lg;
            int cc = bn + wn * 64 + ni * 8 + lk * 2;
            *(float2*)(C + (size_t)rr * N + cc) = make_float2(acc[mi][ni][0], acc[mi][ni][1]);
            *(float2*)(C + (size_t)(rr + 8) * N + cc) = make_float2(acc[mi][ni][2], acc[mi][ni][3]);
        }
    }
}

// ---------------------------------------------------------------------------
// RoPE (in-place, rounds result to tf32 since Q/K feed attention mma anyway).
// ---------------------------------------------------------------------------
__global__ void rope_kernel(float* __restrict__ X, int nheads)
{
    int idx = blockIdx.x * blockDim.x + threadIdx.x;
    int total = MM * nheads * (HD / 2);
    if (idx >= total) return;
    int i = idx & 31;
    int t = idx >> 5;
    int h = t % nheads;
    int ms = t / nheads;
    int s = ms & (SS - 1);

    const float LOG_THETA_OVER_HALF = 9.210340371976184f / 32.0f;
    float inv = expf(-(float)i * LOG_THETA_OVER_HALF);
    float ang = (float)s * inv;
    float sn, cs;
    sincosf(ang, &sn, &cs);

    float* base = X + (size_t)ms * nheads * HD + h * HD;
    float x1 = base[i];
    float x2 = base[i + 32];
    base[i]      = x1 * cs - x2 * sn;
    base[i + 32] = x2 * cs + x1 * sn;
}

// ---------------------------------------------------------------------------
// Tensor-core flash attention, causal. 64x64 tiles, tf32 mma, online softmax.
// grid (S/64, NQ, B), block 128. Output rounded to tf32 (feeds Wo GEMM).
// ---------------------------------------------------------------------------
#define QST 68
#define VST 72

__global__ __launch_bounds__(128) void attn_kernel()
{
    extern __shared__ float sm[];
    float* Qs = sm;
    float* Ks = sm + 64 * QST;
    float* Ps = sm + 2 * 64 * QST;
    float* Vs = sm + 3 * 64 * QST;

    int qt = blockIdx.x, h = blockIdx.y, b = blockIdx.z;
    int kvh = h >> 2;
    int tid = threadIdx.x, lane = tid & 31, w = tid >> 5;
    int lg = lane >> 2, lk = lane & 3;

    const float* Qg = g_Q + (size_t)(b * SS + qt * 64) * (NQ * HD) + h * HD;
    for (int i = tid; i < 64 * 16; i += 128) {
        int rr = i >> 4, c4 = (i & 15) * 4;
        *(float4*)&Qs[rr * QST + c4] = *(const float4*)(Qg + (size_t)rr * (NQ * HD) + c4);
    }
    __syncthreads();

    uint32_t qf[8][4];
    int qr0 = w * 16 + lg, qr1 = qr0 + 8;
#pragma unroll
    for (int kk = 0; kk < 8; kk++) {
        qf[kk][0] = f2tf32(Qs[qr0 * QST + kk * 8 + lk]);
        qf[kk][1] = f2tf32(Qs[qr1 * QST + kk * 8 + lk]);
        qf[kk][2] = f2tf32(Qs[qr0 * QST + kk * 8 + 4 + lk]);
        qf[kk][3] = f2tf32(Qs[qr1 * QST + kk * 8 + 4 + lk]);
    }

    float o[8][4];
#pragma unroll
    for (int j = 0; j < 8; j++)
#pragma unroll
        for (int t = 0; t < 4; t++) o[j][t] = 0.f;
    float m0 = -INFINITY, m1 = -INFINITY, l0 = 0.f, l1 = 0.f;
    int row0 = qt * 64 + w * 16 + lg, row1 = row0 + 8;

    for (int kt = 0; kt <= qt; kt++) {
        __syncthreads();
        const float* Kg = g_K + (size_t)(b * SS + kt * 64) * (NKV * HD) + kvh * HD;
        const float* Vg = g_V + (size_t)(b * SS + kt * 64) * (NKV * HD) + kvh * HD;
        for (int i = tid; i < 64 * 16; i += 128) {
            int rr = i >> 4, c4 = (i & 15) * 4;
            *(float4*)&Ks[rr * QST + c4] = *(const float4*)(Kg + (size_t)rr * (NKV * HD) + c4);
            *(float4*)&Vs[rr * VST + c4] = *(const float4*)(Vg + (size_t)rr * (NKV * HD) + c4);
        }
        __syncthreads();

        float s[8][4];
#pragma unroll
        for (int j = 0; j < 8; j++) {
            s[j][0] = s[j][1] = s[j][2] = s[j][3] = 0.f;
#pragma unroll
            for (int kk = 0; kk < 8; kk++) {
                uint32_t b0 = f2tf32(Ks[(j * 8 + lg) * QST + kk * 8 + lk]);
                uint32_t b1 = f2tf32(Ks[(j * 8 + lg) * QST + kk * 8 + 4 + lk]);
                mma_tf32(s[j], qf[kk], b0, b1);
            }
        }
        const float scale = 0.125f;
#pragma unroll
        for (int j = 0; j < 8; j++) {
            s[j][0] *= scale; s[j][1] *= scale; s[j][2] *= scale; s[j][3] *= scale;
        }
        if (kt == qt) {
#pragma unroll
            for (int j = 0; j < 8; j++) {
                int c0 = kt * 64 + j * 8 + 2 * lk, c1 = c0 + 1;
                if (c0 > row0) s[j][0] = -INFINITY;
                if (c1 > row0) s[j][1] = -INFINITY;
                if (c0 > row1) s[j][2] = -INFINITY;
                if (c1 > row1) s[j][3] = -INFINITY;
            }
        }

        float mn0 = s[0][0], mn1 = s[0][2];
#pragma unroll
        for (int j = 0; j < 8; j++) {
            mn0 = fmaxf(mn0, fmaxf(s[j][0], s[j][1]));
            mn1 = fmaxf(mn1, fmaxf(s[j][2], s[j][3]));
        }
        mn0 = fmaxf(mn0, __shfl_xor_sync(0xffffffffu, mn0, 1));
        mn0 = fmaxf(mn0, __shfl_xor_sync(0xffffffffu, mn0, 2));
        mn1 = fmaxf(mn1, __shfl_xor_sync(0xffffffffu, mn1, 1));
        mn1 = fmaxf(mn1, __shfl_xor_sync(0xffffffffu, mn1, 2));
        float mnew0 = fmaxf(m0, mn0), mnew1 = fmaxf(m1, mn1);
        float a0 = expf(m0 - mnew0), a1 = expf(m1 - mnew1);

        float ll0 = 0.f, ll1 = 0.f;
#pragma unroll
        for (int j = 0; j < 8; j++) {
            float p0 = expf(s[j][0] - mnew0);
            float p1 = expf(s[j][1] - mnew0);
            float p2 = expf(s[j][2] - mnew1);
            float p3 = expf(s[j][3] - mnew1);
            ll0 += p0 + p1; ll1 += p2 + p3;
            *(float2*)&Ps[qr0 * QST + j * 8 + 2 * lk] = make_float2(p0, p1);
            *(float2*)&Ps[qr1 * QST + j * 8 + 2 * lk] = make_float2(p2, p3);
        }
        ll0 += __shfl_xor_sync(0xffffffffu, ll0, 1);
        ll0 += __shfl_xor_sync(0xffffffffu, ll0, 2);
        ll1 += __shfl_xor_sync(0xffffffffu, ll1, 1);
        ll1 += __shfl_xor_sync(0xffffffffu, ll1, 2);
        l0 = l0 * a0 + ll0; l1 = l1 * a1 + ll1;
        m0 = mnew0; m1 = mnew1;
#pragma unroll
        for (int j = 0; j < 8; j++) {
            o[j][0] *= a0; o[j][1] *= a0; o[j][2] *= a1; o[j][3] *= a1;
        }
        __syncwarp();

        uint32_t pf[8][4];
#pragma unroll
        for (int kk = 0; kk < 8; kk++) {
            pf[kk][0] = f2tf32(Ps[qr0 * QST + kk * 8 + lk]);
            pf[kk][1] = f2tf32(Ps[qr1 * QST + kk * 8 + lk]);
            pf[kk][2] = f2tf32(Ps[qr0 * QST + kk * 8 + 4 + lk]);
            pf[kk][3] = f2tf32(Ps[qr1 * QST + kk * 8 + 4 + lk]);
        }
#pragma unroll
        for (int j = 0; j < 8; j++) {
#pragma unroll
            for (int kk = 0; kk < 8; kk++) {
                uint32_t b0 = f2tf32(Vs[(kk * 8 + lk) * VST + j * 8 + lg]);
                uint32_t b1 = f2tf32(Vs[(kk * 8 + lk + 4) * VST + j * 8 + lg]);
                mma_tf32(o[j], pf[kk], b0, b1);
            }
        }
    }

    float il0 = 1.0f / l0, il1 = 1.0f / l1;
    int gr0 = b * SS + qt * 64 + w * 16 + lg;
#pragma unroll
    for (int j = 0; j < 8; j++) {
        int cc = h * HD + j * 8 + 2 * lk;
        float2 v0 = make_float2(__uint_as_float(f2tf32(o[j][0] * il0)),
                                __uint_as_float(f2tf32(o[j][1] * il0)));
        float2 v1 = make_float2(__uint_as_float(f2tf32(o[j][2] * il1)),
                                __uint_as_float(f2tf32(o[j][3] * il1)));
        *(float2*)(g_attn + (size_t)gr0 * DD + cc) = v0;
        *(float2*)(g_attn + (size_t)(gr0 + 8) * DD + cc) = v1;
    }
}

// ---------------------------------------------------------------------------
extern "C" void kernel_launch(void* const* d_in, const int* in_sizes, int n_in,
                              void* d_out, int out_size)
{
    const float* x  = (const float*)d_in[0];
    const float* Wq = (const float*)d_in[2];
    const float* Wk = (const float*)d_in[3];
    const float* Wv = (const float*)d_in[4];
    const float* Wo = (const float*)d_in[5];
    float* out = (float*)d_out;

    float *Qp, *Kp, *Vp, *Ap, *xT, *WqT, *WkT, *WvT, *WoT;
    cudaGetSymbolAddress((void**)&Qp, g_Q);
    cudaGetSymbolAddress((void**)&Kp, g_K);
    cudaGetSymbolAddress((void**)&Vp, g_V);
    cudaGetSymbolAddress((void**)&Ap, g_attn);
    cudaGetSymbolAddress((void**)&xT, g_xT);
    cudaGetSymbolAddress((void**)&WqT, g_WqT);
    cudaGetSymbolAddress((void**)&WkT, g_WkT);
    cudaGetSymbolAddress((void**)&WvT, g_WvT);
    cudaGetSymbolAddress((void**)&WoT, g_WoT);

    // tf32 pre-rounding
    {
        int n4;
        n4 = MM * DD / 4;            cvt_tf32_kernel<<<(n4 + 255) / 256, 256>>>(x,  xT,  n4);
        n4 = DD * DD / 4;            cvt_tf32_kernel<<<(n4 + 255) / 256, 256>>>(Wq, WqT, n4);
        n4 = (NKV * HD) * DD / 4;    cvt_tf32_kernel<<<(n4 + 255) / 256, 256>>>(Wk, WkT, n4);
        n4 = (NKV * HD) * DD / 4;    cvt_tf32_kernel<<<(n4 + 255) / 256, 256>>>(Wv, WvT, n4);
        n4 = DD * DD / 4;            cvt_tf32_kernel<<<(n4 + 255) / 256, 256>>>(Wo, WoT, n4);
    }

    int gemm_smem = NSTG * 2 * STAGE_F * (int)sizeof(float);   // 81920
    cudaFuncSetAttribute(gemm_tf32, cudaFuncAttributeMaxDynamicSharedMemorySize, gemm_smem);

    gemm_tf32<<<dim3(DD / 128, MM / 128), 128, gemm_smem>>>(xT, WqT, Qp, MM, DD, DD);
    gemm_tf32<<<dim3((NKV * HD) / 128, MM / 128), 128, gemm_smem>>>(xT, WkT, Kp, MM, NKV * HD, DD);
    gemm_tf32<<<dim3((NKV * HD) / 128, MM / 128), 128, gemm_smem>>>(xT, WvT, Vp, MM, NKV * HD, DD);

    {
        int totq = MM * NQ * (HD / 2);
        rope_kernel<<<(totq + 255) / 256, 256>>>(Qp, NQ);
        int totk = MM * NKV * (HD / 2);
        rope_kernel<<<(totk + 255) / 256, 256>>>(Kp, NKV);
    }

    {
        int smem = (3 * 64 * QST + 64 * VST) * (int)sizeof(float);
        cudaFuncSetAttribute(attn_kernel, cudaFuncAttributeMaxDynamicSharedMemorySize, smem);
        attn_kernel<<<dim3(SS / 64, NQ, BB), 128, smem>>>();
    }

    gemm_tf32<<<dim3(DD / 128, MM / 128), 128, gemm_smem>>>(Ap, WoT, out, MM, DD, DD);
}

// round 6
// speedup vs baseline: 8.0279x; 1.2154x over previous
#include <cuda_runtime.h>
#include <math.h>
#include <stdint.h>

#define BB 2
#define SS 2048
#define DD 2048
#define NQ 32
#define NKV 8
#define HD 64
#define MM (BB*SS)   // 4096
#define KK 2048

// Scratch (no cudaMalloc allowed)
__device__ float g_Q[(size_t)MM * NQ * HD];
__device__ float g_K[(size_t)MM * NKV * HD];
__device__ float g_V[(size_t)MM * NKV * HD];
__device__ float g_attn[(size_t)MM * DD];
// tf32-rounded copies
__device__ float g_xT[(size_t)MM * DD];
__device__ float g_WqT[(size_t)DD * DD];
__device__ float g_WkT[(size_t)(NKV*HD) * DD];
__device__ float g_WvT[(size_t)(NKV*HD) * DD];
__device__ float g_WoT[(size_t)DD * DD];

__device__ __forceinline__ uint32_t f2tf32(float f) {
    uint32_t o;
    asm("cvt.rna.tf32.f32 %0, %1;" : "=r"(o) : "f"(f));
    return o;
}

__device__ __forceinline__ void mma_tf32(float* c, const uint32_t* a, uint32_t b0, uint32_t b1) {
    asm volatile(
        "mma.sync.aligned.m16n8k8.row.col.f32.tf32.tf32.f32 "
        "{%0,%1,%2,%3}, {%4,%5,%6,%7}, {%8,%9}, {%0,%1,%2,%3};"
        : "+f"(c[0]), "+f"(c[1]), "+f"(c[2]), "+f"(c[3])
        : "r"(a[0]), "r"(a[1]), "r"(a[2]), "r"(a[3]), "r"(b0), "r"(b1));
}

__device__ __forceinline__ void ldsm_x4(uint32_t* d, uint32_t saddr) {
    asm volatile("ldmatrix.sync.aligned.m8n8.x4.shared.b16 {%0,%1,%2,%3}, [%4];"
        : "=r"(d[0]), "=r"(d[1]), "=r"(d[2]), "=r"(d[3]) : "r"(saddr));
}

__device__ __forceinline__ void cp16(uint32_t dst, const float* src) {
    asm volatile("cp.async.cg.shared.global [%0], [%1], 16;" :: "r"(dst), "l"(src));
}
__device__ __forceinline__ void cp_commit() { asm volatile("cp.async.commit_group;"); }
__device__ __forceinline__ void cp_wait2()  { asm volatile("cp.async.wait_group 2;"); }

// ---------------------------------------------------------------------------
// Elementwise tf32 rounding (RNA), vectorized.
// ---------------------------------------------------------------------------
__global__ void cvt_tf32_kernel(const float* __restrict__ in, float* __restrict__ out, int n4)
{
    int i = blockIdx.x * blockDim.x + threadIdx.x;
    if (i >= n4) return;
    float4 v = ((const float4*)in)[i];
    v.x = __uint_as_float(f2tf32(v.x));
    v.y = __uint_as_float(f2tf32(v.y));
    v.z = __uint_as_float(f2tf32(v.z));
    v.w = __uint_as_float(f2tf32(v.w));
    ((float4*)out)[i] = v;
}

// ---------------------------------------------------------------------------
// TF32 GEMM, 4-stage cp.async, ldmatrix fragments. C = A * B^T.
// Inputs pre-rounded to tf32. Block 128x128, BK=16, 128 threads
// (4 warps, 2x2 -> 64x64 warp tile). smem stride 20 floats.
// Fused variant: grid.x routes to (W0,C0,N0) for bx<nb0, etc.
// ---------------------------------------------------------------------------
#define AST 20
#define STAGE_F (128 * AST)
#define NSTG 4
#define GEMM_SMEM (NSTG * 2 * STAGE_F * (int)sizeof(float))

__global__ __launch_bounds__(128, 2) void gemm_tf32(
    const float* __restrict__ A,
    const float* __restrict__ W0, const float* __restrict__ W1, const float* __restrict__ W2,
    float* __restrict__ C0, float* __restrict__ C1, float* __restrict__ C2,
    int nb0, int nb1)
{
    extern __shared__ float smem[];
    float* As = smem;
    float* Bs = smem + NSTG * STAGE_F;

    int tid = threadIdx.x;
    int lane = tid & 31;
    int warp = tid >> 5;
    int wm = warp >> 1, wn = warp & 1;
    int bx = blockIdx.x;
    int bm = blockIdx.y * 128;
    int lg = lane >> 2, lk = lane & 3;

    const float* Bsel; float* Csel; int Ncol, bn;
    if (bx < nb0)            { Bsel = W0; Csel = C0; Ncol = 2048; bn = bx * 128; }
    else if (bx < nb0 + nb1) { Bsel = W1; Csel = C1; Ncol = 512;  bn = (bx - nb0) * 128; }
    else                     { Bsel = W2; Csel = C2; Ncol = 512;  bn = (bx - nb0 - nb1) * 128; }

    uint32_t As_u = (uint32_t)__cvta_generic_to_shared(As);
    uint32_t Bs_u = (uint32_t)__cvta_generic_to_shared(Bs);

    int a_row = (lane & 7) + ((lane >> 3) & 1) * 8;
    int a_k   = (lane >> 4) * 4;
    int b_row = (lane & 7) + (lane >> 4) * 8;
    int b_k   = ((lane >> 3) & 1) * 4;
    uint32_t a_off = (uint32_t)(((wm * 64 + a_row) * AST + a_k) * 4);
    uint32_t b_off = (uint32_t)(((wn * 64 + b_row) * AST + b_k) * 4);

    float acc[4][8][4];
#pragma unroll
    for (int i = 0; i < 4; i++)
#pragma unroll
        for (int j = 0; j < 8; j++)
#pragma unroll
            for (int t = 0; t < 4; t++) acc[i][j][t] = 0.f;

    int lr = tid >> 2, kc = (tid & 3) * 4;
    const float* Ab = A + (size_t)(bm + lr) * KK + kc;
    const float* Bb = Bsel + (size_t)(bn + lr) * KK + kc;
    uint32_t sA = (uint32_t)((lr * AST + kc) * 4);
    const size_t strA = (size_t)32 * KK;
    const uint32_t strS = 32 * AST * 4;

    const int NT = KK / 16;

#pragma unroll
    for (int t = 0; t < 3; t++) {
        uint32_t as = As_u + t * STAGE_F * 4;
        uint32_t bs = Bs_u + t * STAGE_F * 4;
#pragma unroll
        for (int rr = 0; rr < 4; rr++) {
            cp16(as + sA + rr * strS, Ab + t * 16 + rr * strA);
            cp16(bs + sA + rr * strS, Bb + t * 16 + rr * strA);
        }
        cp_commit();
    }

    for (int i = 0; i < NT; i++) {
        cp_wait2();
        __syncthreads();
        if (i + 3 < NT) {
            int sl = (i + 3) & 3;
            uint32_t as = As_u + sl * STAGE_F * 4;
            uint32_t bs = Bs_u + sl * STAGE_F * 4;
#pragma unroll
            for (int rr = 0; rr < 4; rr++) {
                cp16(as + sA + rr * strS, Ab + (i + 3) * 16 + rr * strA);
                cp16(bs + sA + rr * strS, Bb + (i + 3) * 16 + rr * strA);
            }
        }
        cp_commit();

        uint32_t as = As_u + (i & 3) * STAGE_F * 4;
        uint32_t bs = Bs_u + (i & 3) * STAGE_F * 4;
#pragma unroll
        for (int kk = 0; kk < 16; kk += 8) {
            uint32_t af[4][4];
#pragma unroll
            for (int mi = 0; mi < 4; mi++)
                ldsm_x4(af[mi], as + a_off + (uint32_t)((mi * 16 * AST + kk) * 4));
            uint32_t bf[4][4];
#pragma unroll
            for (int np = 0; np < 4; np++)
                ldsm_x4(bf[np], bs + b_off + (uint32_t)((np * 16 * AST + kk) * 4));
#pragma unroll
            for (int mi = 0; mi < 4; mi++)
#pragma unroll
                for (int ni = 0; ni < 8; ni++)
                    mma_tf32(acc[mi][ni], af[mi], bf[ni >> 1][(ni & 1) * 2], bf[ni >> 1][(ni & 1) * 2 + 1]);
        }
    }

#pragma unroll
    for (int mi = 0; mi < 4; mi++) {
#pragma unroll
        for (int ni = 0; ni < 8; ni++) {
            int rr = bm + wm * 64 + mi * 16 + lg;
            int cc = bn + wn * 64 + ni * 8 + lk * 2;
            *(float2*)(Csel + (size_t)rr * Ncol + cc) = make_float2(acc[mi][ni][0], acc[mi][ni][1]);
            *(float2*)(Csel + (size_t)(rr + 8) * Ncol + cc) = make_float2(acc[mi][ni][2], acc[mi][ni][3]);
        }
    }
}

// ---------------------------------------------------------------------------
// RoPE (in-place).
// ---------------------------------------------------------------------------
__global__ void rope_kernel(float* __restrict__ X, int nheads)
{
    int idx = blockIdx.x * blockDim.x + threadIdx.x;
    int total = MM * nheads * (HD / 2);
    if (idx >= total) return;
    int i = idx & 31;
    int t = idx >> 5;
    int h = t % nheads;
    int ms = t / nheads;
    int s = ms & (SS - 1);

    const float LOG_THETA_OVER_HALF = 9.210340371976184f / 32.0f;
    float inv = expf(-(float)i * LOG_THETA_OVER_HALF);
    float ang = (float)s * inv;
    float sn, cs;
    sincosf(ang, &sn, &cs);

    float* base = X + (size_t)ms * nheads * HD + h * HD;
    float x1 = base[i];
    float x2 = base[i + 32];
    base[i]      = x1 * cs - x2 * sn;
    base[i + 32] = x2 * cs + x1 * sn;
}

// ---------------------------------------------------------------------------
// Tensor-core flash attention, causal, 64x64 tiles.
// All smem tiles stored PRE-ROUNDED to tf32 (raw LDS in inner loops, no cvt).
// ---------------------------------------------------------------------------
#define QST 68
#define VST 72

__global__ __launch_bounds__(128) void attn_kernel()
{
    extern __shared__ float sm[];
    float* Qs = sm;
    float* Ks = sm + 64 * QST;
    float* Ps = sm + 2 * 64 * QST;
    float* Vs = sm + 3 * 64 * QST;

    int qt = blockIdx.x, h = blockIdx.y, b = blockIdx.z;
    int kvh = h >> 2;
    int tid = threadIdx.x, lane = tid & 31, w = tid >> 5;
    int lg = lane >> 2, lk = lane & 3;

    // load Q tile, rounding to tf32 at store
    const float* Qg = g_Q + (size_t)(b * SS + qt * 64) * (NQ * HD) + h * HD;
    for (int i = tid; i < 64 * 16; i += 128) {
        int rr = i >> 4, c4 = (i & 15) * 4;
        float4 v = *(const float4*)(Qg + (size_t)rr * (NQ * HD) + c4);
        v.x = __uint_as_float(f2tf32(v.x));
        v.y = __uint_as_float(f2tf32(v.y));
        v.z = __uint_as_float(f2tf32(v.z));
        v.w = __uint_as_float(f2tf32(v.w));
        *(float4*)&Qs[rr * QST + c4] = v;
    }
    __syncthreads();

    uint32_t qf[8][4];
    int qr0 = w * 16 + lg, qr1 = qr0 + 8;
#pragma unroll
    for (int kk = 0; kk < 8; kk++) {
        qf[kk][0] = __float_as_uint(Qs[qr0 * QST + kk * 8 + lk]);
        qf[kk][1] = __float_as_uint(Qs[qr1 * QST + kk * 8 + lk]);
        qf[kk][2] = __float_as_uint(Qs[qr0 * QST + kk * 8 + 4 + lk]);
        qf[kk][3] = __float_as_uint(Qs[qr1 * QST + kk * 8 + 4 + lk]);
    }

    float o[8][4];
#pragma unroll
    for (int j = 0; j < 8; j++)
#pragma unroll
        for (int t = 0; t < 4; t++) o[j][t] = 0.f;
    float m0 = -INFINITY, m1 = -INFINITY, l0 = 0.f, l1 = 0.f;
    int row0 = qt * 64 + w * 16 + lg, row1 = row0 + 8;

    for (int kt = 0; kt <= qt; kt++) {
        __syncthreads();
        const float* Kg = g_K + (size_t)(b * SS + kt * 64) * (NKV * HD) + kvh * HD;
        const float* Vg = g_V + (size_t)(b * SS + kt * 64) * (NKV * HD) + kvh * HD;
        for (int i = tid; i < 64 * 16; i += 128) {
            int rr = i >> 4, c4 = (i & 15) * 4;
            float4 kv = *(const float4*)(Kg + (size_t)rr * (NKV * HD) + c4);
            kv.x = __uint_as_float(f2tf32(kv.x));
            kv.y = __uint_as_float(f2tf32(kv.y));
            kv.z = __uint_as_float(f2tf32(kv.z));
            kv.w = __uint_as_float(f2tf32(kv.w));
            *(float4*)&Ks[rr * QST + c4] = kv;
            float4 vv = *(const float4*)(Vg + (size_t)rr * (NKV * HD) + c4);
            vv.x = __uint_as_float(f2tf32(vv.x));
            vv.y = __uint_as_float(f2tf32(vv.y));
            vv.z = __uint_as_float(f2tf32(vv.z));
            vv.w = __uint_as_float(f2tf32(vv.w));
            *(float4*)&Vs[rr * VST + c4] = vv;
        }
        __syncthreads();

        float s[8][4];
#pragma unroll
        for (int j = 0; j < 8; j++) {
            s[j][0] = s[j][1] = s[j][2] = s[j][3] = 0.f;
#pragma unroll
            for (int kk = 0; kk < 8; kk++) {
                uint32_t b0 = __float_as_uint(Ks[(j * 8 + lg) * QST + kk * 8 + lk]);
                uint32_t b1 = __float_as_uint(Ks[(j * 8 + lg) * QST + kk * 8 + 4 + lk]);
                mma_tf32(s[j], qf[kk], b0, b1);
            }
        }
        const float scale = 0.125f;
#pragma unroll
        for (int j = 0; j < 8; j++) {
            s[j][0] *= scale; s[j][1] *= scale; s[j][2] *= scale; s[j][3] *= scale;
        }
        if (kt == qt) {
#pragma unroll
            for (int j = 0; j < 8; j++) {
                int c0 = kt * 64 + j * 8 + 2 * lk, c1 = c0 + 1;
                if (c0 > row0) s[j][0] = -INFINITY;
                if (c1 > row0) s[j][1] = -INFINITY;
                if (c0 > row1) s[j][2] = -INFINITY;
                if (c1 > row1) s[j][3] = -INFINITY;
            }
        }

        float mn0 = s[0][0], mn1 = s[0][2];
#pragma unroll
        for (int j = 0; j < 8; j++) {
            mn0 = fmaxf(mn0, fmaxf(s[j][0], s[j][1]));
            mn1 = fmaxf(mn1, fmaxf(s[j][2], s[j][3]));
        }
        mn0 = fmaxf(mn0, __shfl_xor_sync(0xffffffffu, mn0, 1));
        mn0 = fmaxf(mn0, __shfl_xor_sync(0xffffffffu, mn0, 2));
        mn1 = fmaxf(mn1, __shfl_xor_sync(0xffffffffu, mn1, 1));
        mn1 = fmaxf(mn1, __shfl_xor_sync(0xffffffffu, mn1, 2));
        float mnew0 = fmaxf(m0, mn0), mnew1 = fmaxf(m1, mn1);
        float a0 = __expf(m0 - mnew0), a1 = __expf(m1 - mnew1);

        float ll0 = 0.f, ll1 = 0.f;
#pragma unroll
        for (int j = 0; j < 8; j++) {
            float p0 = __expf(s[j][0] - mnew0);
            float p1 = __expf(s[j][1] - mnew0);
            float p2 = __expf(s[j][2] - mnew1);
            float p3 = __expf(s[j][3] - mnew1);
            ll0 += p0 + p1; ll1 += p2 + p3;
            // store pre-rounded tf32 P
            float2 w0 = make_float2(__uint_as_float(f2tf32(p0)), __uint_as_float(f2tf32(p1)));
            float2 w1 = make_float2(__uint_as_float(f2tf32(p2)), __uint_as_float(f2tf32(p3)));
            *(float2*)&Ps[qr0 * QST + j * 8 + 2 * lk] = w0;
            *(float2*)&Ps[qr1 * QST + j * 8 + 2 * lk] = w1;
        }
        ll0 += __shfl_xor_sync(0xffffffffu, ll0, 1);
        ll0 += __shfl_xor_sync(0xffffffffu, ll0, 2);
        ll1 += __shfl_xor_sync(0xffffffffu, ll1, 1);
        ll1 += __shfl_xor_sync(0xffffffffu, ll1, 2);
        l0 = l0 * a0 + ll0; l1 = l1 * a1 + ll1;
        m0 = mnew0; m1 = mnew1;
#pragma unroll
        for (int j = 0; j < 8; j++) {
            o[j][0] *= a0; o[j][1] *= a0; o[j][2] *= a1; o[j][3] *= a1;
        }
        __syncwarp();

        uint32_t pf[8][4];
#pragma unroll
        for (int kk = 0; kk < 8; kk++) {
            pf[kk][0] = __float_as_uint(Ps[qr0 * QST + kk * 8 + lk]);
            pf[kk][1] = __float_as_uint(Ps[qr1 * QST + kk * 8 + lk]);
            pf[kk][2] = __float_as_uint(Ps[qr0 * QST + kk * 8 + 4 + lk]);
            pf[kk][3] = __float_as_uint(Ps[qr1 * QST + kk * 8 + 4 + lk]);
        }
#pragma unroll
        for (int j = 0; j < 8; j++) {
#pragma unroll
            for (int kk = 0; kk < 8; kk++) {
                uint32_t b0 = __float_as_uint(Vs[(kk * 8 + lk) * VST + j * 8 + lg]);
                uint32_t b1 = __float_as_uint(Vs[(kk * 8 + lk + 4) * VST + j * 8 + lg]);
                mma_tf32(o[j], pf[kk], b0, b1);
            }
        }
    }

    float il0 = 1.0f / l0, il1 = 1.0f / l1;
    int gr0 = b * SS + qt * 64 + w * 16 + lg;
#pragma unroll
    for (int j = 0; j < 8; j++) {
        int cc = h * HD + j * 8 + 2 * lk;
        float2 v0 = make_float2(__uint_as_float(f2tf32(o[j][0] * il0)),
                                __uint_as_float(f2tf32(o[j][1] * il0)));
        float2 v1 = make_float2(__uint_as_float(f2tf32(o[j][2] * il1)),
                                __uint_as_float(f2tf32(o[j][3] * il1)));
        *(float2*)(g_attn + (size_t)gr0 * DD + cc) = v0;
        *(float2*)(g_attn + (size_t)(gr0 + 8) * DD + cc) = v1;
    }
}

// ---------------------------------------------------------------------------
extern "C" void kernel_launch(void* const* d_in, const int* in_sizes, int n_in,
                              void* d_out, int out_size)
{
    const float* x  = (const float*)d_in[0];
    const float* Wq = (const float*)d_in[2];
    const float* Wk = (const float*)d_in[3];
    const float* Wv = (const float*)d_in[4];
    const float* Wo = (const float*)d_in[5];
    float* out = (float*)d_out;

    float *Qp, *Kp, *Vp, *Ap, *xT, *WqT, *WkT, *WvT, *WoT;
    cudaGetSymbolAddress((void**)&Qp, g_Q);
    cudaGetSymbolAddress((void**)&Kp, g_K);
    cudaGetSymbolAddress((void**)&Vp, g_V);
    cudaGetSymbolAddress((void**)&Ap, g_attn);
    cudaGetSymbolAddress((void**)&xT, g_xT);
    cudaGetSymbolAddress((void**)&WqT, g_WqT);
    cudaGetSymbolAddress((void**)&WkT, g_WkT);
    cudaGetSymbolAddress((void**)&WvT, g_WvT);
    cudaGetSymbolAddress((void**)&WoT, g_WoT);

    // tf32 pre-rounding
    {
        int n4;
        n4 = MM * DD / 4;            cvt_tf32_kernel<<<(n4 + 255) / 256, 256>>>(x,  xT,  n4);
        n4 = DD * DD / 4;            cvt_tf32_kernel<<<(n4 + 255) / 256, 256>>>(Wq, WqT, n4);
        n4 = (NKV * HD) * DD / 4;    cvt_tf32_kernel<<<(n4 + 255) / 256, 256>>>(Wk, WkT, n4);
        n4 = (NKV * HD) * DD / 4;    cvt_tf32_kernel<<<(n4 + 255) / 256, 256>>>(Wv, WvT, n4);
        n4 = DD * DD / 4;            cvt_tf32_kernel<<<(n4 + 255) / 256, 256>>>(Wo, WoT, n4);
    }

    cudaFuncSetAttribute(gemm_tf32, cudaFuncAttributeMaxDynamicSharedMemorySize, GEMM_SMEM);

    // Fused QKV: bx 0..15 -> Q (N=2048), 16..19 -> K, 20..23 -> V
    gemm_tf32<<<dim3(24, MM / 128), 128, GEMM_SMEM>>>(xT, WqT, WkT, WvT, Qp, Kp, Vp, 16, 4);

    {
        int totq = MM * NQ * (HD / 2);
        rope_kernel<<<(totq + 255) / 256, 256>>>(Qp, NQ);
        int totk = MM * NKV * (HD / 2);
        rope_kernel<<<(totk + 255) / 256, 256>>>(Kp, NKV);
    }

    {
        int smem = (3 * 64 * QST + 64 * VST) * (int)sizeof(float);
        cudaFuncSetAttribute(attn_kernel, cudaFuncAttributeMaxDynamicSharedMemorySize, smem);
        attn_kernel<<<dim3(SS / 64, NQ, BB), 128, smem>>>();
    }

    // Output projection (route 0 only)
    gemm_tf32<<<dim3(16, MM / 128), 128, GEMM_SMEM>>>(Ap, WoT, WoT, WoT, out, out, out, 16, 0);
}

// round 12
// speedup vs baseline: 11.0652x; 1.3783x over previous
#include <cuda_runtime.h>
#include <cuda_fp16.h>
#include <math.h>
#include <stdint.h>

#define BB 2
#define SS 2048
#define DD 2048
#define NQ 32
#define NKV 8
#define HD 64
#define MM (BB*SS)   // 4096
#define KK 2048

// Scratch (no cudaMalloc allowed)
__device__ float  g_Q[(size_t)MM * NQ * HD];       // fp32 (attention reads these)
__device__ float  g_K[(size_t)MM * NKV * HD];
__device__ float  g_V[(size_t)MM * NKV * HD];
__device__ __half g_attnh[(size_t)MM * DD];        // half (feeds Wo GEMM)
__device__ __half g_xh[(size_t)MM * DD];
__device__ __half g_Wqh[(size_t)DD * DD];
__device__ __half g_Wkh[(size_t)(NKV*HD) * DD];
__device__ __half g_Wvh[(size_t)(NKV*HD) * DD];
__device__ __half g_Woh[(size_t)DD * DD];

// ---------------------------------------------------------------------------
// helpers
// ---------------------------------------------------------------------------
__device__ __forceinline__ uint32_t f2tf32(float f) {
    uint32_t o;
    asm("cvt.rna.tf32.f32 %0, %1;" : "=r"(o) : "f"(f));
    return o;
}

__device__ __forceinline__ void mma_f16(float* c, const uint32_t* a, uint32_t b0, uint32_t b1) {
    asm volatile(
        "mma.sync.aligned.m16n8k16.row.col.f32.f16.f16.f32 "
        "{%0,%1,%2,%3}, {%4,%5,%6,%7}, {%8,%9}, {%0,%1,%2,%3};"
        : "+f"(c[0]), "+f"(c[1]), "+f"(c[2]), "+f"(c[3])
        : "r"(a[0]), "r"(a[1]), "r"(a[2]), "r"(a[3]), "r"(b0), "r"(b1));
}

__device__ __forceinline__ void mma_tf32(float* c, const uint32_t* a, uint32_t b0, uint32_t b1) {
    asm volatile(
        "mma.sync.aligned.m16n8k8.row.col.f32.tf32.tf32.f32 "
        "{%0,%1,%2,%3}, {%4,%5,%6,%7}, {%8,%9}, {%0,%1,%2,%3};"
        : "+f"(c[0]), "+f"(c[1]), "+f"(c[2]), "+f"(c[3])
        : "r"(a[0]), "r"(a[1]), "r"(a[2]), "r"(a[3]), "r"(b0), "r"(b1));
}

__device__ __forceinline__ void ldsm_x4(uint32_t* d, uint32_t saddr) {
    asm volatile("ldmatrix.sync.aligned.m8n8.x4.shared.b16 {%0,%1,%2,%3}, [%4];"
        : "=r"(d[0]), "=r"(d[1]), "=r"(d[2]), "=r"(d[3]) : "r"(saddr));
}

__device__ __forceinline__ void cp16(uint32_t dst, const void* src) {
    asm volatile("cp.async.cg.shared.global [%0], [%1], 16;" :: "r"(dst), "l"(src));
}
__device__ __forceinline__ void cp_commit() { asm volatile("cp.async.commit_group;"); }
__device__ __forceinline__ void cp_wait2()  { asm volatile("cp.async.wait_group 2;"); }

// ---------------------------------------------------------------------------
// Elementwise fp32 -> fp16 conversion (RN), vectorized.
// ---------------------------------------------------------------------------
__global__ void cvt_f16_kernel(const float* __restrict__ in, __half* __restrict__ out, int n4)
{
    int i = blockIdx.x * blockDim.x + threadIdx.x;
    if (i >= n4) return;
    float4 v = ((const float4*)in)[i];
    __half2 h0 = __floats2half2_rn(v.x, v.y);
    __half2 h1 = __floats2half2_rn(v.z, v.w);
    uint2 o;
    o.x = *(uint32_t*)&h0;
    o.y = *(uint32_t*)&h1;
    ((uint2*)out)[i] = o;
}

// ---------------------------------------------------------------------------
// FP16-operand GEMM with FP32 output. C = A * B^T.
// A:[M,2048] half row-major, W:[N,2048] half. Block 128x128, BK=32,
// 128 threads (4 warps 2x2 -> 64x64 warp tile). smem stride 40 halves (80B).
// grid.x routing: bx<nb0 -> (W0,C0,N=2048), next nb1 -> (W1,C1,512), rest W2.
// ---------------------------------------------------------------------------
#define ASTH 40
#define STAGE_H (128 * ASTH)     // halves per operand per stage (5120)
#define NSTG 4
#define GEMM_SMEM (NSTG * 2 * STAGE_H * 2)   // 81920 bytes

__global__ __launch_bounds__(128, 2) void gemm_f16(
    const __half* __restrict__ A,
    const __half* __restrict__ W0, const __half* __restrict__ W1, const __half* __restrict__ W2,
    float* __restrict__ C0, float* __restrict__ C1, float* __restrict__ C2,
    int nb0, int nb1)
{
    extern __shared__ __half smemh[];
    __half* As = smemh;
    __half* Bs = smemh + NSTG * STAGE_H;

    int tid = threadIdx.x;
    int lane = tid & 31;
    int warp = tid >> 5;
    int wm = warp >> 1, wn = warp & 1;
    int bx = blockIdx.x;
    int bm = blockIdx.y * 128;
    int lg = lane >> 2, lk = lane & 3;

    const __half* Bsel; float* Csel; int Ncol, bn;
    if (bx < nb0)            { Bsel = W0; Csel = C0; Ncol = 2048; bn = bx * 128; }
    else if (bx < nb0 + nb1) { Bsel = W1; Csel = C1; Ncol = 512;  bn = (bx - nb0) * 128; }
    else                     { Bsel = W2; Csel = C2; Ncol = 512;  bn = (bx - nb0 - nb1) * 128; }

    uint32_t As_u = (uint32_t)__cvta_generic_to_shared(As);
    uint32_t Bs_u = (uint32_t)__cvta_generic_to_shared(Bs);

    // fragment lane offsets (bytes)
    int a_row = lane & 15;
    int a_kh  = (lane >> 4) * 8;
    int b_row = (lane & 7) + (lane >> 4) * 8;
    int b_kh  = ((lane >> 3) & 1) * 8;
    uint32_t a_off = (uint32_t)(((wm * 64 + a_row) * ASTH + a_kh) * 2);
    uint32_t b_off = (uint32_t)(((wn * 64 + b_row) * ASTH + b_kh) * 2);

    float acc[4][8][4];
#pragma unroll
    for (int i = 0; i < 4; i++)
#pragma unroll
        for (int j = 0; j < 8; j++)
#pragma unroll
            for (int t = 0; t < 4; t++) acc[i][j][t] = 0.f;

    // loaders: 512 16B-chunks per operand (128 rows x 4 chunks), 4 per thread
    const __half* Agp[4]; const __half* Bgp[4]; uint32_t Ssm[4];
#pragma unroll
    for (int j = 0; j < 4; j++) {
        int ch = tid + j * 128;
        int row = ch >> 2, c = ch & 3;
        Agp[j] = A + (size_t)(bm + row) * KK + c * 8;
        Bgp[j] = Bsel + (size_t)(bn + row) * KK + c * 8;
        Ssm[j] = (uint32_t)((row * ASTH + c * 8) * 2);
    }

    const int NT = KK / 32;   // 64

#pragma unroll
    for (int t = 0; t < 3; t++) {
        uint32_t as = As_u + t * STAGE_H * 2;
        uint32_t bs = Bs_u + t * STAGE_H * 2;
#pragma unroll
        for (int j = 0; j < 4; j++) {
            cp16(as + Ssm[j], Agp[j] + t * 32);
            cp16(bs + Ssm[j], Bgp[j] + t * 32);
        }
        cp_commit();
    }

    for (int i = 0; i < NT; i++) {
        cp_wait2();
        __syncthreads();
        if (i + 3 < NT) {
            int sl = (i + 3) & 3;
            uint32_t as = As_u + sl * STAGE_H * 2;
            uint32_t bs = Bs_u + sl * STAGE_H * 2;
#pragma unroll
            for (int j = 0; j < 4; j++) {
                cp16(as + Ssm[j], Agp[j] + (i + 3) * 32);
                cp16(bs + Ssm[j], Bgp[j] + (i + 3) * 32);
            }
        }
        cp_commit();

        uint32_t as = As_u + (i & 3) * STAGE_H * 2;
        uint32_t bs = Bs_u + (i & 3) * STAGE_H * 2;
#pragma unroll
        for (int ks = 0; ks < 2; ks++) {
            uint32_t af[4][4];
#pragma unroll
            for (int mi = 0; mi < 4; mi++)
                ldsm_x4(af[mi], as + a_off + (uint32_t)((mi * 16 * ASTH + ks * 16) * 2));
            uint32_t bf[4][4];
#pragma unroll
            for (int np = 0; np < 4; np++)
                ldsm_x4(bf[np], bs + b_off + (uint32_t)((np * 16 * ASTH + ks * 16) * 2));
#pragma unroll
            for (int mi = 0; mi < 4; mi++)
#pragma unroll
                for (int ni = 0; ni < 8; ni++)
                    mma_f16(acc[mi][ni], af[mi], bf[ni >> 1][(ni & 1) * 2], bf[ni >> 1][(ni & 1) * 2 + 1]);
        }
    }

#pragma unroll
    for (int mi = 0; mi < 4; mi++) {
#pragma unroll
        for (int ni = 0; ni < 8; ni++) {
            int rr = bm + wm * 64 + mi * 16 + lg;
            int cc = bn + wn * 64 + ni * 8 + lk * 2;
            *(float2*)(Csel + (size_t)rr * Ncol + cc) = make_float2(acc[mi][ni][0], acc[mi][ni][1]);
            *(float2*)(Csel + (size_t)(rr + 8) * Ncol + cc) = make_float2(acc[mi][ni][2], acc[mi][ni][3]);
        }
    }
}

// ---------------------------------------------------------------------------
// RoPE (in-place, fp32).
// ---------------------------------------------------------------------------
__global__ void rope_kernel(float* __restrict__ X, int nheads)
{
    int idx = blockIdx.x * blockDim.x + threadIdx.x;
    int total = MM * nheads * (HD / 2);
    if (idx >= total) return;
    int i = idx & 31;
    int t = idx >> 5;
    int h = t % nheads;
    int ms = t / nheads;
    int s = ms & (SS - 1);

    const float LOG_THETA_OVER_HALF = 9.210340371976184f / 32.0f;
    float inv = expf(-(float)i * LOG_THETA_OVER_HALF);
    float ang = (float)s * inv;
    float sn, cs;
    sincosf(ang, &sn, &cs);

    float* base = X + (size_t)ms * nheads * HD + h * HD;
    float x1 = base[i];
    float x2 = base[i + 32];
    base[i]      = x1 * cs - x2 * sn;
    base[i + 32] = x2 * cs + x1 * sn;
}

// ---------------------------------------------------------------------------
// Tensor-core flash attention, causal, 64x64 tiles, tf32 mma (R6 known-good).
// All smem tiles stored PRE-ROUNDED to tf32. Output written as HALF to g_attnh.
// ---------------------------------------------------------------------------
#define QST 68
#define VST 72

__global__ __launch_bounds__(128) void attn_kernel()
{
    extern __shared__ float sm[];
    float* Qs = sm;
    float* Ks = sm + 64 * QST;
    float* Ps = sm + 2 * 64 * QST;
    float* Vs = sm + 3 * 64 * QST;

    int qt = blockIdx.x, h = blockIdx.y, b = blockIdx.z;
    int kvh = h >> 2;
    int tid = threadIdx.x, lane = tid & 31, w = tid >> 5;
    int lg = lane >> 2, lk = lane & 3;

    const float* Qg = g_Q + (size_t)(b * SS + qt * 64) * (NQ * HD) + h * HD;
    for (int i = tid; i < 64 * 16; i += 128) {
        int rr = i >> 4, c4 = (i & 15) * 4;
        float4 v = *(const float4*)(Qg + (size_t)rr * (NQ * HD) + c4);
        v.x = __uint_as_float(f2tf32(v.x));
        v.y = __uint_as_float(f2tf32(v.y));
        v.z = __uint_as_float(f2tf32(v.z));
        v.w = __uint_as_float(f2tf32(v.w));
        *(float4*)&Qs[rr * QST + c4] = v;
    }
    __syncthreads();

    uint32_t qf[8][4];
    int qr0 = w * 16 + lg, qr1 = qr0 + 8;
#pragma unroll
    for (int kk = 0; kk < 8; kk++) {
        qf[kk][0] = __float_as_uint(Qs[qr0 * QST + kk * 8 + lk]);
        qf[kk][1] = __float_as_uint(Qs[qr1 * QST + kk * 8 + lk]);
        qf[kk][2] = __float_as_uint(Qs[qr0 * QST + kk * 8 + 4 + lk]);
        qf[kk][3] = __float_as_uint(Qs[qr1 * QST + kk * 8 + 4 + lk]);
    }

    float o[8][4];
#pragma unroll
    for (int j = 0; j < 8; j++)
#pragma unroll
        for (int t = 0; t < 4; t++) o[j][t] = 0.f;
    float m0 = -INFINITY, m1 = -INFINITY, l0 = 0.f, l1 = 0.f;
    int row0 = qt * 64 + qr0, row1 = row0 + 8;

    for (int kt = 0; kt <= qt; kt++) {
        __syncthreads();
        const float* Kg = g_K + (size_t)(b * SS + kt * 64) * (NKV * HD) + kvh * HD;
        const float* Vg = g_V + (size_t)(b * SS + kt * 64) * (NKV * HD) + kvh * HD;
        for (int i = tid; i < 64 * 16; i += 128) {
            int rr = i >> 4, c4 = (i & 15) * 4;
            float4 kv = *(const float4*)(Kg + (size_t)rr * (NKV * HD) + c4);
            kv.x = __uint_as_float(f2tf32(kv.x));
            kv.y = __uint_as_float(f2tf32(kv.y));
            kv.z = __uint_as_float(f2tf32(kv.z));
            kv.w = __uint_as_float(f2tf32(kv.w));
            *(float4*)&Ks[rr * QST + c4] = kv;
            float4 vv = *(const float4*)(Vg + (size_t)rr * (NKV * HD) + c4);
            vv.x = __uint_as_float(f2tf32(vv.x));
            vv.y = __uint_as_float(f2tf32(vv.y));
            vv.z = __uint_as_float(f2tf32(vv.z));
            vv.w = __uint_as_float(f2tf32(vv.w));
            *(float4*)&Vs[rr * VST + c4] = vv;
        }
        __syncthreads();

        float s[8][4];
#pragma unroll
        for (int j = 0; j < 8; j++) { s[j][0] = s[j][1] = s[j][2] = s[j][3] = 0.f; }
#pragma unroll
        for (int j = 0; j < 8; j++) {
#pragma unroll
            for (int kk = 0; kk < 8; kk++) {
                uint32_t b0 = __float_as_uint(Ks[(j * 8 + lg) * QST + kk * 8 + lk]);
                uint32_t b1 = __float_as_uint(Ks[(j * 8 + lg) * QST + kk * 8 + 4 + lk]);
                mma_tf32(s[j], qf[kk], b0, b1);
            }
        }
        const float scale = 0.125f;
#pragma unroll
        for (int j = 0; j < 8; j++) {
            s[j][0] *= scale; s[j][1] *= scale; s[j][2] *= scale; s[j][3] *= scale;
        }
        if (kt == qt) {
#pragma unroll
            for (int j = 0; j < 8; j++) {
                int c0 = kt * 64 + j * 8 + 2 * lk, c1 = c0 + 1;
                if (c0 > row0) s[j][0] = -INFINITY;
                if (c1 > row0) s[j][1] = -INFINITY;
                if (c0 > row1) s[j][2] = -INFINITY;
                if (c1 > row1) s[j][3] = -INFINITY;
            }
        }

        float mn0 = s[0][0], mn1 = s[0][2];
#pragma unroll
        for (int j = 0; j < 8; j++) {
            mn0 = fmaxf(mn0, fmaxf(s[j][0], s[j][1]));
            mn1 = fmaxf(mn1, fmaxf(s[j][2], s[j][3]));
        }
        mn0 = fmaxf(mn0, __shfl_xor_sync(0xffffffffu, mn0, 1));
        mn0 = fmaxf(mn0, __shfl_xor_sync(0xffffffffu, mn0, 2));
        mn1 = fmaxf(mn1, __shfl_xor_sync(0xffffffffu, mn1, 1));
        mn1 = fmaxf(mn1, __shfl_xor_sync(0xffffffffu, mn1, 2));
        float mnew0 = fmaxf(m0, mn0), mnew1 = fmaxf(m1, mn1);
        float a0 = __expf(m0 - mnew0), a1 = __expf(m1 - mnew1);

        float ll0 = 0.f, ll1 = 0.f;
#pragma unroll
        for (int j = 0; j < 8; j++) {
            float p0 = __expf(s[j][0] - mnew0);
            float p1 = __expf(s[j][1] - mnew0);
            float p2 = __expf(s[j][2] - mnew1);
            float p3 = __expf(s[j][3] - mnew1);
            ll0 += p0 + p1; ll1 += p2 + p3;
            float2 w0 = make_float2(__uint_as_float(f2tf32(p0)), __uint_as_float(f2tf32(p1)));
            float2 w1 = make_float2(__uint_as_float(f2tf32(p2)), __uint_as_float(f2tf32(p3)));
            *(float2*)&Ps[qr0 * QST + j * 8 + 2 * lk] = w0;
            *(float2*)&Ps[qr1 * QST + j * 8 + 2 * lk] = w1;
        }
        ll0 += __shfl_xor_sync(0xffffffffu, ll0, 1);
        ll0 += __shfl_xor_sync(0xffffffffu, ll0, 2);
        ll1 += __shfl_xor_sync(0xffffffffu, ll1, 1);
        ll1 += __shfl_xor_sync(0xffffffffu, ll1, 2);
        l0 = l0 * a0 + ll0; l1 = l1 * a1 + ll1;
        m0 = mnew0; m1 = mnew1;
#pragma unroll
        for (int j = 0; j < 8; j++) {
            o[j][0] *= a0; o[j][1] *= a0; o[j][2] *= a1; o[j][3] *= a1;
        }
        __syncwarp();

        uint32_t pf[8][4];
#pragma unroll
        for (int kk = 0; kk < 8; kk++) {
            pf[kk][0] = __float_as_uint(Ps[qr0 * QST + kk * 8 + lk]);
            pf[kk][1] = __float_as_uint(Ps[qr1 * QST + kk * 8 + lk]);
            pf[kk][2] = __float_as_uint(Ps[qr0 * QST + kk * 8 + 4 + lk]);
            pf[kk][3] = __float_as_uint(Ps[qr1 * QST + kk * 8 + 4 + lk]);
        }
#pragma unroll
        for (int j = 0; j < 8; j++) {
#pragma unroll
            for (int kk = 0; kk < 8; kk++) {
                uint32_t b0 = __float_as_uint(Vs[(kk * 8 + lk) * VST + j * 8 + lg]);
                uint32_t b1 = __float_as_uint(Vs[(kk * 8 + lk + 4) * VST + j * 8 + lg]);
                mma_tf32(o[j], pf[kk], b0, b1);
            }
        }
    }

    float il0 = 1.0f / l0, il1 = 1.0f / l1;
    int gr0 = b * SS + qt * 64 + w * 16 + lg;
#pragma unroll
    for (int j = 0; j < 8; j++) {
        int cc = h * HD + j * 8 + 2 * lk;
        *(__half2*)(g_attnh + (size_t)gr0 * DD + cc) = __floats2half2_rn(o[j][0] * il0, o[j][1] * il0);
        *(__half2*)(g_attnh + (size_t)(gr0 + 8) * DD + cc) = __floats2half2_rn(o[j][2] * il1, o[j][3] * il1);
    }
}

// ---------------------------------------------------------------------------
extern "C" void kernel_launch(void* const* d_in, const int* in_sizes, int n_in,
                              void* d_out, int out_size)
{
    const float* x  = (const float*)d_in[0];
    const float* Wq = (const float*)d_in[2];
    const float* Wk = (const float*)d_in[3];
    const float* Wv = (const float*)d_in[4];
    const float* Wo = (const float*)d_in[5];
    float* out = (float*)d_out;

    float *Qp, *Kp, *Vp;
    __half *Ah, *xh, *Wqh, *Wkh, *Wvh, *Woh;
    cudaGetSymbolAddress((void**)&Qp, g_Q);
    cudaGetSymbolAddress((void**)&Kp, g_K);
    cudaGetSymbolAddress((void**)&Vp, g_V);
    cudaGetSymbolAddress((void**)&Ah, g_attnh);
    cudaGetSymbolAddress((void**)&xh, g_xh);
    cudaGetSymbolAddress((void**)&Wqh, g_Wqh);
    cudaGetSymbolAddress((void**)&Wkh, g_Wkh);
    cudaGetSymbolAddress((void**)&Wvh, g_Wvh);
    cudaGetSymbolAddress((void**)&Woh, g_Woh);

    {
        int n4;
        n4 = MM * DD / 4;            cvt_f16_kernel<<<(n4 + 255) / 256, 256>>>(x,  xh,  n4);
        n4 = DD * DD / 4;            cvt_f16_kernel<<<(n4 + 255) / 256, 256>>>(Wq, Wqh, n4);
        n4 = (NKV * HD) * DD / 4;    cvt_f16_kernel<<<(n4 + 255) / 256, 256>>>(Wk, Wkh, n4);
        n4 = (NKV * HD) * DD / 4;    cvt_f16_kernel<<<(n4 + 255) / 256, 256>>>(Wv, Wvh, n4);
        n4 = DD * DD / 4;            cvt_f16_kernel<<<(n4 + 255) / 256, 256>>>(Wo, Woh, n4);
    }

    cudaFuncSetAttribute(gemm_f16, cudaFuncAttributeMaxDynamicSharedMemorySize, GEMM_SMEM);

    // Fused QKV: bx 0..15 -> Q, 16..19 -> K, 20..23 -> V  (fp32 outputs)
    gemm_f16<<<dim3(24, MM / 128), 128, GEMM_SMEM>>>(xh, Wqh, Wkh, Wvh, Qp, Kp, Vp, 16, 4);

    {
        int totq = MM * NQ * (HD / 2);
        rope_kernel<<<(totq + 255) / 256, 256>>>(Qp, NQ);
        int totk = MM * NKV * (HD / 2);
        rope_kernel<<<(totk + 255) / 256, 256>>>(Kp, NKV);
    }

    {
        int smem = (3 * 64 * QST + 64 * VST) * (int)sizeof(float);   // 70656
        cudaFuncSetAttribute(attn_kernel, cudaFuncAttributeMaxDynamicSharedMemorySize, smem);
        attn_kernel<<<dim3(SS / 64, NQ, BB), 128, smem>>>();
    }

    // Output projection: A = attn (half), W = Wo (half), out fp32
    gemm_f16<<<dim3(16, MM / 128), 128, GEMM_SMEM>>>(Ah, Woh, Woh, Woh, out, out, out, 16, 0);
}

// round 14
// speedup vs baseline: 14.4595x; 1.3068x over previous
#include <cuda_runtime.h>
#include <cuda_fp16.h>
#include <math.h>
#include <stdint.h>

#define BB 2
#define SS 2048
#define DD 2048
#define NQ 32
#define NKV 8
#define HD 64
#define MM (BB*SS)   // 4096
#define KK 2048

// Scratch (no cudaMalloc allowed)
__device__ __half g_Qh[(size_t)MM * NQ * HD];
__device__ __half g_Kh[(size_t)MM * NKV * HD];
__device__ __half g_Vt[(size_t)BB * NKV * HD * SS];   // [(b*8+kvh)*64+d][token]
__device__ __half g_attnh[(size_t)MM * DD];
__device__ __half g_xh[(size_t)MM * DD];
__device__ __half g_Wqh[(size_t)DD * DD];
__device__ __half g_Wkh[(size_t)(NKV*HD) * DD];
__device__ __half g_Wvh[(size_t)(NKV*HD) * DD];
__device__ __half g_Woh[(size_t)DD * DD];

__device__ __forceinline__ void mma_f16(float* c, const uint32_t* a, uint32_t b0, uint32_t b1) {
    asm volatile(
        "mma.sync.aligned.m16n8k16.row.col.f32.f16.f16.f32 "
        "{%0,%1,%2,%3}, {%4,%5,%6,%7}, {%8,%9}, {%0,%1,%2,%3};"
        : "+f"(c[0]), "+f"(c[1]), "+f"(c[2]), "+f"(c[3])
        : "r"(a[0]), "r"(a[1]), "r"(a[2]), "r"(a[3]), "r"(b0), "r"(b1));
}

__device__ __forceinline__ void ldsm_x4(uint32_t* d, uint32_t saddr) {
    asm volatile("ldmatrix.sync.aligned.m8n8.x4.shared.b16 {%0,%1,%2,%3}, [%4];"
        : "=r"(d[0]), "=r"(d[1]), "=r"(d[2]), "=r"(d[3]) : "r"(saddr));
}

__device__ __forceinline__ void cp16(uint32_t dst, const void* src) {
    asm volatile("cp.async.cg.shared.global [%0], [%1], 16;" :: "r"(dst), "l"(src));
}
__device__ __forceinline__ void cp_commit() { asm volatile("cp.async.commit_group;"); }
__device__ __forceinline__ void cp_wait2()  { asm volatile("cp.async.wait_group 2;"); }

// ---------------------------------------------------------------------------
// Elementwise fp32 -> fp16 conversion (RN), vectorized.
// ---------------------------------------------------------------------------
__global__ void cvt_f16_kernel(const float* __restrict__ in, __half* __restrict__ out, int n4)
{
    int i = blockIdx.x * blockDim.x + threadIdx.x;
    if (i >= n4) return;
    float4 v = ((const float4*)in)[i];
    __half2 h0 = __floats2half2_rn(v.x, v.y);
    __half2 h1 = __floats2half2_rn(v.z, v.w);
    uint2 o;
    o.x = *(uint32_t*)&h0;
    o.y = *(uint32_t*)&h1;
    ((uint2*)out)[i] = o;
}

// ---------------------------------------------------------------------------
// FP16 GEMM (verified core). C = A * B^T. Block 128x128, BK=32, 128 threads.
// tv=1: the W2 route scatter-stores its output TRANSPOSED into g_Vt.
// ---------------------------------------------------------------------------
#define ASTH 40
#define STAGE_H (128 * ASTH)
#define NSTG 4
#define GEMM_SMEM (NSTG * 2 * STAGE_H * 2)   // 81920 bytes

template<typename OutT>
__global__ __launch_bounds__(128, 2) void gemm_f16(
    const __half* __restrict__ A,
    const __half* __restrict__ W0, const __half* __restrict__ W1, const __half* __restrict__ W2,
    OutT* __restrict__ C0, OutT* __restrict__ C1, OutT* __restrict__ C2,
    int nb0, int nb1, int tv)
{
    extern __shared__ __half smemh[];
    __half* As = smemh;
    __half* Bs = smemh + NSTG * STAGE_H;

    int tid = threadIdx.x;
    int lane = tid & 31;
    int warp = tid >> 5;
    int wm = warp >> 1, wn = warp & 1;
    int bx = blockIdx.x;
    int bm = blockIdx.y * 128;
    int lg = lane >> 2, lk = lane & 3;

    const __half* Bsel; OutT* Csel; int Ncol, bn;
    int vroute = 0;
    if (bx < nb0)            { Bsel = W0; Csel = C0; Ncol = 2048; bn = bx * 128; }
    else if (bx < nb0 + nb1) { Bsel = W1; Csel = C1; Ncol = 512;  bn = (bx - nb0) * 128; }
    else                     { Bsel = W2; Csel = C2; Ncol = 512;  bn = (bx - nb0 - nb1) * 128; vroute = tv; }

    uint32_t As_u = (uint32_t)__cvta_generic_to_shared(As);
    uint32_t Bs_u = (uint32_t)__cvta_generic_to_shared(Bs);

    int a_row = lane & 15;
    int a_kh  = (lane >> 4) * 8;
    int b_row = (lane & 7) + (lane >> 4) * 8;
    int b_kh  = ((lane >> 3) & 1) * 8;
    uint32_t a_off = (uint32_t)(((wm * 64 + a_row) * ASTH + a_kh) * 2);
    uint32_t b_off = (uint32_t)(((wn * 64 + b_row) * ASTH + b_kh) * 2);

    float acc[4][8][4];
#pragma unroll
    for (int i = 0; i < 4; i++)
#pragma unroll
        for (int j = 0; j < 8; j++)
#pragma unroll
            for (int t = 0; t < 4; t++) acc[i][j][t] = 0.f;

    const __half* Agp[4]; const __half* Bgp[4]; uint32_t Ssm[4];
#pragma unroll
    for (int j = 0; j < 4; j++) {
        int ch = tid + j * 128;
        int row = ch >> 2, c = ch & 3;
        Agp[j] = A + (size_t)(bm + row) * KK + c * 8;
        Bgp[j] = Bsel + (size_t)(bn + row) * KK + c * 8;
        Ssm[j] = (uint32_t)((row * ASTH + c * 8) * 2);
    }

    const int NT = KK / 32;

#pragma unroll
    for (int t = 0; t < 3; t++) {
        uint32_t as = As_u + t * STAGE_H * 2;
        uint32_t bs = Bs_u + t * STAGE_H * 2;
#pragma unroll
        for (int j = 0; j < 4; j++) {
            cp16(as + Ssm[j], Agp[j] + t * 32);
            cp16(bs + Ssm[j], Bgp[j] + t * 32);
        }
        cp_commit();
    }

    for (int i = 0; i < NT; i++) {
        cp_wait2();
        __syncthreads();
        if (i + 3 < NT) {
            int sl = (i + 3) & 3;
            uint32_t as = As_u + sl * STAGE_H * 2;
            uint32_t bs = Bs_u + sl * STAGE_H * 2;
#pragma unroll
            for (int j = 0; j < 4; j++) {
                cp16(as + Ssm[j], Agp[j] + (i + 3) * 32);
                cp16(bs + Ssm[j], Bgp[j] + (i + 3) * 32);
            }
        }
        cp_commit();

        uint32_t as = As_u + (i & 3) * STAGE_H * 2;
        uint32_t bs = Bs_u + (i & 3) * STAGE_H * 2;
#pragma unroll
        for (int ks = 0; ks < 2; ks++) {
            uint32_t af[4][4];
#pragma unroll
            for (int mi = 0; mi < 4; mi++)
                ldsm_x4(af[mi], as + a_off + (uint32_t)((mi * 16 * ASTH + ks * 16) * 2));
            uint32_t bf[4][4];
#pragma unroll
            for (int np = 0; np < 4; np++)
                ldsm_x4(bf[np], bs + b_off + (uint32_t)((np * 16 * ASTH + ks * 16) * 2));
#pragma unroll
            for (int mi = 0; mi < 4; mi++)
#pragma unroll
                for (int ni = 0; ni < 8; ni++)
                    mma_f16(acc[mi][ni], af[mi], bf[ni >> 1][(ni & 1) * 2], bf[ni >> 1][(ni & 1) * 2 + 1]);
        }
    }

    if (vroute) {
        // transposed scatter into g_Vt[(b*512 + col)*SS + s]
#pragma unroll
        for (int mi = 0; mi < 4; mi++) {
#pragma unroll
            for (int ni = 0; ni < 8; ni++) {
                int token0 = bm + wm * 64 + mi * 16 + lg;
                int col = bn + wn * 64 + ni * 8 + lk * 2;
#pragma unroll
                for (int half_m = 0; half_m < 2; half_m++) {
                    int token = token0 + half_m * 8;
                    int b = token >> 11, s2 = token & (SS - 1);
                    g_Vt[((size_t)(b * (NKV * HD) + col)) * SS + s2]     = __float2half_rn(acc[mi][ni][half_m * 2 + 0]);
                    g_Vt[((size_t)(b * (NKV * HD) + col + 1)) * SS + s2] = __float2half_rn(acc[mi][ni][half_m * 2 + 1]);
                }
            }
        }
    } else {
#pragma unroll
        for (int mi = 0; mi < 4; mi++) {
#pragma unroll
            for (int ni = 0; ni < 8; ni++) {
                int rr = bm + wm * 64 + mi * 16 + lg;
                int cc = bn + wn * 64 + ni * 8 + lk * 2;
                if (sizeof(OutT) == 4) {
                    float* Cf = (float*)Csel;
                    *(float2*)(Cf + (size_t)rr * Ncol + cc) = make_float2(acc[mi][ni][0], acc[mi][ni][1]);
                    *(float2*)(Cf + (size_t)(rr + 8) * Ncol + cc) = make_float2(acc[mi][ni][2], acc[mi][ni][3]);
                } else {
                    __half* Ch = (__half*)Csel;
                    *(__half2*)(Ch + (size_t)rr * Ncol + cc) = __floats2half2_rn(acc[mi][ni][0], acc[mi][ni][1]);
                    *(__half2*)(Ch + (size_t)(rr + 8) * Ncol + cc) = __floats2half2_rn(acc[mi][ni][2], acc[mi][ni][3]);
                }
            }
        }
    }
}

// ---------------------------------------------------------------------------
// RoPE (in-place on half). Pair (i, i+32) within each head.
// ---------------------------------------------------------------------------
__global__ void rope_kernel(__half* __restrict__ X, int nheads)
{
    int idx = blockIdx.x * blockDim.x + threadIdx.x;
    int total = MM * nheads * (HD / 2);
    if (idx >= total) return;
    int i = idx & 31;
    int t = idx >> 5;
    int h = t % nheads;
    int ms = t / nheads;
    int s = ms & (SS - 1);

    const float LOG_THETA_OVER_HALF = 9.210340371976184f / 32.0f;
    float inv = expf(-(float)i * LOG_THETA_OVER_HALF);
    float ang = (float)s * inv;
    float sn, cs;
    sincosf(ang, &sn, &cs);

    __half* base = X + (size_t)ms * nheads * HD + h * HD;
    float x1 = __half2float(base[i]);
    float x2 = __half2float(base[i + 32]);
    base[i]      = __float2half_rn(x1 * cs - x2 * sn);
    base[i + 32] = __float2half_rn(x2 * cs + x1 * sn);
}

// ---------------------------------------------------------------------------
// FP16 flash attention, causal, 64x64 tiles, fp32 softmax state.
// Verified fragment maps only (A-map, B-map; no trans). V from g_Vt [d][token].
// Q pre-scaled by 0.125 (exact). All tile loads are 16-byte uint4 (8 halves).
// ---------------------------------------------------------------------------
#define FST 72
#define ATT_SMEM (4 * 64 * FST * 2)   // 36864 bytes

__global__ __launch_bounds__(128) void attn_kernel()
{
    extern __shared__ __half smh[];
    __half* Qs = smh;
    __half* Ks = smh + 64 * FST;
    __half* Ps = smh + 2 * 64 * FST;
    __half* Vs = smh + 3 * 64 * FST;   // [d][token]

    int qt = blockIdx.x, h = blockIdx.y, b = blockIdx.z;
    int kvh = h >> 2;
    int tid = threadIdx.x, lane = tid & 31, w = tid >> 5;
    int lg = lane >> 2, lk = lane & 3;

    uint32_t Ks_u = (uint32_t)__cvta_generic_to_shared(Ks);
    uint32_t Ps_u = (uint32_t)__cvta_generic_to_shared(Ps);
    uint32_t Vs_u = (uint32_t)__cvta_generic_to_shared(Vs);
    uint32_t Qs_u = (uint32_t)__cvta_generic_to_shared(Qs);

    // load Q tile (64 rows x 64 halves), scale by 0.125 — uint4 = 8 halves
    const __half* Qg = g_Qh + (size_t)(b * SS + qt * 64) * (NQ * HD) + h * HD;
    const __half2 sc = __float2half2_rn(0.125f);
    for (int i = tid; i < 64 * 8; i += 128) {
        int rr = i >> 3, c8 = (i & 7) * 8;
        uint4 raw = *(const uint4*)(Qg + (size_t)rr * (NQ * HD) + c8);
        __half2 p0 = __hmul2(*(__half2*)&raw.x, sc);
        __half2 p1 = __hmul2(*(__half2*)&raw.y, sc);
        __half2 p2 = __hmul2(*(__half2*)&raw.z, sc);
        __half2 p3 = __hmul2(*(__half2*)&raw.w, sc);
        uint4 outv;
        outv.x = *(uint32_t*)&p0; outv.y = *(uint32_t*)&p1;
        outv.z = *(uint32_t*)&p2; outv.w = *(uint32_t*)&p3;
        *(uint4*)&Qs[rr * FST + c8] = outv;
    }
    __syncthreads();

    // Q fragments (verified A-map), 4 k-steps of 16
    int arow = lane & 15, akh = (lane >> 4) * 8;
    uint32_t qa_off = (uint32_t)(((w * 16 + arow) * FST + akh) * 2);
    uint32_t qf[4][4];
#pragma unroll
    for (int ks = 0; ks < 4; ks++)
        ldsm_x4(qf[ks], Qs_u + qa_off + (uint32_t)(ks * 16 * 2));

    float o[8][4];
#pragma unroll
    for (int j = 0; j < 8; j++)
#pragma unroll
        for (int t = 0; t < 4; t++) o[j][t] = 0.f;
    float m0 = -INFINITY, m1 = -INFINITY, l0 = 0.f, l1 = 0.f;
    int qr0 = w * 16 + lg, qr1 = qr0 + 8;
    int row0 = qt * 64 + qr0, row1 = row0 + 8;

    // verified B-map lane offset (used for K and V^T tiles)
    int brow = (lane & 7) + (lane >> 4) * 8;
    int bkh  = ((lane >> 3) & 1) * 8;
    uint32_t kb_off = (uint32_t)((brow * FST + bkh) * 2);

    const __half* Vtg = g_Vt + (size_t)(b * (NKV * HD) + kvh * HD) * SS;

    for (int kt = 0; kt <= qt; kt++) {
        __syncthreads();
        const __half* Kg = g_Kh + (size_t)(b * SS + kt * 64) * (NKV * HD) + kvh * HD;
        for (int i = tid; i < 64 * 8; i += 128) {
            int rr = i >> 3, c8 = (i & 7) * 8;
            *(uint4*)&Ks[rr * FST + c8] = *(const uint4*)(Kg + (size_t)rr * (NKV * HD) + c8);
            *(uint4*)&Vs[rr * FST + c8] = *(const uint4*)(Vtg + (size_t)rr * SS + kt * 64 + c8);
        }
        __syncthreads();

        // S = (Q*0.125) K^T
        float s[8][4];
#pragma unroll
        for (int j = 0; j < 8; j++) { s[j][0] = s[j][1] = s[j][2] = s[j][3] = 0.f; }
#pragma unroll
        for (int ks = 0; ks < 4; ks++) {
            uint32_t bf[4][4];
#pragma unroll
            for (int np = 0; np < 4; np++)
                ldsm_x4(bf[np], Ks_u + kb_off + (uint32_t)((np * 16 * FST + ks * 16) * 2));
#pragma unroll
            for (int j = 0; j < 8; j++)
                mma_f16(s[j], qf[ks], bf[j >> 1][(j & 1) * 2], bf[j >> 1][(j & 1) * 2 + 1]);
        }

        if (kt == qt) {
#pragma unroll
            for (int j = 0; j < 8; j++) {
                int c0 = kt * 64 + j * 8 + 2 * lk, c1 = c0 + 1;
                if (c0 > row0) s[j][0] = -INFINITY;
                if (c1 > row0) s[j][1] = -INFINITY;
                if (c0 > row1) s[j][2] = -INFINITY;
                if (c1 > row1) s[j][3] = -INFINITY;
            }
        }

        float mn0 = s[0][0], mn1 = s[0][2];
#pragma unroll
        for (int j = 0; j < 8; j++) {
            mn0 = fmaxf(mn0, fmaxf(s[j][0], s[j][1]));
            mn1 = fmaxf(mn1, fmaxf(s[j][2], s[j][3]));
        }
        mn0 = fmaxf(mn0, __shfl_xor_sync(0xffffffffu, mn0, 1));
        mn0 = fmaxf(mn0, __shfl_xor_sync(0xffffffffu, mn0, 2));
        mn1 = fmaxf(mn1, __shfl_xor_sync(0xffffffffu, mn1, 1));
        mn1 = fmaxf(mn1, __shfl_xor_sync(0xffffffffu, mn1, 2));
        float mnew0 = fmaxf(m0, mn0), mnew1 = fmaxf(m1, mn1);
        float a0 = __expf(m0 - mnew0), a1 = __expf(m1 - mnew1);

        float ll0 = 0.f, ll1 = 0.f;
#pragma unroll
        for (int j = 0; j < 8; j++) {
            float p0 = __expf(s[j][0] - mnew0);
            float p1 = __expf(s[j][1] - mnew0);
            float p2 = __expf(s[j][2] - mnew1);
            float p3 = __expf(s[j][3] - mnew1);
            ll0 += p0 + p1; ll1 += p2 + p3;
            *(__half2*)&Ps[qr0 * FST + j * 8 + 2 * lk] = __floats2half2_rn(p0, p1);
            *(__half2*)&Ps[qr1 * FST + j * 8 + 2 * lk] = __floats2half2_rn(p2, p3);
        }
        ll0 += __shfl_xor_sync(0xffffffffu, ll0, 1);
        ll0 += __shfl_xor_sync(0xffffffffu, ll0, 2);
        ll1 += __shfl_xor_sync(0xffffffffu, ll1, 1);
        ll1 += __shfl_xor_sync(0xffffffffu, ll1, 2);
        l0 = l0 * a0 + ll0; l1 = l1 * a1 + ll1;
        m0 = mnew0; m1 = mnew1;
#pragma unroll
        for (int j = 0; j < 8; j++) {
            o[j][0] *= a0; o[j][1] *= a0; o[j][2] *= a1; o[j][3] *= a1;
        }
        __syncwarp();

        // P fragments (verified A-map)
        uint32_t pf[4][4];
#pragma unroll
        for (int ks = 0; ks < 4; ks++)
            ldsm_x4(pf[ks], Ps_u + qa_off + (uint32_t)(ks * 16 * 2));

        // O += P V : B operand = Vs[d][token] via verified B-map
#pragma unroll
        for (int ks = 0; ks < 4; ks++) {
            uint32_t vf[4][4];
#pragma unroll
            for (int np = 0; np < 4; np++)
                ldsm_x4(vf[np], Vs_u + kb_off + (uint32_t)((np * 16 * FST + ks * 16) * 2));
#pragma unroll
            for (int j = 0; j < 8; j++)
                mma_f16(o[j], pf[ks], vf[j >> 1][(j & 1) * 2], vf[j >> 1][(j & 1) * 2 + 1]);
        }
    }

    float il0 = 1.0f / l0, il1 = 1.0f / l1;
    int gr0 = b * SS + qt * 64 + qr0;
#pragma unroll
    for (int j = 0; j < 8; j++) {
        int cc = h * HD + j * 8 + 2 * lk;
        *(__half2*)(g_attnh + (size_t)gr0 * DD + cc) = __floats2half2_rn(o[j][0] * il0, o[j][1] * il0);
        *(__half2*)(g_attnh + (size_t)(gr0 + 8) * DD + cc) = __floats2half2_rn(o[j][2] * il1, o[j][3] * il1);
    }
}

// ---------------------------------------------------------------------------
extern "C" void kernel_launch(void* const* d_in, const int* in_sizes, int n_in,
                              void* d_out, int out_size)
{
    const float* x  = (const float*)d_in[0];
    const float* Wq = (const float*)d_in[2];
    const float* Wk = (const float*)d_in[3];
    const float* Wv = (const float*)d_in[4];
    const float* Wo = (const float*)d_in[5];
    float* out = (float*)d_out;

    __half *Qh, *Kh, *Ah, *xh, *Wqh, *Wkh, *Wvh, *Woh, *Vth;
    cudaGetSymbolAddress((void**)&Qh, g_Qh);
    cudaGetSymbolAddress((void**)&Kh, g_Kh);
    cudaGetSymbolAddress((void**)&Vth, g_Vt);
    cudaGetSymbolAddress((void**)&Ah, g_attnh);
    cudaGetSymbolAddress((void**)&xh, g_xh);
    cudaGetSymbolAddress((void**)&Wqh, g_Wqh);
    cudaGetSymbolAddress((void**)&Wkh, g_Wkh);
    cudaGetSymbolAddress((void**)&Wvh, g_Wvh);
    cudaGetSymbolAddress((void**)&Woh, g_Woh);

    {
        int n4;
        n4 = MM * DD / 4;            cvt_f16_kernel<<<(n4 + 255) / 256, 256>>>(x,  xh,  n4);
        n4 = DD * DD / 4;            cvt_f16_kernel<<<(n4 + 255) / 256, 256>>>(Wq, Wqh, n4);
        n4 = (NKV * HD) * DD / 4;    cvt_f16_kernel<<<(n4 + 255) / 256, 256>>>(Wk, Wkh, n4);
        n4 = (NKV * HD) * DD / 4;    cvt_f16_kernel<<<(n4 + 255) / 256, 256>>>(Wv, Wvh, n4);
        n4 = DD * DD / 4;            cvt_f16_kernel<<<(n4 + 255) / 256, 256>>>(Wo, Woh, n4);
    }

    cudaFuncSetAttribute(gemm_f16<__half>, cudaFuncAttributeMaxDynamicSharedMemorySize, GEMM_SMEM);
    cudaFuncSetAttribute(gemm_f16<float>, cudaFuncAttributeMaxDynamicSharedMemorySize, GEMM_SMEM);

    // Fused QKV: bx 0..15 -> Q, 16..19 -> K, 20..23 -> V (transposed into g_Vt)
    gemm_f16<__half><<<dim3(24, MM / 128), 128, GEMM_SMEM>>>(xh, Wqh, Wkh, Wvh,
                                                             Qh, Kh, Kh, 16, 4, 1);

    {
        int totq = MM * NQ * (HD / 2);
        rope_kernel<<<(totq + 255) / 256, 256>>>(Qh, NQ);
        int totk = MM * NKV * (HD / 2);
        rope_kernel<<<(totk + 255) / 256, 256>>>(Kh, NKV);
    }

    {
        cudaFuncSetAttribute(attn_kernel, cudaFuncAttributeMaxDynamicSharedMemorySize, ATT_SMEM);
        attn_kernel<<<dim3(SS / 64, NQ, BB), 128, ATT_SMEM>>>();
    }

    // Output projection -> fp32 out
    gemm_f16<float><<<dim3(16, MM / 128), 128, GEMM_SMEM>>>(Ah, Woh, Woh, Woh,
                                                            out, out, out, 16, 0, 0);
}

// round 15
// speedup vs baseline: 15.3753x; 1.0633x over previous
#include <cuda_runtime.h>
#include <cuda_fp16.h>
#include <math.h>
#include <stdint.h>

#define BB 2
#define SS 2048
#define DD 2048
#define NQ 32
#define NKV 8
#define HD 64
#define MM (BB*SS)   // 4096
#define KK 2048

// Scratch (no cudaMalloc allowed)
__device__ __half g_Qh[(size_t)MM * NQ * HD];
__device__ __half g_Kh[(size_t)MM * NKV * HD];
__device__ __half g_Vt[(size_t)BB * NKV * HD * SS];   // [(b*8+kvh)*64+d][token]
__device__ __half g_attnh[(size_t)MM * DD];
__device__ __half g_xh[(size_t)MM * DD];
__device__ __half g_Wqh[(size_t)DD * DD];
__device__ __half g_Wkh[(size_t)(NKV*HD) * DD];
__device__ __half g_Wvh[(size_t)(NKV*HD) * DD];
__device__ __half g_Woh[(size_t)DD * DD];

__device__ __forceinline__ void mma_f16(float* c, const uint32_t* a, uint32_t b0, uint32_t b1) {
    asm volatile(
        "mma.sync.aligned.m16n8k16.row.col.f32.f16.f16.f32 "
        "{%0,%1,%2,%3}, {%4,%5,%6,%7}, {%8,%9}, {%0,%1,%2,%3};"
        : "+f"(c[0]), "+f"(c[1]), "+f"(c[2]), "+f"(c[3])
        : "r"(a[0]), "r"(a[1]), "r"(a[2]), "r"(a[3]), "r"(b0), "r"(b1));
}

__device__ __forceinline__ void ldsm_x4(uint32_t* d, uint32_t saddr) {
    asm volatile("ldmatrix.sync.aligned.m8n8.x4.shared.b16 {%0,%1,%2,%3}, [%4];"
        : "=r"(d[0]), "=r"(d[1]), "=r"(d[2]), "=r"(d[3]) : "r"(saddr));
}

__device__ __forceinline__ void cp16(uint32_t dst, const void* src) {
    asm volatile("cp.async.cg.shared.global [%0], [%1], 16;" :: "r"(dst), "l"(src));
}
__device__ __forceinline__ void cp_commit() { asm volatile("cp.async.commit_group;"); }
__device__ __forceinline__ void cp_wait2()  { asm volatile("cp.async.wait_group 2;"); }
__device__ __forceinline__ void cp_wait1()  { asm volatile("cp.async.wait_group 1;"); }
__device__ __forceinline__ void cp_wait0()  { asm volatile("cp.async.wait_group 0;"); }

// ---------------------------------------------------------------------------
// Elementwise fp32 -> fp16 conversion (RN), vectorized.
// ---------------------------------------------------------------------------
__global__ void cvt_f16_kernel(const float* __restrict__ in, __half* __restrict__ out, int n4)
{
    int i = blockIdx.x * blockDim.x + threadIdx.x;
    if (i >= n4) return;
    float4 v = ((const float4*)in)[i];
    __half2 h0 = __floats2half2_rn(v.x, v.y);
    __half2 h1 = __floats2half2_rn(v.z, v.w);
    uint2 o;
    o.x = *(uint32_t*)&h0;
    o.y = *(uint32_t*)&h1;
    ((uint2*)out)[i] = o;
}

// ---------------------------------------------------------------------------
// FP16 GEMM (verified core, UNCHANGED). C = A * B^T. 128x128, BK=32, 128 thr.
// tv=1: W2 route scatter-stores output TRANSPOSED into g_Vt.
// ---------------------------------------------------------------------------
#define ASTH 40
#define STAGE_H (128 * ASTH)
#define NSTG 4
#define GEMM_SMEM (NSTG * 2 * STAGE_H * 2)   // 81920 bytes

template<typename OutT>
__global__ __launch_bounds__(128, 2) void gemm_f16(
    const __half* __restrict__ A,
    const __half* __restrict__ W0, const __half* __restrict__ W1, const __half* __restrict__ W2,
    OutT* __restrict__ C0, OutT* __restrict__ C1, OutT* __restrict__ C2,
    int nb0, int nb1, int tv)
{
    extern __shared__ __half smemh[];
    __half* As = smemh;
    __half* Bs = smemh + NSTG * STAGE_H;

    int tid = threadIdx.x;
    int lane = tid & 31;
    int warp = tid >> 5;
    int wm = warp >> 1, wn = warp & 1;
    int bx = blockIdx.x;
    int bm = blockIdx.y * 128;
    int lg = lane >> 2, lk = lane & 3;

    const __half* Bsel; OutT* Csel; int Ncol, bn;
    int vroute = 0;
    if (bx < nb0)            { Bsel = W0; Csel = C0; Ncol = 2048; bn = bx * 128; }
    else if (bx < nb0 + nb1) { Bsel = W1; Csel = C1; Ncol = 512;  bn = (bx - nb0) * 128; }
    else                     { Bsel = W2; Csel = C2; Ncol = 512;  bn = (bx - nb0 - nb1) * 128; vroute = tv; }

    uint32_t As_u = (uint32_t)__cvta_generic_to_shared(As);
    uint32_t Bs_u = (uint32_t)__cvta_generic_to_shared(Bs);

    int a_row = lane & 15;
    int a_kh  = (lane >> 4) * 8;
    int b_row = (lane & 7) + (lane >> 4) * 8;
    int b_kh  = ((lane >> 3) & 1) * 8;
    uint32_t a_off = (uint32_t)(((wm * 64 + a_row) * ASTH + a_kh) * 2);
    uint32_t b_off = (uint32_t)(((wn * 64 + b_row) * ASTH + b_kh) * 2);

    float acc[4][8][4];
#pragma unroll
    for (int i = 0; i < 4; i++)
#pragma unroll
        for (int j = 0; j < 8; j++)
#pragma unroll
            for (int t = 0; t < 4; t++) acc[i][j][t] = 0.f;

    const __half* Agp[4]; const __half* Bgp[4]; uint32_t Ssm[4];
#pragma unroll
    for (int j = 0; j < 4; j++) {
        int ch = tid + j * 128;
        int row = ch >> 2, c = ch & 3;
        Agp[j] = A + (size_t)(bm + row) * KK + c * 8;
        Bgp[j] = Bsel + (size_t)(bn + row) * KK + c * 8;
        Ssm[j] = (uint32_t)((row * ASTH + c * 8) * 2);
    }

    const int NT = KK / 32;

#pragma unroll
    for (int t = 0; t < 3; t++) {
        uint32_t as = As_u + t * STAGE_H * 2;
        uint32_t bs = Bs_u + t * STAGE_H * 2;
#pragma unroll
        for (int j = 0; j < 4; j++) {
            cp16(as + Ssm[j], Agp[j] + t * 32);
            cp16(bs + Ssm[j], Bgp[j] + t * 32);
        }
        cp_commit();
    }

    for (int i = 0; i < NT; i++) {
        cp_wait2();
        __syncthreads();
        if (i + 3 < NT) {
            int sl = (i + 3) & 3;
            uint32_t as = As_u + sl * STAGE_H * 2;
            uint32_t bs = Bs_u + sl * STAGE_H * 2;
#pragma unroll
            for (int j = 0; j < 4; j++) {
                cp16(as + Ssm[j], Agp[j] + (i + 3) * 32);
                cp16(bs + Ssm[j], Bgp[j] + (i + 3) * 32);
            }
        }
        cp_commit();

        uint32_t as = As_u + (i & 3) * STAGE_H * 2;
        uint32_t bs = Bs_u + (i & 3) * STAGE_H * 2;
#pragma unroll
        for (int ks = 0; ks < 2; ks++) {
            uint32_t af[4][4];
#pragma unroll
            for (int mi = 0; mi < 4; mi++)
                ldsm_x4(af[mi], as + a_off + (uint32_t)((mi * 16 * ASTH + ks * 16) * 2));
            uint32_t bf[4][4];
#pragma unroll
            for (int np = 0; np < 4; np++)
                ldsm_x4(bf[np], bs + b_off + (uint32_t)((np * 16 * ASTH + ks * 16) * 2));
#pragma unroll
            for (int mi = 0; mi < 4; mi++)
#pragma unroll
                for (int ni = 0; ni < 8; ni++)
                    mma_f16(acc[mi][ni], af[mi], bf[ni >> 1][(ni & 1) * 2], bf[ni >> 1][(ni & 1) * 2 + 1]);
        }
    }

    if (vroute) {
#pragma unroll
        for (int mi = 0; mi < 4; mi++) {
#pragma unroll
            for (int ni = 0; ni < 8; ni++) {
                int token0 = bm + wm * 64 + mi * 16 + lg;
                int col = bn + wn * 64 + ni * 8 + lk * 2;
#pragma unroll
                for (int half_m = 0; half_m < 2; half_m++) {
                    int token = token0 + half_m * 8;
                    int b = token >> 11, s2 = token & (SS - 1);
                    g_Vt[((size_t)(b * (NKV * HD) + col)) * SS + s2]     = __float2half_rn(acc[mi][ni][half_m * 2 + 0]);
                    g_Vt[((size_t)(b * (NKV * HD) + col + 1)) * SS + s2] = __float2half_rn(acc[mi][ni][half_m * 2 + 1]);
                }
            }
        }
    } else {
#pragma unroll
        for (int mi = 0; mi < 4; mi++) {
#pragma unroll
            for (int ni = 0; ni < 8; ni++) {
                int rr = bm + wm * 64 + mi * 16 + lg;
                int cc = bn + wn * 64 + ni * 8 + lk * 2;
                if (sizeof(OutT) == 4) {
                    float* Cf = (float*)Csel;
                    *(float2*)(Cf + (size_t)rr * Ncol + cc) = make_float2(acc[mi][ni][0], acc[mi][ni][1]);
                    *(float2*)(Cf + (size_t)(rr + 8) * Ncol + cc) = make_float2(acc[mi][ni][2], acc[mi][ni][3]);
                } else {
                    __half* Ch = (__half*)Csel;
                    *(__half2*)(Ch + (size_t)rr * Ncol + cc) = __floats2half2_rn(acc[mi][ni][0], acc[mi][ni][1]);
                    *(__half2*)(Ch + (size_t)(rr + 8) * Ncol + cc) = __floats2half2_rn(acc[mi][ni][2], acc[mi][ni][3]);
                }
            }
        }
    }
}

// ---------------------------------------------------------------------------
// RoPE (in-place on half). Pair (i, i+32) within each head.
// ---------------------------------------------------------------------------
__global__ void rope_kernel(__half* __restrict__ X, int nheads)
{
    int idx = blockIdx.x * blockDim.x + threadIdx.x;
    int total = MM * nheads * (HD / 2);
    if (idx >= total) return;
    int i = idx & 31;
    int t = idx >> 5;
    int h = t % nheads;
    int ms = t / nheads;
    int s = ms & (SS - 1);

    const float LOG_THETA_OVER_HALF = 9.210340371976184f / 32.0f;
    float inv = expf(-(float)i * LOG_THETA_OVER_HALF);
    float ang = (float)s * inv;
    float sn, cs;
    sincosf(ang, &sn, &cs);

    __half* base = X + (size_t)ms * nheads * HD + h * HD;
    float x1 = __half2float(base[i]);
    float x2 = __half2float(base[i + 32]);
    base[i]      = __float2half_rn(x1 * cs - x2 * sn);
    base[i + 32] = __float2half_rn(x2 * cs + x1 * sn);
}

// ---------------------------------------------------------------------------
// FP16 flash attention v2: 128 q-rows per CTA (256 thr, 8 warps), causal,
// 64-token K/V tiles double-buffered via cp.async. Verified maps only.
// V from g_Vt [d][token]. Q pre-scaled by 0.125.
// ---------------------------------------------------------------------------
#define FST 72
#define KT_H (64 * FST)            // halves per K/V buffer
#define KT_B (KT_H * 2)            // bytes
#define ATT_SMEM ((2 * 128 * FST + 4 * 64 * FST) * 2)   // 73728 bytes

__global__ __launch_bounds__(256) void attn_kernel()
{
    extern __shared__ __half smh[];
    __half* Qs = smh;                          // 128 x FST
    __half* Ps = smh + 128 * FST;              // 128 x FST
    __half* Kb = smh + 2 * 128 * FST;          // 2 x 64 x FST
    __half* Vb = Kb + 2 * KT_H;                // 2 x 64 x FST

    int qt = (gridDim.x - 1) - blockIdx.x;     // heavy-first
    int h = blockIdx.y, b = blockIdx.z;
    int kvh = h >> 2;
    int tid = threadIdx.x, lane = tid & 31, w = tid >> 5;
    int lg = lane >> 2, lk = lane & 3;

    uint32_t Qs_u = (uint32_t)__cvta_generic_to_shared(Qs);
    uint32_t Ps_u = (uint32_t)__cvta_generic_to_shared(Ps);
    uint32_t Kb_u = (uint32_t)__cvta_generic_to_shared(Kb);
    uint32_t Vb_u = (uint32_t)__cvta_generic_to_shared(Vb);

    const __half* Vtg = g_Vt + (size_t)(b * (NKV * HD) + kvh * HD) * SS;

    // load Q tile (128 rows x 64 halves), scale by 0.125
    const __half* Qg = g_Qh + (size_t)(b * SS + qt * 128) * (NQ * HD) + h * HD;
    const __half2 sc = __float2half2_rn(0.125f);
    for (int i = tid; i < 128 * 8; i += 256) {
        int rr = i >> 3, c8 = (i & 7) * 8;
        uint4 raw = *(const uint4*)(Qg + (size_t)rr * (NQ * HD) + c8);
        __half2 p0 = __hmul2(*(__half2*)&raw.x, sc);
        __half2 p1 = __hmul2(*(__half2*)&raw.y, sc);
        __half2 p2 = __hmul2(*(__half2*)&raw.z, sc);
        __half2 p3 = __hmul2(*(__half2*)&raw.w, sc);
        uint4 outv;
        outv.x = *(uint32_t*)&p0; outv.y = *(uint32_t*)&p1;
        outv.z = *(uint32_t*)&p2; outv.w = *(uint32_t*)&p3;
        *(uint4*)&Qs[rr * FST + c8] = outv;
    }

    // loader lane precompute: 2 K chunks + 2 V chunks per thread per tile
    int kid0 = tid, kid1 = tid + 256;
    int kr0 = kid0 >> 3, kc0 = (kid0 & 7) * 8;
    int kr1 = kid1 >> 3, kc1 = (kid1 & 7) * 8;

    // prologue: prefetch tile 0 into buffer 0
    {
        const __half* Kg = g_Kh + (size_t)(b * SS) * (NKV * HD) + kvh * HD;
        cp16(Kb_u + (uint32_t)((kr0 * FST + kc0) * 2), Kg + (size_t)kr0 * (NKV * HD) + kc0);
        cp16(Kb_u + (uint32_t)((kr1 * FST + kc1) * 2), Kg + (size_t)kr1 * (NKV * HD) + kc1);
        cp16(Vb_u + (uint32_t)((kr0 * FST + kc0) * 2), Vtg + (size_t)kr0 * SS + kc0);
        cp16(Vb_u + (uint32_t)((kr1 * FST + kc1) * 2), Vtg + (size_t)kr1 * SS + kc1);
        cp_commit();
    }
    __syncthreads();   // Q tile visible to all

    // Q fragments (verified A-map), 4 k-steps of 16
    int arow = lane & 15, akh = (lane >> 4) * 8;
    uint32_t qa_off = (uint32_t)(((w * 16 + arow) * FST + akh) * 2);
    uint32_t qf[4][4];
#pragma unroll
    for (int ks = 0; ks < 4; ks++)
        ldsm_x4(qf[ks], Qs_u + qa_off + (uint32_t)(ks * 16 * 2));

    float o[8][4];
#pragma unroll
    for (int j = 0; j < 8; j++)
#pragma unroll
        for (int t = 0; t < 4; t++) o[j][t] = 0.f;
    float m0 = -INFINITY, m1 = -INFINITY, l0 = 0.f, l1 = 0.f;
    int qr0 = w * 16 + lg, qr1 = qr0 + 8;
    int row0 = qt * 128 + qr0, row1 = row0 + 8;

    // verified B-map lane offset (K and V^T tiles)
    int brow = (lane & 7) + (lane >> 4) * 8;
    int bkh  = ((lane >> 3) & 1) * 8;
    uint32_t kb_off = (uint32_t)((brow * FST + bkh) * 2);

    const int NT = 2 * qt + 2;

    for (int kt = 0; kt < NT; kt++) {
        // prefetch kt+1 into the other buffer
        if (kt + 1 < NT) {
            int nb = (kt + 1) & 1;
            const __half* Kg = g_Kh + (size_t)(b * SS + (kt + 1) * 64) * (NKV * HD) + kvh * HD;
            cp16(Kb_u + (uint32_t)(nb * KT_B) + (uint32_t)((kr0 * FST + kc0) * 2), Kg + (size_t)kr0 * (NKV * HD) + kc0);
            cp16(Kb_u + (uint32_t)(nb * KT_B) + (uint32_t)((kr1 * FST + kc1) * 2), Kg + (size_t)kr1 * (NKV * HD) + kc1);
            cp16(Vb_u + (uint32_t)(nb * KT_B) + (uint32_t)((kr0 * FST + kc0) * 2), Vtg + (size_t)kr0 * SS + (kt + 1) * 64 + kc0);
            cp16(Vb_u + (uint32_t)(nb * KT_B) + (uint32_t)((kr1 * FST + kc1) * 2), Vtg + (size_t)kr1 * SS + (kt + 1) * 64 + kc1);
            cp_commit();
            cp_wait1();    // tile kt complete
        } else {
            cp_wait0();
        }
        __syncthreads();

        uint32_t kbase = Kb_u + (uint32_t)((kt & 1) * KT_B);
        uint32_t vbase = Vb_u + (uint32_t)((kt & 1) * KT_B);

        // S = (Q*0.125) K^T
        float s[8][4];
#pragma unroll
        for (int j = 0; j < 8; j++) { s[j][0] = s[j][1] = s[j][2] = s[j][3] = 0.f; }
#pragma unroll
        for (int ks = 0; ks < 4; ks++) {
            uint32_t bf[4][4];
#pragma unroll
            for (int np = 0; np < 4; np++)
                ldsm_x4(bf[np], kbase + kb_off + (uint32_t)((np * 16 * FST + ks * 16) * 2));
#pragma unroll
            for (int j = 0; j < 8; j++)
                mma_f16(s[j], qf[ks], bf[j >> 1][(j & 1) * 2], bf[j >> 1][(j & 1) * 2 + 1]);
        }

        if (kt >= 2 * qt) {
#pragma unroll
            for (int j = 0; j < 8; j++) {
                int c0 = kt * 64 + j * 8 + 2 * lk, c1 = c0 + 1;
                if (c0 > row0) s[j][0] = -INFINITY;
                if (c1 > row0) s[j][1] = -INFINITY;
                if (c0 > row1) s[j][2] = -INFINITY;
                if (c1 > row1) s[j][3] = -INFINITY;
            }
        }

        float mn0 = s[0][0], mn1 = s[0][2];
#pragma unroll
        for (int j = 0; j < 8; j++) {
            mn0 = fmaxf(mn0, fmaxf(s[j][0], s[j][1]));
            mn1 = fmaxf(mn1, fmaxf(s[j][2], s[j][3]));
        }
        mn0 = fmaxf(mn0, __shfl_xor_sync(0xffffffffu, mn0, 1));
        mn0 = fmaxf(mn0, __shfl_xor_sync(0xffffffffu, mn0, 2));
        mn1 = fmaxf(mn1, __shfl_xor_sync(0xffffffffu, mn1, 1));
        mn1 = fmaxf(mn1, __shfl_xor_sync(0xffffffffu, mn1, 2));
        float mnew0 = fmaxf(m0, mn0), mnew1 = fmaxf(m1, mn1);
        float a0 = __expf(m0 - mnew0), a1 = __expf(m1 - mnew1);

        float ll0 = 0.f, ll1 = 0.f;
#pragma unroll
        for (int j = 0; j < 8; j++) {
            float p0 = __expf(s[j][0] - mnew0);
            float p1 = __expf(s[j][1] - mnew0);
            float p2 = __expf(s[j][2] - mnew1);
            float p3 = __expf(s[j][3] - mnew1);
            ll0 += p0 + p1; ll1 += p2 + p3;
            *(__half2*)&Ps[qr0 * FST + j * 8 + 2 * lk] = __floats2half2_rn(p0, p1);
            *(__half2*)&Ps[qr1 * FST + j * 8 + 2 * lk] = __floats2half2_rn(p2, p3);
        }
        ll0 += __shfl_xor_sync(0xffffffffu, ll0, 1);
        ll0 += __shfl_xor_sync(0xffffffffu, ll0, 2);
        ll1 += __shfl_xor_sync(0xffffffffu, ll1, 1);
        ll1 += __shfl_xor_sync(0xffffffffu, ll1, 2);
        l0 = l0 * a0 + ll0; l1 = l1 * a1 + ll1;
        m0 = mnew0; m1 = mnew1;
#pragma unroll
        for (int j = 0; j < 8; j++) {
            o[j][0] *= a0; o[j][1] *= a0; o[j][2] *= a1; o[j][3] *= a1;
        }
        __syncwarp();

        // P fragments (verified A-map)
        uint32_t pf[4][4];
#pragma unroll
        for (int ks = 0; ks < 4; ks++)
            ldsm_x4(pf[ks], Ps_u + qa_off + (uint32_t)(ks * 16 * 2));

        // O += P V : B operand = Vs[d][token] via verified B-map
#pragma unroll
        for (int ks = 0; ks < 4; ks++) {
            uint32_t vf[4][4];
#pragma unroll
            for (int np = 0; np < 4; np++)
                ldsm_x4(vf[np], vbase + kb_off + (uint32_t)((np * 16 * FST + ks * 16) * 2));
#pragma unroll
            for (int j = 0; j < 8; j++)
                mma_f16(o[j], pf[ks], vf[j >> 1][(j & 1) * 2], vf[j >> 1][(j & 1) * 2 + 1]);
        }
        __syncthreads();   // all warps done with buffer (kt&1) before next prefetch overwrites the OTHER one; and P reuse
    }

    float il0 = 1.0f / l0, il1 = 1.0f / l1;
    int gr0 = b * SS + qt * 128 + qr0;
#pragma unroll
    for (int j = 0; j < 8; j++) {
        int cc = h * HD + j * 8 + 2 * lk;
        *(__half2*)(g_attnh + (size_t)gr0 * DD + cc) = __floats2half2_rn(o[j][0] * il0, o[j][1] * il0);
        *(__half2*)(g_attnh + (size_t)(gr0 + 8) * DD + cc) = __floats2half2_rn(o[j][2] * il1, o[j][3] * il1);
    }
}

// ---------------------------------------------------------------------------
extern "C" void kernel_launch(void* const* d_in, const int* in_sizes, int n_in,
                              void* d_out, int out_size)
{
    const float* x  = (const float*)d_in[0];
    const float* Wq = (const float*)d_in[2];
    const float* Wk = (const float*)d_in[3];
    const float* Wv = (const float*)d_in[4];
    const float* Wo = (const float*)d_in[5];
    float* out = (float*)d_out;

    __half *Qh, *Kh, *Ah, *xh, *Wqh, *Wkh, *Wvh, *Woh, *Vth;
    cudaGetSymbolAddress((void**)&Qh, g_Qh);
    cudaGetSymbolAddress((void**)&Kh, g_Kh);
    cudaGetSymbolAddress((void**)&Vth, g_Vt);
    cudaGetSymbolAddress((void**)&Ah, g_attnh);
    cudaGetSymbolAddress((void**)&xh, g_xh);
    cudaGetSymbolAddress((void**)&Wqh, g_Wqh);
    cudaGetSymbolAddress((void**)&Wkh, g_Wkh);
    cudaGetSymbolAddress((void**)&Wvh, g_Wvh);
    cudaGetSymbolAddress((void**)&Woh, g_Woh);

    {
        int n4;
        n4 = MM * DD / 4;            cvt_f16_kernel<<<(n4 + 255) / 256, 256>>>(x,  xh,  n4);
        n4 = DD * DD / 4;            cvt_f16_kernel<<<(n4 + 255) / 256, 256>>>(Wq, Wqh, n4);
        n4 = (NKV * HD) * DD / 4;    cvt_f16_kernel<<<(n4 + 255) / 256, 256>>>(Wk, Wkh, n4);
        n4 = (NKV * HD) * DD / 4;    cvt_f16_kernel<<<(n4 + 255) / 256, 256>>>(Wv, Wvh, n4);
        n4 = DD * DD / 4;            cvt_f16_kernel<<<(n4 + 255) / 256, 256>>>(Wo, Woh, n4);
    }

    cudaFuncSetAttribute(gemm_f16<__half>, cudaFuncAttributeMaxDynamicSharedMemorySize, GEMM_SMEM);
    cudaFuncSetAttribute(gemm_f16<float>, cudaFuncAttributeMaxDynamicSharedMemorySize, GEMM_SMEM);

    // Fused QKV: bx 0..15 -> Q, 16..19 -> K, 20..23 -> V (transposed into g_Vt)
    gemm_f16<__half><<<dim3(24, MM / 128), 128, GEMM_SMEM>>>(xh, Wqh, Wkh, Wvh,
                                                             Qh, Kh, Kh, 16, 4, 1);

    {
        int totq = MM * NQ * (HD / 2);
        rope_kernel<<<(totq + 255) / 256, 256>>>(Qh, NQ);
        int totk = MM * NKV * (HD / 2);
        rope_kernel<<<(totk + 255) / 256, 256>>>(Kh, NKV);
    }

    {
        cudaFuncSetAttribute(attn_kernel, cudaFuncAttributeMaxDynamicSharedMemorySize, ATT_SMEM);
        attn_kernel<<<dim3(SS / 128, NQ, BB), 256, ATT_SMEM>>>();
    }

    // Output projection -> fp32 out
    gemm_f16<float><<<dim3(16, MM / 128), 128, GEMM_SMEM>>>(Ah, Woh, Woh, Woh,
                                                            out, out, out, 16, 0, 0);
}

// round 16
// speedup vs baseline: 16.1636x; 1.0513x over previous
#include <cuda_runtime.h>
#include <cuda_fp16.h>
#include <math.h>
#include <stdint.h>

#define BB 2
#define SS 2048
#define DD 2048
#define NQ 32
#define NKV 8
#define HD 64
#define MM (BB*SS)   // 4096
#define KK 2048

// Scratch (no cudaMalloc allowed)
__device__ __half g_Qh[(size_t)MM * NQ * HD];
__device__ __half g_Kh[(size_t)MM * NKV * HD];
__device__ __half g_Vt[(size_t)BB * NKV * HD * SS];   // [(b*8+kvh)*64+d][token]
__device__ __half g_attnh[(size_t)MM * DD];
__device__ __half g_xh[(size_t)MM * DD];
__device__ __half g_Wqh[(size_t)DD * DD];
__device__ __half g_Wkh[(size_t)(NKV*HD) * DD];
__device__ __half g_Wvh[(size_t)(NKV*HD) * DD];
__device__ __half g_Woh[(size_t)DD * DD];

__device__ __forceinline__ void mma_f16(float* c, const uint32_t* a, uint32_t b0, uint32_t b1) {
    asm volatile(
        "mma.sync.aligned.m16n8k16.row.col.f32.f16.f16.f32 "
        "{%0,%1,%2,%3}, {%4,%5,%6,%7}, {%8,%9}, {%0,%1,%2,%3};"
        : "+f"(c[0]), "+f"(c[1]), "+f"(c[2]), "+f"(c[3])
        : "r"(a[0]), "r"(a[1]), "r"(a[2]), "r"(a[3]), "r"(b0), "r"(b1));
}

__device__ __forceinline__ void ldsm_x4(uint32_t* d, uint32_t saddr) {
    asm volatile("ldmatrix.sync.aligned.m8n8.x4.shared.b16 {%0,%1,%2,%3}, [%4];"
        : "=r"(d[0]), "=r"(d[1]), "=r"(d[2]), "=r"(d[3]) : "r"(saddr));
}

__device__ __forceinline__ void cp16(uint32_t dst, const void* src) {
    asm volatile("cp.async.cg.shared.global [%0], [%1], 16;" :: "r"(dst), "l"(src));
}
__device__ __forceinline__ void cp_commit() { asm volatile("cp.async.commit_group;"); }
__device__ __forceinline__ void cp_wait2()  { asm volatile("cp.async.wait_group 2;"); }
__device__ __forceinline__ void cp_wait1()  { asm volatile("cp.async.wait_group 1;"); }
__device__ __forceinline__ void cp_wait0()  { asm volatile("cp.async.wait_group 0;"); }

// ---------------------------------------------------------------------------
// Fused elementwise fp32 -> fp16 conversion for all five tensors (one launch).
// ---------------------------------------------------------------------------
#define N_X   (MM * DD / 4)                 // 2097152
#define N_WQ  (DD * DD / 4)                 // 1048576
#define N_WK  ((NKV * HD) * DD / 4)         // 262144
#define CVT_TOTAL (N_X + 2 * N_WQ + 2 * N_WK)

__global__ void cvt_all_kernel(const float* __restrict__ x,  const float* __restrict__ wq,
                               const float* __restrict__ wk, const float* __restrict__ wv,
                               const float* __restrict__ wo,
                               __half* __restrict__ xh,  __half* __restrict__ wqh,
                               __half* __restrict__ wkh, __half* __restrict__ wvh,
                               __half* __restrict__ woh)
{
    int i = blockIdx.x * blockDim.x + threadIdx.x;
    if (i >= CVT_TOTAL) return;
    const float* src; __half* dst; int off;
    if (i < N_X)                         { src = x;  dst = xh;  off = i; }
    else if (i < N_X + N_WQ)             { src = wq; dst = wqh; off = i - N_X; }
    else if (i < N_X + N_WQ + N_WK)      { src = wk; dst = wkh; off = i - N_X - N_WQ; }
    else if (i < N_X + N_WQ + 2 * N_WK)  { src = wv; dst = wvh; off = i - N_X - N_WQ - N_WK; }
    else                                 { src = wo; dst = woh; off = i - N_X - N_WQ - 2 * N_WK; }
    float4 v = ((const float4*)src)[off];
    __half2 h0 = __floats2half2_rn(v.x, v.y);
    __half2 h1 = __floats2half2_rn(v.z, v.w);
    uint2 o;
    o.x = *(uint32_t*)&h0;
    o.y = *(uint32_t*)&h1;
    ((uint2*)dst)[off] = o;
}

// ---------------------------------------------------------------------------
// FP16 GEMM (verified core, UNCHANGED). C = A * B^T. 128x128, BK=32, 128 thr.
// tv=1: W2 route scatter-stores output TRANSPOSED into g_Vt.
// ---------------------------------------------------------------------------
#define ASTH 40
#define STAGE_H (128 * ASTH)
#define NSTG 4
#define GEMM_SMEM (NSTG * 2 * STAGE_H * 2)   // 81920 bytes

template<typename OutT>
__global__ __launch_bounds__(128, 2) void gemm_f16(
    const __half* __restrict__ A,
    const __half* __restrict__ W0, const __half* __restrict__ W1, const __half* __restrict__ W2,
    OutT* __restrict__ C0, OutT* __restrict__ C1, OutT* __restrict__ C2,
    int nb0, int nb1, int tv)
{
    extern __shared__ __half smemh[];
    __half* As = smemh;
    __half* Bs = smemh + NSTG * STAGE_H;

    int tid = threadIdx.x;
    int lane = tid & 31;
    int warp = tid >> 5;
    int wm = warp >> 1, wn = warp & 1;
    int bx = blockIdx.x;
    int bm = blockIdx.y * 128;
    int lg = lane >> 2, lk = lane & 3;

    const __half* Bsel; OutT* Csel; int Ncol, bn;
    int vroute = 0;
    if (bx < nb0)            { Bsel = W0; Csel = C0; Ncol = 2048; bn = bx * 128; }
    else if (bx < nb0 + nb1) { Bsel = W1; Csel = C1; Ncol = 512;  bn = (bx - nb0) * 128; }
    else                     { Bsel = W2; Csel = C2; Ncol = 512;  bn = (bx - nb0 - nb1) * 128; vroute = tv; }

    uint32_t As_u = (uint32_t)__cvta_generic_to_shared(As);
    uint32_t Bs_u = (uint32_t)__cvta_generic_to_shared(Bs);

    int a_row = lane & 15;
    int a_kh  = (lane >> 4) * 8;
    int b_row = (lane & 7) + (lane >> 4) * 8;
    int b_kh  = ((lane >> 3) & 1) * 8;
    uint32_t a_off = (uint32_t)(((wm * 64 + a_row) * ASTH + a_kh) * 2);
    uint32_t b_off = (uint32_t)(((wn * 64 + b_row) * ASTH + b_kh) * 2);

    float acc[4][8][4];
#pragma unroll
    for (int i = 0; i < 4; i++)
#pragma unroll
        for (int j = 0; j < 8; j++)
#pragma unroll
            for (int t = 0; t < 4; t++) acc[i][j][t] = 0.f;

    const __half* Agp[4]; const __half* Bgp[4]; uint32_t Ssm[4];
#pragma unroll
    for (int j = 0; j < 4; j++) {
        int ch = tid + j * 128;
        int row = ch >> 2, c = ch & 3;
        Agp[j] = A + (size_t)(bm + row) * KK + c * 8;
        Bgp[j] = Bsel + (size_t)(bn + row) * KK + c * 8;
        Ssm[j] = (uint32_t)((row * ASTH + c * 8) * 2);
    }

    const int NT = KK / 32;

#pragma unroll
    for (int t = 0; t < 3; t++) {
        uint32_t as = As_u + t * STAGE_H * 2;
        uint32_t bs = Bs_u + t * STAGE_H * 2;
#pragma unroll
        for (int j = 0; j < 4; j++) {
            cp16(as + Ssm[j], Agp[j] + t * 32);
            cp16(bs + Ssm[j], Bgp[j] + t * 32);
        }
        cp_commit();
    }

    for (int i = 0; i < NT; i++) {
        cp_wait2();
        __syncthreads();
        if (i + 3 < NT) {
            int sl = (i + 3) & 3;
            uint32_t as = As_u + sl * STAGE_H * 2;
            uint32_t bs = Bs_u + sl * STAGE_H * 2;
#pragma unroll
            for (int j = 0; j < 4; j++) {
                cp16(as + Ssm[j], Agp[j] + (i + 3) * 32);
                cp16(bs + Ssm[j], Bgp[j] + (i + 3) * 32);
            }
        }
        cp_commit();

        uint32_t as = As_u + (i & 3) * STAGE_H * 2;
        uint32_t bs = Bs_u + (i & 3) * STAGE_H * 2;
#pragma unroll
        for (int ks = 0; ks < 2; ks++) {
            uint32_t af[4][4];
#pragma unroll
            for (int mi = 0; mi < 4; mi++)
                ldsm_x4(af[mi], as + a_off + (uint32_t)((mi * 16 * ASTH + ks * 16) * 2));
            uint32_t bf[4][4];
#pragma unroll
            for (int np = 0; np < 4; np++)
                ldsm_x4(bf[np], bs + b_off + (uint32_t)((np * 16 * ASTH + ks * 16) * 2));
#pragma unroll
            for (int mi = 0; mi < 4; mi++)
#pragma unroll
                for (int ni = 0; ni < 8; ni++)
                    mma_f16(acc[mi][ni], af[mi], bf[ni >> 1][(ni & 1) * 2], bf[ni >> 1][(ni & 1) * 2 + 1]);
        }
    }

    if (vroute) {
#pragma unroll
        for (int mi = 0; mi < 4; mi++) {
#pragma unroll
            for (int ni = 0; ni < 8; ni++) {
                int token0 = bm + wm * 64 + mi * 16 + lg;
                int col = bn + wn * 64 + ni * 8 + lk * 2;
#pragma unroll
                for (int half_m = 0; half_m < 2; half_m++) {
                    int token = token0 + half_m * 8;
                    int b = token >> 11, s2 = token & (SS - 1);
                    g_Vt[((size_t)(b * (NKV * HD) + col)) * SS + s2]     = __float2half_rn(acc[mi][ni][half_m * 2 + 0]);
                    g_Vt[((size_t)(b * (NKV * HD) + col + 1)) * SS + s2] = __float2half_rn(acc[mi][ni][half_m * 2 + 1]);
                }
            }
        }
    } else {
#pragma unroll
        for (int mi = 0; mi < 4; mi++) {
#pragma unroll
            for (int ni = 0; ni < 8; ni++) {
                int rr = bm + wm * 64 + mi * 16 + lg;
                int cc = bn + wn * 64 + ni * 8 + lk * 2;
                if (sizeof(OutT) == 4) {
                    float* Cf = (float*)Csel;
                    *(float2*)(Cf + (size_t)rr * Ncol + cc) = make_float2(acc[mi][ni][0], acc[mi][ni][1]);
                    *(float2*)(Cf + (size_t)(rr + 8) * Ncol + cc) = make_float2(acc[mi][ni][2], acc[mi][ni][3]);
                } else {
                    __half* Ch = (__half*)Csel;
                    *(__half2*)(Ch + (size_t)rr * Ncol + cc) = __floats2half2_rn(acc[mi][ni][0], acc[mi][ni][1]);
                    *(__half2*)(Ch + (size_t)(rr + 8) * Ncol + cc) = __floats2half2_rn(acc[mi][ni][2], acc[mi][ni][3]);
                }
            }
        }
    }
}

// ---------------------------------------------------------------------------
// RoPE fused: ONE sincos per (s, i), reused across all 32 Q heads + 8 K heads.
// Warp lane = pair index i (0..31); each warp owns one token ms.
// Q additionally scaled by 0.125 (exact; folded out of the attention kernel).
// ---------------------------------------------------------------------------
__global__ void rope_fused_kernel()
{
    int ms = blockIdx.x * 8 + (threadIdx.x >> 5);
    if (ms >= MM) return;
    int i = threadIdx.x & 31;
    int s = ms & (SS - 1);

    const float LOG_THETA_OVER_HALF = 9.210340371976184f / 32.0f;
    float inv = expf(-(float)i * LOG_THETA_OVER_HALF);
    float ang = (float)s * inv;
    float sn, cs;
    sincosf(ang, &sn, &cs);

    __half* Qb = g_Qh + (size_t)ms * (NQ * HD);
#pragma unroll 4
    for (int h = 0; h < NQ; h++) {
        float x1 = __half2float(Qb[h * HD + i]);
        float x2 = __half2float(Qb[h * HD + i + 32]);
        Qb[h * HD + i]      = __float2half_rn((x1 * cs - x2 * sn) * 0.125f);
        Qb[h * HD + i + 32] = __float2half_rn((x2 * cs + x1 * sn) * 0.125f);
    }
    __half* Kb = g_Kh + (size_t)ms * (NKV * HD);
#pragma unroll
    for (int h = 0; h < NKV; h++) {
        float x1 = __half2float(Kb[h * HD + i]);
        float x2 = __half2float(Kb[h * HD + i + 32]);
        Kb[h * HD + i]      = __float2half_rn(x1 * cs - x2 * sn);
        Kb[h * HD + i + 32] = __float2half_rn(x2 * cs + x1 * sn);
    }
}

// ---------------------------------------------------------------------------
// FP16 flash attention: 128 q-rows per CTA (256 thr, 8 warps), causal,
// 64-token K/V tiles double-buffered via cp.async. Verified maps only.
// V from g_Vt [d][token]. Q arrives pre-scaled by 0.125 (done in rope).
// ---------------------------------------------------------------------------
#define FST 72
#define KT_H (64 * FST)
#define KT_B (KT_H * 2)
#define ATT_SMEM ((2 * 128 * FST + 4 * 64 * FST) * 2)   // 73728 bytes

__global__ __launch_bounds__(256) void attn_kernel()
{
    extern __shared__ __half smh[];
    __half* Qs = smh;                          // 128 x FST
    __half* Ps = smh + 128 * FST;              // 128 x FST
    __half* Kb = smh + 2 * 128 * FST;          // 2 x 64 x FST
    __half* Vb = Kb + 2 * KT_H;                // 2 x 64 x FST

    int qt = (gridDim.x - 1) - blockIdx.x;     // heavy-first
    int h = blockIdx.y, b = blockIdx.z;
    int kvh = h >> 2;
    int tid = threadIdx.x, lane = tid & 31, w = tid >> 5;
    int lg = lane >> 2, lk = lane & 3;

    uint32_t Qs_u = (uint32_t)__cvta_generic_to_shared(Qs);
    uint32_t Ps_u = (uint32_t)__cvta_generic_to_shared(Ps);
    uint32_t Kb_u = (uint32_t)__cvta_generic_to_shared(Kb);
    uint32_t Vb_u = (uint32_t)__cvta_generic_to_shared(Vb);

    const __half* Vtg = g_Vt + (size_t)(b * (NKV * HD) + kvh * HD) * SS;

    // load Q tile (128 rows x 64 halves) — pre-scaled in rope
    const __half* Qg = g_Qh + (size_t)(b * SS + qt * 128) * (NQ * HD) + h * HD;
    for (int i = tid; i < 128 * 8; i += 256) {
        int rr = i >> 3, c8 = (i & 7) * 8;
        *(uint4*)&Qs[rr * FST + c8] = *(const uint4*)(Qg + (size_t)rr * (NQ * HD) + c8);
    }

    int kid0 = tid, kid1 = tid + 256;
    int kr0 = kid0 >> 3, kc0 = (kid0 & 7) * 8;
    int kr1 = kid1 >> 3, kc1 = (kid1 & 7) * 8;

    // prologue: prefetch tile 0 into buffer 0
    {
        const __half* Kg = g_Kh + (size_t)(b * SS) * (NKV * HD) + kvh * HD;
        cp16(Kb_u + (uint32_t)((kr0 * FST + kc0) * 2), Kg + (size_t)kr0 * (NKV * HD) + kc0);
        cp16(Kb_u + (uint32_t)((kr1 * FST + kc1) * 2), Kg + (size_t)kr1 * (NKV * HD) + kc1);
        cp16(Vb_u + (uint32_t)((kr0 * FST + kc0) * 2), Vtg + (size_t)kr0 * SS + kc0);
        cp16(Vb_u + (uint32_t)((kr1 * FST + kc1) * 2), Vtg + (size_t)kr1 * SS + kc1);
        cp_commit();
    }
    __syncthreads();

    int arow = lane & 15, akh = (lane >> 4) * 8;
    uint32_t qa_off = (uint32_t)(((w * 16 + arow) * FST + akh) * 2);
    uint32_t qf[4][4];
#pragma unroll
    for (int ks = 0; ks < 4; ks++)
        ldsm_x4(qf[ks], Qs_u + qa_off + (uint32_t)(ks * 16 * 2));

    float o[8][4];
#pragma unroll
    for (int j = 0; j < 8; j++)
#pragma unroll
        for (int t = 0; t < 4; t++) o[j][t] = 0.f;
    float m0 = -INFINITY, m1 = -INFINITY, l0 = 0.f, l1 = 0.f;
    int qr0 = w * 16 + lg, qr1 = qr0 + 8;
    int row0 = qt * 128 + qr0, row1 = row0 + 8;

    int brow = (lane & 7) + (lane >> 4) * 8;
    int bkh  = ((lane >> 3) & 1) * 8;
    uint32_t kb_off = (uint32_t)((brow * FST + bkh) * 2);

    const int NT = 2 * qt + 2;

    for (int kt = 0; kt < NT; kt++) {
        if (kt + 1 < NT) {
            int nb = (kt + 1) & 1;
            const __half* Kg = g_Kh + (size_t)(b * SS + (kt + 1) * 64) * (NKV * HD) + kvh * HD;
            cp16(Kb_u + (uint32_t)(nb * KT_B) + (uint32_t)((kr0 * FST + kc0) * 2), Kg + (size_t)kr0 * (NKV * HD) + kc0);
            cp16(Kb_u + (uint32_t)(nb * KT_B) + (uint32_t)((kr1 * FST + kc1) * 2), Kg + (size_t)kr1 * (NKV * HD) + kc1);
            cp16(Vb_u + (uint32_t)(nb * KT_B) + (uint32_t)((kr0 * FST + kc0) * 2), Vtg + (size_t)kr0 * SS + (kt + 1) * 64 + kc0);
            cp16(Vb_u + (uint32_t)(nb * KT_B) + (uint32_t)((kr1 * FST + kc1) * 2), Vtg + (size_t)kr1 * SS + (kt + 1) * 64 + kc1);
            cp_commit();
            cp_wait1();
        } else {
            cp_wait0();
        }
        __syncthreads();

        uint32_t kbase = Kb_u + (uint32_t)((kt & 1) * KT_B);
        uint32_t vbase = Vb_u + (uint32_t)((kt & 1) * KT_B);

        float s[8][4];
#pragma unroll
        for (int j = 0; j < 8; j++) { s[j][0] = s[j][1] = s[j][2] = s[j][3] = 0.f; }
#pragma unroll
        for (int ks = 0; ks < 4; ks++) {
            uint32_t bf[4][4];
#pragma unroll
            for (int np = 0; np < 4; np++)
                ldsm_x4(bf[np], kbase + kb_off + (uint32_t)((np * 16 * FST + ks * 16) * 2));
#pragma unroll
            for (int j = 0; j < 8; j++)
                mma_f16(s[j], qf[ks], bf[j >> 1][(j & 1) * 2], bf[j >> 1][(j & 1) * 2 + 1]);
        }

        if (kt >= 2 * qt) {
#pragma unroll
            for (int j = 0; j < 8; j++) {
                int c0 = kt * 64 + j * 8 + 2 * lk, c1 = c0 + 1;
                if (c0 > row0) s[j][0] = -INFINITY;
                if (c1 > row0) s[j][1] = -INFINITY;
                if (c0 > row1) s[j][2] = -INFINITY;
                if (c1 > row1) s[j][3] = -INFINITY;
            }
        }

        float mn0 = s[0][0], mn1 = s[0][2];
#pragma unroll
        for (int j = 0; j < 8; j++) {
            mn0 = fmaxf(mn0, fmaxf(s[j][0], s[j][1]));
            mn1 = fmaxf(mn1, fmaxf(s[j][2], s[j][3]));
        }
        mn0 = fmaxf(mn0, __shfl_xor_sync(0xffffffffu, mn0, 1));
        mn0 = fmaxf(mn0, __shfl_xor_sync(0xffffffffu, mn0, 2));
        mn1 = fmaxf(mn1, __shfl_xor_sync(0xffffffffu, mn1, 1));
        mn1 = fmaxf(mn1, __shfl_xor_sync(0xffffffffu, mn1, 2));
        float mnew0 = fmaxf(m0, mn0), mnew1 = fmaxf(m1, mn1);
        float a0 = __expf(m0 - mnew0), a1 = __expf(m1 - mnew1);

        float ll0 = 0.f, ll1 = 0.f;
#pragma unroll
        for (int j = 0; j < 8; j++) {
            float p0 = __expf(s[j][0] - mnew0);
            float p1 = __expf(s[j][1] - mnew0);
            float p2 = __expf(s[j][2] - mnew1);
            float p3 = __expf(s[j][3] - mnew1);
            ll0 += p0 + p1; ll1 += p2 + p3;
            *(__half2*)&Ps[qr0 * FST + j * 8 + 2 * lk] = __floats2half2_rn(p0, p1);
            *(__half2*)&Ps[qr1 * FST + j * 8 + 2 * lk] = __floats2half2_rn(p2, p3);
        }
        ll0 += __shfl_xor_sync(0xffffffffu, ll0, 1);
        ll0 += __shfl_xor_sync(0xffffffffu, ll0, 2);
        ll1 += __shfl_xor_sync(0xffffffffu, ll1, 1);
        ll1 += __shfl_xor_sync(0xffffffffu, ll1, 2);
        l0 = l0 * a0 + ll0; l1 = l1 * a1 + ll1;
        m0 = mnew0; m1 = mnew1;
#pragma unroll
        for (int j = 0; j < 8; j++) {
            o[j][0] *= a0; o[j][1] *= a0; o[j][2] *= a1; o[j][3] *= a1;
        }
        __syncwarp();

        uint32_t pf[4][4];
#pragma unroll
        for (int ks = 0; ks < 4; ks++)
            ldsm_x4(pf[ks], Ps_u + qa_off + (uint32_t)(ks * 16 * 2));

#pragma unroll
        for (int ks = 0; ks < 4; ks++) {
            uint32_t vf[4][4];
#pragma unroll
            for (int np = 0; np < 4; np++)
                ldsm_x4(vf[np], vbase + kb_off + (uint32_t)((np * 16 * FST + ks * 16) * 2));
#pragma unroll
            for (int j = 0; j < 8; j++)
                mma_f16(o[j], pf[ks], vf[j >> 1][(j & 1) * 2], vf[j >> 1][(j & 1) * 2 + 1]);
        }
        __syncthreads();
    }

    float il0 = 1.0f / l0, il1 = 1.0f / l1;
    int gr0 = b * SS + qt * 128 + qr0;
#pragma unroll
    for (int j = 0; j < 8; j++) {
        int cc = h * HD + j * 8 + 2 * lk;
        *(__half2*)(g_attnh + (size_t)gr0 * DD + cc) = __floats2half2_rn(o[j][0] * il0, o[j][1] * il0);
        *(__half2*)(g_attnh + (size_t)(gr0 + 8) * DD + cc) = __floats2half2_rn(o[j][2] * il1, o[j][3] * il1);
    }
}

// ---------------------------------------------------------------------------
extern "C" void kernel_launch(void* const* d_in, const int* in_sizes, int n_in,
                              void* d_out, int out_size)
{
    const float* x  = (const float*)d_in[0];
    const float* Wq = (const float*)d_in[2];
    const float* Wk = (const float*)d_in[3];
    const float* Wv = (const float*)d_in[4];
    const float* Wo = (const float*)d_in[5];
    float* out = (float*)d_out;

    __half *Qh, *Kh, *Ah, *xh, *Wqh, *Wkh, *Wvh, *Woh, *Vth;
    cudaGetSymbolAddress((void**)&Qh, g_Qh);
    cudaGetSymbolAddress((void**)&Kh, g_Kh);
    cudaGetSymbolAddress((void**)&Vth, g_Vt);
    cudaGetSymbolAddress((void**)&Ah, g_attnh);
    cudaGetSymbolAddress((void**)&xh, g_xh);
    cudaGetSymbolAddress((void**)&Wqh, g_Wqh);
    cudaGetSymbolAddress((void**)&Wkh, g_Wkh);
    cudaGetSymbolAddress((void**)&Wvh, g_Wvh);
    cudaGetSymbolAddress((void**)&Woh, g_Woh);

    // Fused tf32->fp16 rounding for all five tensors
    cvt_all_kernel<<<(CVT_TOTAL + 255) / 256, 256>>>(x, Wq, Wk, Wv, Wo,
                                                     xh, Wqh, Wkh, Wvh, Woh);

    cudaFuncSetAttribute(gemm_f16<__half>, cudaFuncAttributeMaxDynamicSharedMemorySize, GEMM_SMEM);
    cudaFuncSetAttribute(gemm_f16<float>, cudaFuncAttributeMaxDynamicSharedMemorySize, GEMM_SMEM);

    // Fused QKV: bx 0..15 -> Q, 16..19 -> K, 20..23 -> V (transposed into g_Vt)
    gemm_f16<__half><<<dim3(24, MM / 128), 128, GEMM_SMEM>>>(xh, Wqh, Wkh, Wvh,
                                                             Qh, Kh, Kh, 16, 4, 1);

    // RoPE: one sincos per (s,i) reused across heads; Q scaled by 0.125 here
    rope_fused_kernel<<<MM / 8, 256>>>();

    {
        cudaFuncSetAttribute(attn_kernel, cudaFuncAttributeMaxDynamicSharedMemorySize, ATT_SMEM);
        attn_kernel<<<dim3(SS / 128, NQ, BB), 256, ATT_SMEM>>>();
    }

    // Output projection -> fp32 out
    gemm_f16<float><<<dim3(16, MM / 128), 128, GEMM_SMEM>>>(Ah, Woh, Woh, Woh,
                                                            out, out, out, 16, 0, 0);
}

// round 17
// speedup vs baseline: 16.2097x; 1.0029x over previous
#include <cuda_runtime.h>
#include <cuda_fp16.h>
#include <math.h>
#include <stdint.h>

#define BB 2
#define SS 2048
#define DD 2048
#define NQ 32
#define NKV 8
#define HD 64
#define MM (BB*SS)   // 4096
#define KK 2048

// Scratch (no cudaMalloc allowed)
__device__ __half g_Qh[(size_t)MM * NQ * HD];
__device__ __half g_Kh[(size_t)MM * NKV * HD];
__device__ __half g_Vt[(size_t)BB * NKV * HD * SS];   // [(b*8+kvh)*64+d][token]
__device__ __half g_attnh[(size_t)MM * DD];
__device__ __half g_xh[(size_t)MM * DD];
__device__ __half g_Wqh[(size_t)DD * DD];
__device__ __half g_Wkh[(size_t)(NKV*HD) * DD];
__device__ __half g_Wvh[(size_t)(NKV*HD) * DD];
__device__ __half g_Woh[(size_t)DD * DD];

__device__ __forceinline__ void mma_f16(float* c, const uint32_t* a, uint32_t b0, uint32_t b1) {
    asm volatile(
        "mma.sync.aligned.m16n8k16.row.col.f32.f16.f16.f32 "
        "{%0,%1,%2,%3}, {%4,%5,%6,%7}, {%8,%9}, {%0,%1,%2,%3};"
        : "+f"(c[0]), "+f"(c[1]), "+f"(c[2]), "+f"(c[3])
        : "r"(a[0]), "r"(a[1]), "r"(a[2]), "r"(a[3]), "r"(b0), "r"(b1));
}

__device__ __forceinline__ void ldsm_x4(uint32_t* d, uint32_t saddr) {
    asm volatile("ldmatrix.sync.aligned.m8n8.x4.shared.b16 {%0,%1,%2,%3}, [%4];"
        : "=r"(d[0]), "=r"(d[1]), "=r"(d[2]), "=r"(d[3]) : "r"(saddr));
}

__device__ __forceinline__ void cp16(uint32_t dst, const void* src) {
    asm volatile("cp.async.cg.shared.global [%0], [%1], 16;" :: "r"(dst), "l"(src));
}
__device__ __forceinline__ void cp_commit() { asm volatile("cp.async.commit_group;"); }
__device__ __forceinline__ void cp_wait2()  { asm volatile("cp.async.wait_group 2;"); }
__device__ __forceinline__ void cp_wait1()  { asm volatile("cp.async.wait_group 1;"); }
__device__ __forceinline__ void cp_wait0()  { asm volatile("cp.async.wait_group 0;"); }

// ---------------------------------------------------------------------------
// Fused elementwise fp32 -> fp16 conversion for all five tensors (one launch).
// ---------------------------------------------------------------------------
#define N_X   (MM * DD / 4)
#define N_WQ  (DD * DD / 4)
#define N_WK  ((NKV * HD) * DD / 4)
#define CVT_TOTAL (N_X + 2 * N_WQ + 2 * N_WK)

__global__ void cvt_all_kernel(const float* __restrict__ x,  const float* __restrict__ wq,
                               const float* __restrict__ wk, const float* __restrict__ wv,
                               const float* __restrict__ wo,
                               __half* __restrict__ xh,  __half* __restrict__ wqh,
                               __half* __restrict__ wkh, __half* __restrict__ wvh,
                               __half* __restrict__ woh)
{
    int i = blockIdx.x * blockDim.x + threadIdx.x;
    if (i >= CVT_TOTAL) return;
    const float* src; __half* dst; int off;
    if (i < N_X)                         { src = x;  dst = xh;  off = i; }
    else if (i < N_X + N_WQ)             { src = wq; dst = wqh; off = i - N_X; }
    else if (i < N_X + N_WQ + N_WK)      { src = wk; dst = wkh; off = i - N_X - N_WQ; }
    else if (i < N_X + N_WQ + 2 * N_WK)  { src = wv; dst = wvh; off = i - N_X - N_WQ - N_WK; }
    else                                 { src = wo; dst = woh; off = i - N_X - N_WQ - 2 * N_WK; }
    float4 v = ((const float4*)src)[off];
    __half2 h0 = __floats2half2_rn(v.x, v.y);
    __half2 h1 = __floats2half2_rn(v.z, v.w);
    uint2 o;
    o.x = *(uint32_t*)&h0;
    o.y = *(uint32_t*)&h1;
    ((uint2*)dst)[off] = o;
}

// ---------------------------------------------------------------------------
// FP16 GEMM (verified core, UNCHANGED). C = A * B^T. 128x128, BK=32, 128 thr.
// tv=1: W2 route scatter-stores output TRANSPOSED into g_Vt.
// ---------------------------------------------------------------------------
#define ASTH 40
#define STAGE_H (128 * ASTH)
#define NSTG 4
#define GEMM_SMEM (NSTG * 2 * STAGE_H * 2)   // 81920 bytes

template<typename OutT>
__global__ __launch_bounds__(128, 2) void gemm_f16(
    const __half* __restrict__ A,
    const __half* __restrict__ W0, const __half* __restrict__ W1, const __half* __restrict__ W2,
    OutT* __restrict__ C0, OutT* __restrict__ C1, OutT* __restrict__ C2,
    int nb0, int nb1, int tv)
{
    extern __shared__ __half smemh[];
    __half* As = smemh;
    __half* Bs = smemh + NSTG * STAGE_H;

    int tid = threadIdx.x;
    int lane = tid & 31;
    int warp = tid >> 5;
    int wm = warp >> 1, wn = warp & 1;
    int bx = blockIdx.x;
    int bm = blockIdx.y * 128;
    int lg = lane >> 2, lk = lane & 3;

    const __half* Bsel; OutT* Csel; int Ncol, bn;
    int vroute = 0;
    if (bx < nb0)            { Bsel = W0; Csel = C0; Ncol = 2048; bn = bx * 128; }
    else if (bx < nb0 + nb1) { Bsel = W1; Csel = C1; Ncol = 512;  bn = (bx - nb0) * 128; }
    else                     { Bsel = W2; Csel = C2; Ncol = 512;  bn = (bx - nb0 - nb1) * 128; vroute = tv; }

    uint32_t As_u = (uint32_t)__cvta_generic_to_shared(As);
    uint32_t Bs_u = (uint32_t)__cvta_generic_to_shared(Bs);

    int a_row = lane & 15;
    int a_kh  = (lane >> 4) * 8;
    int b_row = (lane & 7) + (lane >> 4) * 8;
    int b_kh  = ((lane >> 3) & 1) * 8;
    uint32_t a_off = (uint32_t)(((wm * 64 + a_row) * ASTH + a_kh) * 2);
    uint32_t b_off = (uint32_t)(((wn * 64 + b_row) * ASTH + b_kh) * 2);

    float acc[4][8][4];
#pragma unroll
    for (int i = 0; i < 4; i++)
#pragma unroll
        for (int j = 0; j < 8; j++)
#pragma unroll
            for (int t = 0; t < 4; t++) acc[i][j][t] = 0.f;

    const __half* Agp[4]; const __half* Bgp[4]; uint32_t Ssm[4];
#pragma unroll
    for (int j = 0; j < 4; j++) {
        int ch = tid + j * 128;
        int row = ch >> 2, c = ch & 3;
        Agp[j] = A + (size_t)(bm + row) * KK + c * 8;
        Bgp[j] = Bsel + (size_t)(bn + row) * KK + c * 8;
        Ssm[j] = (uint32_t)((row * ASTH + c * 8) * 2);
    }

    const int NT = KK / 32;

#pragma unroll
    for (int t = 0; t < 3; t++) {
        uint32_t as = As_u + t * STAGE_H * 2;
        uint32_t bs = Bs_u + t * STAGE_H * 2;
#pragma unroll
        for (int j = 0; j < 4; j++) {
            cp16(as + Ssm[j], Agp[j] + t * 32);
            cp16(bs + Ssm[j], Bgp[j] + t * 32);
        }
        cp_commit();
    }

    for (int i = 0; i < NT; i++) {
        cp_wait2();
        __syncthreads();
        if (i + 3 < NT) {
            int sl = (i + 3) & 3;
            uint32_t as = As_u + sl * STAGE_H * 2;
            uint32_t bs = Bs_u + sl * STAGE_H * 2;
#pragma unroll
            for (int j = 0; j < 4; j++) {
                cp16(as + Ssm[j], Agp[j] + (i + 3) * 32);
                cp16(bs + Ssm[j], Bgp[j] + (i + 3) * 32);
            }
        }
        cp_commit();

        uint32_t as = As_u + (i & 3) * STAGE_H * 2;
        uint32_t bs = Bs_u + (i & 3) * STAGE_H * 2;
#pragma unroll
        for (int ks = 0; ks < 2; ks++) {
            uint32_t af[4][4];
#pragma unroll
            for (int mi = 0; mi < 4; mi++)
                ldsm_x4(af[mi], as + a_off + (uint32_t)((mi * 16 * ASTH + ks * 16) * 2));
            uint32_t bf[4][4];
#pragma unroll
            for (int np = 0; np < 4; np++)
                ldsm_x4(bf[np], bs + b_off + (uint32_t)((np * 16 * ASTH + ks * 16) * 2));
#pragma unroll
            for (int mi = 0; mi < 4; mi++)
#pragma unroll
                for (int ni = 0; ni < 8; ni++)
                    mma_f16(acc[mi][ni], af[mi], bf[ni >> 1][(ni & 1) * 2], bf[ni >> 1][(ni & 1) * 2 + 1]);
        }
    }

    if (vroute) {
#pragma unroll
        for (int mi = 0; mi < 4; mi++) {
#pragma unroll
            for (int ni = 0; ni < 8; ni++) {
                int token0 = bm + wm * 64 + mi * 16 + lg;
                int col = bn + wn * 64 + ni * 8 + lk * 2;
#pragma unroll
                for (int half_m = 0; half_m < 2; half_m++) {
                    int token = token0 + half_m * 8;
                    int b = token >> 11, s2 = token & (SS - 1);
                    g_Vt[((size_t)(b * (NKV * HD) + col)) * SS + s2]     = __float2half_rn(acc[mi][ni][half_m * 2 + 0]);
                    g_Vt[((size_t)(b * (NKV * HD) + col + 1)) * SS + s2] = __float2half_rn(acc[mi][ni][half_m * 2 + 1]);
                }
            }
        }
    } else {
#pragma unroll
        for (int mi = 0; mi < 4; mi++) {
#pragma unroll
            for (int ni = 0; ni < 8; ni++) {
                int rr = bm + wm * 64 + mi * 16 + lg;
                int cc = bn + wn * 64 + ni * 8 + lk * 2;
                if (sizeof(OutT) == 4) {
                    float* Cf = (float*)Csel;
                    *(float2*)(Cf + (size_t)rr * Ncol + cc) = make_float2(acc[mi][ni][0], acc[mi][ni][1]);
                    *(float2*)(Cf + (size_t)(rr + 8) * Ncol + cc) = make_float2(acc[mi][ni][2], acc[mi][ni][3]);
                } else {
                    __half* Ch = (__half*)Csel;
                    *(__half2*)(Ch + (size_t)rr * Ncol + cc) = __floats2half2_rn(acc[mi][ni][0], acc[mi][ni][1]);
                    *(__half2*)(Ch + (size_t)(rr + 8) * Ncol + cc) = __floats2half2_rn(acc[mi][ni][2], acc[mi][ni][3]);
                }
            }
        }
    }
}

// ---------------------------------------------------------------------------
// RoPE fused: ONE sincos per (s, i), reused across all 32 Q heads + 8 K heads.
// Q additionally scaled by 0.125 (exact).
// ---------------------------------------------------------------------------
__global__ void rope_fused_kernel()
{
    int ms = blockIdx.x * 8 + (threadIdx.x >> 5);
    if (ms >= MM) return;
    int i = threadIdx.x & 31;
    int s = ms & (SS - 1);

    const float LOG_THETA_OVER_HALF = 9.210340371976184f / 32.0f;
    float inv = expf(-(float)i * LOG_THETA_OVER_HALF);
    float ang = (float)s * inv;
    float sn, cs;
    sincosf(ang, &sn, &cs);

    __half* Qb = g_Qh + (size_t)ms * (NQ * HD);
#pragma unroll 4
    for (int h = 0; h < NQ; h++) {
        float x1 = __half2float(Qb[h * HD + i]);
        float x2 = __half2float(Qb[h * HD + i + 32]);
        Qb[h * HD + i]      = __float2half_rn((x1 * cs - x2 * sn) * 0.125f);
        Qb[h * HD + i + 32] = __float2half_rn((x2 * cs + x1 * sn) * 0.125f);
    }
    __half* Kb = g_Kh + (size_t)ms * (NKV * HD);
#pragma unroll
    for (int h = 0; h < NKV; h++) {
        float x1 = __half2float(Kb[h * HD + i]);
        float x2 = __half2float(Kb[h * HD + i + 32]);
        Kb[h * HD + i]      = __float2half_rn(x1 * cs - x2 * sn);
        Kb[h * HD + i + 32] = __float2half_rn(x2 * cs + x1 * sn);
    }
}

// ---------------------------------------------------------------------------
// FP16 flash attention v3: 128 q-rows per CTA, causal, double-buffered K/V,
// P kept entirely in REGISTERS (S C-fragment == PV A-fragment identity).
// V from g_Vt [d][token]. Q pre-scaled by 0.125.
// ---------------------------------------------------------------------------
#define FST 72
#define KT_H (64 * FST)
#define KT_B (KT_H * 2)
#define ATT_SMEM ((128 * FST + 4 * 64 * FST) * 2)   // 55296 bytes

__global__ __launch_bounds__(256) void attn_kernel()
{
    extern __shared__ __half smh[];
    __half* Qs = smh;                          // 128 x FST
    __half* Kb = smh + 128 * FST;              // 2 x 64 x FST
    __half* Vb = Kb + 2 * KT_H;                // 2 x 64 x FST

    int qt = (gridDim.x - 1) - blockIdx.x;     // heavy-first
    int h = blockIdx.y, b = blockIdx.z;
    int kvh = h >> 2;
    int tid = threadIdx.x, lane = tid & 31, w = tid >> 5;
    int lg = lane >> 2, lk = lane & 3;

    uint32_t Qs_u = (uint32_t)__cvta_generic_to_shared(Qs);
    uint32_t Kb_u = (uint32_t)__cvta_generic_to_shared(Kb);
    uint32_t Vb_u = (uint32_t)__cvta_generic_to_shared(Vb);

    const __half* Vtg = g_Vt + (size_t)(b * (NKV * HD) + kvh * HD) * SS;

    // load Q tile (128 rows x 64 halves) — pre-scaled in rope
    const __half* Qg = g_Qh + (size_t)(b * SS + qt * 128) * (NQ * HD) + h * HD;
    for (int i = tid; i < 128 * 8; i += 256) {
        int rr = i >> 3, c8 = (i & 7) * 8;
        *(uint4*)&Qs[rr * FST + c8] = *(const uint4*)(Qg + (size_t)rr * (NQ * HD) + c8);
    }

    int kid0 = tid, kid1 = tid + 256;
    int kr0 = kid0 >> 3, kc0 = (kid0 & 7) * 8;
    int kr1 = kid1 >> 3, kc1 = (kid1 & 7) * 8;

    // prologue: prefetch tile 0 into buffer 0
    {
        const __half* Kg = g_Kh + (size_t)(b * SS) * (NKV * HD) + kvh * HD;
        cp16(Kb_u + (uint32_t)((kr0 * FST + kc0) * 2), Kg + (size_t)kr0 * (NKV * HD) + kc0);
        cp16(Kb_u + (uint32_t)((kr1 * FST + kc1) * 2), Kg + (size_t)kr1 * (NKV * HD) + kc1);
        cp16(Vb_u + (uint32_t)((kr0 * FST + kc0) * 2), Vtg + (size_t)kr0 * SS + kc0);
        cp16(Vb_u + (uint32_t)((kr1 * FST + kc1) * 2), Vtg + (size_t)kr1 * SS + kc1);
        cp_commit();
    }
    __syncthreads();

    int arow = lane & 15, akh = (lane >> 4) * 8;
    uint32_t qa_off = (uint32_t)(((w * 16 + arow) * FST + akh) * 2);
    uint32_t qf[4][4];
#pragma unroll
    for (int ks = 0; ks < 4; ks++)
        ldsm_x4(qf[ks], Qs_u + qa_off + (uint32_t)(ks * 16 * 2));

    float o[8][4];
#pragma unroll
    for (int j = 0; j < 8; j++)
#pragma unroll
        for (int t = 0; t < 4; t++) o[j][t] = 0.f;
    float m0 = -INFINITY, m1 = -INFINITY, l0 = 0.f, l1 = 0.f;
    int qr0 = w * 16 + lg, qr1 = qr0 + 8;
    int row0 = qt * 128 + qr0, row1 = row0 + 8;

    int brow = (lane & 7) + (lane >> 4) * 8;
    int bkh  = ((lane >> 3) & 1) * 8;
    uint32_t kb_off = (uint32_t)((brow * FST + bkh) * 2);

    const int NT = 2 * qt + 2;

    for (int kt = 0; kt < NT; kt++) {
        if (kt + 1 < NT) {
            int nb = (kt + 1) & 1;
            const __half* Kg = g_Kh + (size_t)(b * SS + (kt + 1) * 64) * (NKV * HD) + kvh * HD;
            cp16(Kb_u + (uint32_t)(nb * KT_B) + (uint32_t)((kr0 * FST + kc0) * 2), Kg + (size_t)kr0 * (NKV * HD) + kc0);
            cp16(Kb_u + (uint32_t)(nb * KT_B) + (uint32_t)((kr1 * FST + kc1) * 2), Kg + (size_t)kr1 * (NKV * HD) + kc1);
            cp16(Vb_u + (uint32_t)(nb * KT_B) + (uint32_t)((kr0 * FST + kc0) * 2), Vtg + (size_t)kr0 * SS + (kt + 1) * 64 + kc0);
            cp16(Vb_u + (uint32_t)(nb * KT_B) + (uint32_t)((kr1 * FST + kc1) * 2), Vtg + (size_t)kr1 * SS + (kt + 1) * 64 + kc1);
            cp_commit();
            cp_wait1();
        } else {
            cp_wait0();
        }
        __syncthreads();

        uint32_t kbase = Kb_u + (uint32_t)((kt & 1) * KT_B);
        uint32_t vbase = Vb_u + (uint32_t)((kt & 1) * KT_B);

        // S = (Q*0.125) K^T
        float s[8][4];
#pragma unroll
        for (int j = 0; j < 8; j++) { s[j][0] = s[j][1] = s[j][2] = s[j][3] = 0.f; }
#pragma unroll
        for (int ks = 0; ks < 4; ks++) {
            uint32_t bf[4][4];
#pragma unroll
            for (int np = 0; np < 4; np++)
                ldsm_x4(bf[np], kbase + kb_off + (uint32_t)((np * 16 * FST + ks * 16) * 2));
#pragma unroll
            for (int j = 0; j < 8; j++)
                mma_f16(s[j], qf[ks], bf[j >> 1][(j & 1) * 2], bf[j >> 1][(j & 1) * 2 + 1]);
        }

        if (kt >= 2 * qt) {
#pragma unroll
            for (int j = 0; j < 8; j++) {
                int c0 = kt * 64 + j * 8 + 2 * lk, c1 = c0 + 1;
                if (c0 > row0) s[j][0] = -INFINITY;
                if (c1 > row0) s[j][1] = -INFINITY;
                if (c0 > row1) s[j][2] = -INFINITY;
                if (c1 > row1) s[j][3] = -INFINITY;
            }
        }

        float mn0 = s[0][0], mn1 = s[0][2];
#pragma unroll
        for (int j = 0; j < 8; j++) {
            mn0 = fmaxf(mn0, fmaxf(s[j][0], s[j][1]));
            mn1 = fmaxf(mn1, fmaxf(s[j][2], s[j][3]));
        }
        mn0 = fmaxf(mn0, __shfl_xor_sync(0xffffffffu, mn0, 1));
        mn0 = fmaxf(mn0, __shfl_xor_sync(0xffffffffu, mn0, 2));
        mn1 = fmaxf(mn1, __shfl_xor_sync(0xffffffffu, mn1, 1));
        mn1 = fmaxf(mn1, __shfl_xor_sync(0xffffffffu, mn1, 2));
        float mnew0 = fmaxf(m0, mn0), mnew1 = fmaxf(m1, mn1);
        float a0 = __expf(m0 - mnew0), a1 = __expf(m1 - mnew1);

        // exp + build P fragments DIRECTLY in registers:
        // pf[ks] = { pack(s[2ks][0],s[2ks][1]), pack(s[2ks][2],s[2ks][3]),
        //            pack(s[2ks+1][0],s[2ks+1][1]), pack(s[2ks+1][2],s[2ks+1][3]) }
        uint32_t ph01[8], ph23[8];
        float ll0 = 0.f, ll1 = 0.f;
#pragma unroll
        for (int j = 0; j < 8; j++) {
            float p0 = __expf(s[j][0] - mnew0);
            float p1 = __expf(s[j][1] - mnew0);
            float p2 = __expf(s[j][2] - mnew1);
            float p3 = __expf(s[j][3] - mnew1);
            ll0 += p0 + p1; ll1 += p2 + p3;
            __half2 h01 = __floats2half2_rn(p0, p1);
            __half2 h23 = __floats2half2_rn(p2, p3);
            ph01[j] = *(uint32_t*)&h01;
            ph23[j] = *(uint32_t*)&h23;
        }
        ll0 += __shfl_xor_sync(0xffffffffu, ll0, 1);
        ll0 += __shfl_xor_sync(0xffffffffu, ll0, 2);
        ll1 += __shfl_xor_sync(0xffffffffu, ll1, 1);
        ll1 += __shfl_xor_sync(0xffffffffu, ll1, 2);
        l0 = l0 * a0 + ll0; l1 = l1 * a1 + ll1;
        m0 = mnew0; m1 = mnew1;
#pragma unroll
        for (int j = 0; j < 8; j++) {
            o[j][0] *= a0; o[j][1] *= a0; o[j][2] *= a1; o[j][3] *= a1;
        }

        // O += P V : A fragments from registers, B = Vs[d][token]
#pragma unroll
        for (int ks = 0; ks < 4; ks++) {
            uint32_t pf[4];
            pf[0] = ph01[2 * ks];
            pf[1] = ph23[2 * ks];
            pf[2] = ph01[2 * ks + 1];
            pf[3] = ph23[2 * ks + 1];
            uint32_t vf[4][4];
#pragma unroll
            for (int np = 0; np < 4; np++)
                ldsm_x4(vf[np], vbase + kb_off + (uint32_t)((np * 16 * FST + ks * 16) * 2));
#pragma unroll
            for (int j = 0; j < 8; j++)
                mma_f16(o[j], pf, vf[j >> 1][(j & 1) * 2], vf[j >> 1][(j & 1) * 2 + 1]);
        }
        __syncthreads();   // all warps done with buffer (kt&1) before it is overwritten
    }

    float il0 = 1.0f / l0, il1 = 1.0f / l1;
    int gr0 = b * SS + qt * 128 + qr0;
#pragma unroll
    for (int j = 0; j < 8; j++) {
        int cc = h * HD + j * 8 + 2 * lk;
        *(__half2*)(g_attnh + (size_t)gr0 * DD + cc) = __floats2half2_rn(o[j][0] * il0, o[j][1] * il0);
        *(__half2*)(g_attnh + (size_t)(gr0 + 8) * DD + cc) = __floats2half2_rn(o[j][2] * il1, o[j][3] * il1);
    }
}

// ---------------------------------------------------------------------------
extern "C" void kernel_launch(void* const* d_in, const int* in_sizes, int n_in,
                              void* d_out, int out_size)
{
    const float* x  = (const float*)d_in[0];
    const float* Wq = (const float*)d_in[2];
    const float* Wk = (const float*)d_in[3];
    const float* Wv = (const float*)d_in[4];
    const float* Wo = (const float*)d_in[5];
    float* out = (float*)d_out;

    __half *Qh, *Kh, *Ah, *xh, *Wqh, *Wkh, *Wvh, *Woh, *Vth;
    cudaGetSymbolAddress((void**)&Qh, g_Qh);
    cudaGetSymbolAddress((void**)&Kh, g_Kh);
    cudaGetSymbolAddress((void**)&Vth, g_Vt);
    cudaGetSymbolAddress((void**)&Ah, g_attnh);
    cudaGetSymbolAddress((void**)&xh, g_xh);
    cudaGetSymbolAddress((void**)&Wqh, g_Wqh);
    cudaGetSymbolAddress((void**)&Wkh, g_Wkh);
    cudaGetSymbolAddress((void**)&Wvh, g_Wvh);
    cudaGetSymbolAddress((void**)&Woh, g_Woh);

    cvt_all_kernel<<<(CVT_TOTAL + 255) / 256, 256>>>(x, Wq, Wk, Wv, Wo,
                                                     xh, Wqh, Wkh, Wvh, Woh);

    cudaFuncSetAttribute(gemm_f16<__half>, cudaFuncAttributeMaxDynamicSharedMemorySize, GEMM_SMEM);
    cudaFuncSetAttribute(gemm_f16<float>, cudaFuncAttributeMaxDynamicSharedMemorySize, GEMM_SMEM);

    gemm_f16<__half><<<dim3(24, MM / 128), 128, GEMM_SMEM>>>(xh, Wqh, Wkh, Wvh,
                                                             Qh, Kh, Kh, 16, 4, 1);

    rope_fused_kernel<<<MM / 8, 256>>>();

    {
        cudaFuncSetAttribute(attn_kernel, cudaFuncAttributeMaxDynamicSharedMemorySize, ATT_SMEM);
        attn_kernel<<<dim3(SS / 128, NQ, BB), 256, ATT_SMEM>>>();
    }

    gemm_f16<float><<<dim3(16, MM / 128), 128, GEMM_SMEM>>>(Ah, Woh, Woh, Woh,
                                                            out, out, out, 16, 0, 0);
}